// round 7
// baseline (speedup 1.0000x reference)
#include <cuda_runtime.h>
#include <cuda_bf16.h>
#include <cstdint>
#include <cstddef>

typedef __nv_bfloat16 bf16;

// ============================ helpers ============================
__device__ __forceinline__ uint32_t smem_u32(const void* p) {
    uint32_t a;
    asm("{ .reg .u64 t; cvta.to.shared.u64 t, %1; cvt.u32.u64 %0, t; }" : "=r"(a) : "l"(p));
    return a;
}
__device__ __forceinline__ void ldsm4(uint32_t& r0, uint32_t& r1, uint32_t& r2, uint32_t& r3,
                                      uint32_t addr) {
    asm volatile("ldmatrix.sync.aligned.m8n8.x4.shared.b16 {%0,%1,%2,%3}, [%4];"
                 : "=r"(r0), "=r"(r1), "=r"(r2), "=r"(r3) : "r"(addr));
}
__device__ __forceinline__ void mma16816(float c[4], const uint32_t a[4], const uint32_t b[2]) {
    asm volatile(
        "mma.sync.aligned.m16n8k16.row.col.f32.bf16.bf16.f32 "
        "{%0,%1,%2,%3}, {%4,%5,%6,%7}, {%8,%9}, {%0,%1,%2,%3};"
        : "+f"(c[0]), "+f"(c[1]), "+f"(c[2]), "+f"(c[3])
        : "r"(a[0]), "r"(a[1]), "r"(a[2]), "r"(a[3]), "r"(b[0]), "r"(b[1]));
}
__device__ __forceinline__ void bsplit(float v, bf16& h, bf16& l) {
    h = __float2bfloat16(v);
    l = __float2bfloat16(v - __bfloat162float(h));
}
// 16B async copy, zero-fill when srcsize==0
__device__ __forceinline__ void cp16(uint32_t dst, const void* src, uint32_t srcsize) {
    asm volatile("cp.async.cg.shared.global [%0], [%1], 16, %2;"
                 :: "r"(dst), "l"(src), "r"(srcsize) : "memory");
}
#define CP_COMMIT() asm volatile("cp.async.commit_group;" ::: "memory")
#define CP_WAIT(n)  asm volatile("cp.async.wait_group %0;" :: "n"(n) : "memory")

// smem tile pitch: 72 bf16 (144 B) -> row stride 36 words -> ldmatrix conflict-free
static constexpr int PITCH = 72;
static constexpr int ATILE_B = 128 * PITCH * 2;   // 18432 bytes per 128x64 bf16 tile

// ============================ scratch ============================
__device__ bf16 g_x1h[(size_t)64 * 112 * 112 * 64];
__device__ bf16 g_x1l[(size_t)64 * 112 * 112 * 64];
__device__ bf16 g_x2h[(size_t)64 * 56 * 56 * 128];
__device__ bf16 g_x2l[(size_t)64 * 56 * 56 * 128];
__device__ bf16 g_x3h[(size_t)64 * 28 * 28 * 256];
__device__ bf16 g_x3l[(size_t)64 * 28 * 28 * 256];
__device__ bf16 g_x4h[(size_t)64 * 14 * 14 * 512];
__device__ bf16 g_x4l[(size_t)64 * 14 * 14 * 512];
__device__ bf16 g_w1h[64 * 64], g_w1l[64 * 64];              // conv1 padded [co][64]
__device__ bf16 g_w2h[9 * 128 * 64],  g_w2l[9 * 128 * 64];   // [t][co][ci]
__device__ bf16 g_w3h[9 * 256 * 128], g_w3l[9 * 256 * 128];
__device__ bf16 g_w4h[9 * 512 * 256], g_w4l[9 * 512 * 256];
__device__ float g_mean[64 * 512];
__device__ float g_sent[64 * 512];
__device__ float g_img[64 * 512];
__device__ float g_feats[64 * 1024];
__device__ float g_h1[64 * 512];
__device__ float g_h2[64 * 512];

// ============================ weight prep ============================
__global__ void wprep1_k(const float* __restrict__ w, bf16* __restrict__ wh, bf16* __restrict__ wl) {
    int idx = blockIdx.x * 256 + threadIdx.x;      // 64*64
    if (idx >= 64 * 64) return;
    int co = idx >> 6, k = idx & 63;
    float v = (k < 27) ? w[co * 27 + k] : 0.0f;
    bf16 h, l; bsplit(v, h, l);
    wh[idx] = h; wl[idx] = l;
}
__global__ void wprepT_k(const float* __restrict__ w, bf16* __restrict__ wh, bf16* __restrict__ wl,
                         int COUT, int CIN) {
    int idx = blockIdx.x * 256 + threadIdx.x;      // COUT*CIN*9
    if (idx >= COUT * CIN * 9) return;
    int co = idx / (CIN * 9);
    int rem = idx - co * (CIN * 9);
    int ci = rem / 9, t = rem - ci * 9;
    bf16 h, l; bsplit(w[idx], h, l);
    int o = (t * COUT + co) * CIN + ci;
    wh[o] = h; wl[o] = l;
}

// ============================ warp-level GEMM core ============================
// one 64-wide k chunk: c += Ah*Bh^T + Ah*Bl^T + Al*Bh^T  (3-term bf16 split)
template <int NFRAG>
__device__ __forceinline__ void chunk_mma(uint32_t sbA_h, uint32_t sbA_l,
                                          uint32_t sbB_h, uint32_t sbB_l,
                                          int lane, int warpM, int warpN,
                                          float (&c)[2][NFRAG][4]) {
    const int arow = warpM * 32 + (lane & 15);
    const int akoff = (lane >> 4) * 8;
    const int brow = warpN * (NFRAG * 8) + (lane & 7) + ((lane >> 3) & 1) * 8;
    const int bkoff = (lane >> 4) * 8;
#pragma unroll
    for (int ks = 0; ks < 4; ks++) {
        const int k0 = ks * 16;
        uint32_t ah[2][4], al[2][4];
#pragma unroll
        for (int i = 0; i < 2; i++) {
            const uint32_t aoff = (((arow + i * 16) * PITCH) + k0 + akoff) * 2;
            ldsm4(ah[i][0], ah[i][1], ah[i][2], ah[i][3], sbA_h + aoff);
            ldsm4(al[i][0], al[i][1], al[i][2], al[i][3], sbA_l + aoff);
        }
        uint32_t bh[NFRAG][2], bl[NFRAG][2];
#pragma unroll
        for (int j2 = 0; j2 < NFRAG / 2; j2++) {
            const uint32_t boff = (((brow + j2 * 16) * PITCH) + k0 + bkoff) * 2;
            uint32_t r0, r1, r2, r3;
            ldsm4(r0, r1, r2, r3, sbB_h + boff);
            bh[2 * j2][0] = r0; bh[2 * j2][1] = r2;
            bh[2 * j2 + 1][0] = r1; bh[2 * j2 + 1][1] = r3;
            ldsm4(r0, r1, r2, r3, sbB_l + boff);
            bl[2 * j2][0] = r0; bl[2 * j2][1] = r2;
            bl[2 * j2 + 1][0] = r1; bl[2 * j2 + 1][1] = r3;
        }
#pragma unroll
        for (int i = 0; i < 2; i++)
#pragma unroll
            for (int j = 0; j < NFRAG; j++) {
                mma16816(c[i][j], ah[i], bh[j]);
                mma16816(c[i][j], ah[i], bl[j]);
                mma16816(c[i][j], al[i], bh[j]);
            }
    }
}

// epilogue: bias + relu + bsplit -> NHWC hi/lo
template <int NFRAG, int COUT>
__device__ __forceinline__ void epilogue(float (&c)[2][NFRAG][4], const float* __restrict__ bias,
                                         int tile0, int cob, int lane, int warpM, int warpN,
                                         bf16* __restrict__ yh, bf16* __restrict__ yl) {
#pragma unroll
    for (int i = 0; i < 2; i++) {
        const int r0 = tile0 + warpM * 32 + i * 16 + (lane >> 2);
#pragma unroll
        for (int j = 0; j < NFRAG; j++) {
            const int col = cob + warpN * (NFRAG * 8) + j * 8 + (lane & 3) * 2;
            const float b0 = bias[col], b1 = bias[col + 1];
#pragma unroll
            for (int h = 0; h < 2; h++) {
                const int r = r0 + h * 8;
                float v0 = c[i][j][2 * h + 0] + b0; if (v0 < 0.0f) v0 = 0.0f;
                float v1 = c[i][j][2 * h + 1] + b1; if (v1 < 0.0f) v1 = 0.0f;
                bf16 h0, l0, h1, l1;
                bsplit(v0, h0, l0); bsplit(v1, h1, l1);
                const size_t o = (size_t)r * COUT + col;
                __nv_bfloat162 ph, pl;
                ph.x = h0; ph.y = h1; pl.x = l0; pl.y = l1;
                *(__nv_bfloat162*)(yh + o) = ph;
                *(__nv_bfloat162*)(yl + o) = pl;
            }
        }
    }
}

// ============================ conv2/3/4: implicit GEMM, cp.async double-buffered ============================
template <int CIN, int COUT, int HIN, int WIN>
__global__ void __launch_bounds__(256, 1)
convmm_k(const bf16* __restrict__ xh, const bf16* __restrict__ xl,
         const bf16* __restrict__ wth, const bf16* __restrict__ wtl,
         const float* __restrict__ bias,
         bf16* __restrict__ yh, bf16* __restrict__ yl) {
    constexpr int HOUT = HIN / 2, WOUT = WIN / 2;
    constexpr int CPT = CIN / 64;
    constexpr int NCH = 9 * CPT;
    constexpr int NFRAG = 8;

    extern __shared__ char sb[];
    const uint32_t sb32 = smem_u32(sb);

    const int tid = threadIdx.x, lane = tid & 31, wid = tid >> 5;
    const int warpM = wid >> 1, warpN = wid & 1;
    const int tile0 = blockIdx.x * 128;
    const int cob = blockIdx.y * 128;

    // staging coords: 4 slots per thread; row = (tid>>3)+32*r4, c16 = tid&7
    const int c16 = tid & 7;
    int baseoff[4]; bool xe[4], ye[4];
#pragma unroll
    for (int r4 = 0; r4 < 4; r4++) {
        const int row = (tid >> 3) + 32 * r4;
        const int s = tile0 + row;
        const int n = s / (HOUT * WOUT);
        const int rem = s - n * (HOUT * WOUT);
        const int y = rem / WOUT;
        const int x = rem - y * WOUT;
        baseoff[r4] = ((n * HIN + 2 * y) * WIN + 2 * x) * CIN;
        xe[r4] = (2 * x + 2 >= WIN);
        ye[r4] = (2 * y + 2 >= HIN);
    }

    // stage chunk ch into buffer ch&1 via cp.async (4 tiles: Ah, Al, Bh, Bl)
    auto stage = [&](int ch) {
        const int buf = ch & 1;
        const int t = ch / CPT;
        const int cb = (ch - t * CPT) * 64;
        const int ky = t / 3, kx = t - ky * 3;
        const uint32_t base = sb32 + buf * (4 * ATILE_B);
#pragma unroll
        for (int r4 = 0; r4 < 4; r4++) {
            const int row = (tid >> 3) + 32 * r4;
            const uint32_t soff = (row * PITCH + c16 * 8) * 2;
            const bool valid = !((kx == 2 && xe[r4]) || (ky == 2 && ye[r4]));
            const uint32_t vsz = valid ? 16u : 0u;
            const size_t src = (size_t)baseoff[r4] + (ky * WIN + kx) * CIN + cb + c16 * 8;
            cp16(base + 0 * ATILE_B + soff, xh + src, vsz);
            cp16(base + 1 * ATILE_B + soff, xl + src, vsz);
            const size_t wsrc = ((size_t)t * COUT + cob + row) * CIN + cb + c16 * 8;
            cp16(base + 2 * ATILE_B + soff, wth + wsrc, 16u);
            cp16(base + 3 * ATILE_B + soff, wtl + wsrc, 16u);
        }
        CP_COMMIT();
    };

    float c[2][NFRAG][4];
#pragma unroll
    for (int i = 0; i < 2; i++)
#pragma unroll
        for (int j = 0; j < NFRAG; j++)
#pragma unroll
            for (int q = 0; q < 4; q++) c[i][j][q] = 0.0f;

    stage(0);
    for (int ch = 0; ch < NCH; ch++) {
        if (ch + 1 < NCH) { stage(ch + 1); CP_WAIT(1); }
        else              { CP_WAIT(0); }
        __syncthreads();
        const uint32_t base = sb32 + (ch & 1) * (4 * ATILE_B);
        chunk_mma<NFRAG>(base, base + ATILE_B, base + 2 * ATILE_B, base + 3 * ATILE_B,
                         lane, warpM, warpN, c);
        __syncthreads();   // buffer (ch+1)&1 safe to overwrite next iteration
    }

    epilogue<NFRAG, COUT>(c, bias, tile0, cob, lane, warpM, warpN, yh, yl);
}

// ============================ conv1: implicit GEMM, K=27 (padded 64) ============================
__global__ void __launch_bounds__(256, 2)
conv1mm_k(const float* __restrict__ images,
          const bf16* __restrict__ wh, const bf16* __restrict__ wl,
          const float* __restrict__ bias,
          bf16* __restrict__ yh, bf16* __restrict__ yl) {
    constexpr int HOUT = 112, WOUT = 112, HIN = 224, WIN = 224;
    constexpr int NFRAG = 4;   // 64 couts: warp tile 32x32

    extern __shared__ char sb[];
    const uint32_t sb32 = smem_u32(sb);
    const uint32_t oAh = 0, oAl = ATILE_B, oBh = 2 * ATILE_B;
    const uint32_t oBl = 2 * ATILE_B + 64 * PITCH * 2;

    const int tid = threadIdx.x, lane = tid & 31, wid = tid >> 5;
    const int warpM = wid >> 1, warpN = wid & 1;
    const int tile0 = blockIdx.x * 128;

    // A staging: thread owns k = tid&63, rows (tid>>6)+4i
    {
        const int k = tid & 63;
        const int r0 = tid >> 6;
        int ci = 0, ky = 0, kx = 0;
        const bool kvalid = (k < 27);
        if (kvalid) { ci = k / 9; int r = k - ci * 9; ky = r / 3; kx = r - ky * 3; }
        for (int i = 0; i < 32; i++) {
            const int row = r0 + 4 * i;
            bf16 h = __float2bfloat16(0.0f), l = __float2bfloat16(0.0f);
            if (kvalid) {
                const int s = tile0 + row;
                const int n = s / (HOUT * WOUT);
                const int rem = s - n * (HOUT * WOUT);
                const int y = rem / WOUT;
                const int x = rem - y * WOUT;
                const int iy = 2 * y + ky, ix = 2 * x + kx;
                if (iy < HIN && ix < WIN) {
                    float v = images[((size_t)(n * 3 + ci) * HIN + iy) * WIN + ix];
                    bsplit(v, h, l);
                }
            }
            const uint32_t soff = (row * PITCH + k) * 2;
            *(bf16*)(sb + oAh + soff) = h;
            *(bf16*)(sb + oAl + soff) = l;
        }
    }
    // B staging: 64 rows x 8 c16
    for (int idx = tid; idx < 512; idx += 256) {
        const int row = idx >> 3, c16 = idx & 7;
        const uint32_t soff = (row * PITCH + c16 * 8) * 2;
        *(uint4*)(sb + oBh + soff) = *(const uint4*)(wh + row * 64 + c16 * 8);
        *(uint4*)(sb + oBl + soff) = *(const uint4*)(wl + row * 64 + c16 * 8);
    }
    __syncthreads();

    float c[2][NFRAG][4];
#pragma unroll
    for (int i = 0; i < 2; i++)
#pragma unroll
        for (int j = 0; j < NFRAG; j++)
#pragma unroll
            for (int q = 0; q < 4; q++) c[i][j][q] = 0.0f;

    chunk_mma<NFRAG>(sb32 + oAh, sb32 + oAl, sb32 + oBh, sb32 + oBl,
                     lane, warpM, warpN, c);

    epilogue<NFRAG, 64>(c, bias, tile0, 0, lane, warpM, warpN, yh, yl);
}

// ============================ misc kernels ============================
__global__ void embed_mean_k(const int* __restrict__ seq, const int* __restrict__ len,
                             const float* __restrict__ emb, float* __restrict__ mean) {
    const int b = blockIdx.x;
    const int L = len[b];
    __shared__ int s_idx[128];
    for (int i = threadIdx.x; i < 128; i += blockDim.x) s_idx[i] = seq[b * 128 + i];
    __syncthreads();
    const float inv = 1.0f / (float)L;
    for (int d = threadIdx.x; d < 512; d += blockDim.x) {
        float acc = 0.0f;
        for (int s = 0; s < L; s++) acc += emb[(size_t)s_idx[s] * 512 + d];
        mean[b * 512 + d] = acc * inv;
    }
}

__global__ void linear_k(const float* __restrict__ X, const float* __restrict__ W,
                         const float* __restrict__ bias, float* __restrict__ Y,
                         int K, int N, int relu) {
    const int j = blockIdx.x * blockDim.x + threadIdx.x;
    const int b = blockIdx.y;
    if (j >= N) return;
    const float* x = X + (size_t)b * K;
    float acc = bias[j];
    for (int k = 0; k < K; k++) acc = fmaf(x[k], W[(size_t)k * N + j], acc);
    if (relu && acc < 0.0f) acc = 0.0f;
    Y[(size_t)b * N + j] = acc;
}

// pool over 196 spatial (NHWC hi/lo), thread per (n,c)
__global__ void pool2_k(const bf16* __restrict__ xh, const bf16* __restrict__ xl,
                        float* __restrict__ y) {
    const int idx = blockIdx.x * 256 + threadIdx.x;   // 64*512
    const int n = idx >> 9, c = idx & 511;
    const bf16* ph = xh + (size_t)n * 196 * 512 + c;
    const bf16* pl = xl + (size_t)n * 196 * 512 + c;
    float s = 0.0f;
    for (int p = 0; p < 196; p++)
        s += __bfloat162float(ph[(size_t)p * 512]) + __bfloat162float(pl[(size_t)p * 512]);
    y[idx] = s * (1.0f / 196.0f);
}

__global__ void concat_k(const float* __restrict__ img, const float* __restrict__ sent,
                         float* __restrict__ feats) {
    const int i = blockIdx.x * blockDim.x + threadIdx.x;
    const int b = i >> 10, j = i & 1023;
    feats[i] = (j < 512) ? img[b * 512 + j] : sent[b * 512 + (j - 512)];
}

// ============================ launch ============================
extern "C" void kernel_launch(void* const* d_in, const int* in_sizes, int n_in,
                              void* d_out, int out_size) {
    const float* images = (const float*)d_in[0];
    const int*   seq    = (const int*)d_in[1];
    const int*   len    = (const int*)d_in[2];
    const float* emb    = (const float*)d_in[4];
    const float* cw1 = (const float*)d_in[5],  *cb1 = (const float*)d_in[6];
    const float* cw2 = (const float*)d_in[7],  *cb2 = (const float*)d_in[8];
    const float* cw3 = (const float*)d_in[9],  *cb3 = (const float*)d_in[10];
    const float* cw4 = (const float*)d_in[11], *cb4 = (const float*)d_in[12];
    const float* rnn_w = (const float*)d_in[13], *rnn_b = (const float*)d_in[14];
    const float* fc1_w = (const float*)d_in[15], *fc1_b = (const float*)d_in[16];
    const float* fc2_w = (const float*)d_in[17], *fc2_b = (const float*)d_in[18];
    const float* clf_w = (const float*)d_in[19], *clf_b = (const float*)d_in[20];
    float* out = (float*)d_out;

    bf16 *x1h, *x1l, *x2h, *x2l, *x3h, *x3l, *x4h, *x4l;
    bf16 *w1h, *w1l, *w2h, *w2l, *w3h, *w3l, *w4h, *w4l;
    float *mean, *sent, *img, *feats, *h1, *h2;
    cudaGetSymbolAddress((void**)&x1h, g_x1h); cudaGetSymbolAddress((void**)&x1l, g_x1l);
    cudaGetSymbolAddress((void**)&x2h, g_x2h); cudaGetSymbolAddress((void**)&x2l, g_x2l);
    cudaGetSymbolAddress((void**)&x3h, g_x3h); cudaGetSymbolAddress((void**)&x3l, g_x3l);
    cudaGetSymbolAddress((void**)&x4h, g_x4h); cudaGetSymbolAddress((void**)&x4l, g_x4l);
    cudaGetSymbolAddress((void**)&w1h, g_w1h); cudaGetSymbolAddress((void**)&w1l, g_w1l);
    cudaGetSymbolAddress((void**)&w2h, g_w2h); cudaGetSymbolAddress((void**)&w2l, g_w2l);
    cudaGetSymbolAddress((void**)&w3h, g_w3h); cudaGetSymbolAddress((void**)&w3l, g_w3l);
    cudaGetSymbolAddress((void**)&w4h, g_w4h); cudaGetSymbolAddress((void**)&w4l, g_w4l);
    cudaGetSymbolAddress((void**)&mean, g_mean); cudaGetSymbolAddress((void**)&sent, g_sent);
    cudaGetSymbolAddress((void**)&img, g_img);   cudaGetSymbolAddress((void**)&feats, g_feats);
    cudaGetSymbolAddress((void**)&h1, g_h1);     cudaGetSymbolAddress((void**)&h2, g_h2);

    const int smem234 = 2 * 4 * ATILE_B;                // 147456 (double-buffered)
    const int smem1 = 2 * ATILE_B + 2 * 64 * PITCH * 2; // 55296
    cudaFuncSetAttribute(conv1mm_k, cudaFuncAttributeMaxDynamicSharedMemorySize, smem1);
    cudaFuncSetAttribute(convmm_k<64, 128, 112, 112>, cudaFuncAttributeMaxDynamicSharedMemorySize, smem234);
    cudaFuncSetAttribute(convmm_k<128, 256, 56, 56>,  cudaFuncAttributeMaxDynamicSharedMemorySize, smem234);
    cudaFuncSetAttribute(convmm_k<256, 512, 28, 28>,  cudaFuncAttributeMaxDynamicSharedMemorySize, smem234);

    // weight prep
    wprep1_k<<<16, 256>>>(cw1, w1h, w1l);
    wprepT_k<<<(128 * 64 * 9 + 255) / 256, 256>>>(cw2, w2h, w2l, 128, 64);
    wprepT_k<<<(256 * 128 * 9 + 255) / 256, 256>>>(cw3, w3h, w3l, 256, 128);
    wprepT_k<<<(512 * 256 * 9 + 255) / 256, 256>>>(cw4, w4h, w4l, 512, 256);

    // text branch
    embed_mean_k<<<64, 512>>>(seq, len, emb, mean);
    linear_k<<<dim3(2, 64), 256>>>(mean, rnn_w, rnn_b, sent, 512, 512, 0);

    // vision branch (implicit GEMM, NHWC bf16 hi/lo, mma.sync + cp.async pipeline)
    conv1mm_k<<<6272, 256, smem1>>>(images, w1h, w1l, cb1, x1h, x1l);
    convmm_k<64, 128, 112, 112><<<dim3(1568, 1), 256, smem234>>>(x1h, x1l, w2h, w2l, cb2, x2h, x2l);
    convmm_k<128, 256, 56, 56><<<dim3(392, 2), 256, smem234>>>(x2h, x2l, w3h, w3l, cb3, x3h, x3l);
    convmm_k<256, 512, 28, 28><<<dim3(98, 4), 256, smem234>>>(x3h, x3l, w4h, w4l, cb4, x4h, x4l);
    pool2_k<<<128, 256>>>(x4h, x4l, img);

    // head
    concat_k<<<(64 * 1024) / 256, 256>>>(img, sent, feats);
    linear_k<<<dim3(2, 64), 256>>>(feats, fc1_w, fc1_b, h1, 1024, 512, 1);
    linear_k<<<dim3(2, 64), 256>>>(h1, fc2_w, fc2_b, h2, 512, 512, 1);
    linear_k<<<dim3(4, 64), 256>>>(h2, clf_w, clf_b, out, 512, 1000, 0);
}

// round 8
// speedup vs baseline: 1.0139x; 1.0139x over previous
#include <cuda_runtime.h>
#include <cuda_bf16.h>
#include <cstdint>
#include <cstddef>

typedef __nv_bfloat16 bf16;

// ============================ helpers ============================
__device__ __forceinline__ uint32_t smem_u32(const void* p) {
    uint32_t a;
    asm("{ .reg .u64 t; cvta.to.shared.u64 t, %1; cvt.u32.u64 %0, t; }" : "=r"(a) : "l"(p));
    return a;
}
__device__ __forceinline__ void ldsm4(uint32_t& r0, uint32_t& r1, uint32_t& r2, uint32_t& r3,
                                      uint32_t addr) {
    asm volatile("ldmatrix.sync.aligned.m8n8.x4.shared.b16 {%0,%1,%2,%3}, [%4];"
                 : "=r"(r0), "=r"(r1), "=r"(r2), "=r"(r3) : "r"(addr));
}
__device__ __forceinline__ void mma16816(float c[4], const uint32_t a[4], const uint32_t b[2]) {
    asm volatile(
        "mma.sync.aligned.m16n8k16.row.col.f32.bf16.bf16.f32 "
        "{%0,%1,%2,%3}, {%4,%5,%6,%7}, {%8,%9}, {%0,%1,%2,%3};"
        : "+f"(c[0]), "+f"(c[1]), "+f"(c[2]), "+f"(c[3])
        : "r"(a[0]), "r"(a[1]), "r"(a[2]), "r"(a[3]), "r"(b[0]), "r"(b[1]));
}
__device__ __forceinline__ void bsplit(float v, bf16& h, bf16& l) {
    h = __float2bfloat16(v);
    l = __float2bfloat16(v - __bfloat162float(h));
}
// 16B async copy, zero-fill when srcsize==0
__device__ __forceinline__ void cp16(uint32_t dst, const void* src, uint32_t srcsize) {
    asm volatile("cp.async.cg.shared.global [%0], [%1], 16, %2;"
                 :: "r"(dst), "l"(src), "r"(srcsize) : "memory");
}
#define CP_COMMIT() asm volatile("cp.async.commit_group;" ::: "memory")
#define CP_WAIT(n)  asm volatile("cp.async.wait_group %0;" :: "n"(n) : "memory")

// conv2-4 pipeline tiles: 128 rows x 32 bf16, pitch 40 (conflict-free ldmatrix)
static constexpr int PIT32 = 40;
static constexpr int TB32 = 128 * PIT32 * 2;      // 10240 B
// conv1 tiles: 128 rows x 64 bf16, pitch 72
static constexpr int PITCH = 72;
static constexpr int ATILE_B = 128 * PITCH * 2;   // 18432 B

// ============================ scratch ============================
__device__ bf16 g_x1h[(size_t)64 * 112 * 112 * 64];
__device__ bf16 g_x1l[(size_t)64 * 112 * 112 * 64];
__device__ bf16 g_x2h[(size_t)64 * 56 * 56 * 128];
__device__ bf16 g_x2l[(size_t)64 * 56 * 56 * 128];
__device__ bf16 g_x3h[(size_t)64 * 28 * 28 * 256];
__device__ bf16 g_x3l[(size_t)64 * 28 * 28 * 256];
__device__ bf16 g_x4h[(size_t)64 * 14 * 14 * 512];
__device__ bf16 g_x4l[(size_t)64 * 14 * 14 * 512];
__device__ bf16 g_w1h[64 * 64], g_w1l[64 * 64];              // conv1 padded [co][64]
__device__ bf16 g_w2h[9 * 128 * 64],  g_w2l[9 * 128 * 64];   // [t][co][ci]
__device__ bf16 g_w3h[9 * 256 * 128], g_w3l[9 * 256 * 128];
__device__ bf16 g_w4h[9 * 512 * 256], g_w4l[9 * 512 * 256];
__device__ float g_mean[64 * 512];
__device__ float g_sent[64 * 512];
__device__ float g_img[64 * 512];
__device__ float g_feats[64 * 1024];
__device__ float g_h1[64 * 512];
__device__ float g_h2[64 * 512];

// ============================ weight prep ============================
__global__ void wprep1_k(const float* __restrict__ w, bf16* __restrict__ wh, bf16* __restrict__ wl) {
    int idx = blockIdx.x * 256 + threadIdx.x;      // 64*64
    if (idx >= 64 * 64) return;
    int co = idx >> 6, k = idx & 63;
    float v = (k < 27) ? w[co * 27 + k] : 0.0f;
    bf16 h, l; bsplit(v, h, l);
    wh[idx] = h; wl[idx] = l;
}
__global__ void wprepT_k(const float* __restrict__ w, bf16* __restrict__ wh, bf16* __restrict__ wl,
                         int COUT, int CIN) {
    int idx = blockIdx.x * 256 + threadIdx.x;      // COUT*CIN*9
    if (idx >= COUT * CIN * 9) return;
    int co = idx / (CIN * 9);
    int rem = idx - co * (CIN * 9);
    int ci = rem / 9, t = rem - ci * 9;
    bf16 h, l; bsplit(w[idx], h, l);
    int o = (t * COUT + co) * CIN + ci;
    wh[o] = h; wl[o] = l;
}

// ============================ warp-level GEMM core ============================
// KSTEPS k16-steps: c += Ah*Bh^T + Ah*Bl^T + Al*Bh^T  (3-term bf16 split)
template <int NFRAG, int KSTEPS, int PIT>
__device__ __forceinline__ void chunk_mma(uint32_t sbA_h, uint32_t sbA_l,
                                          uint32_t sbB_h, uint32_t sbB_l,
                                          int lane, int warpM, int warpN,
                                          float (&c)[2][NFRAG][4]) {
    const int arow = warpM * 32 + (lane & 15);
    const int akoff = (lane >> 4) * 8;
    const int brow = warpN * (NFRAG * 8) + (lane & 7) + ((lane >> 3) & 1) * 8;
    const int bkoff = (lane >> 4) * 8;
#pragma unroll
    for (int ks = 0; ks < KSTEPS; ks++) {
        const int k0 = ks * 16;
        uint32_t ah[2][4], al[2][4];
#pragma unroll
        for (int i = 0; i < 2; i++) {
            const uint32_t aoff = (((arow + i * 16) * PIT) + k0 + akoff) * 2;
            ldsm4(ah[i][0], ah[i][1], ah[i][2], ah[i][3], sbA_h + aoff);
            ldsm4(al[i][0], al[i][1], al[i][2], al[i][3], sbA_l + aoff);
        }
        uint32_t bh[NFRAG][2], bl[NFRAG][2];
#pragma unroll
        for (int j2 = 0; j2 < NFRAG / 2; j2++) {
            const uint32_t boff = (((brow + j2 * 16) * PIT) + k0 + bkoff) * 2;
            uint32_t r0, r1, r2, r3;
            ldsm4(r0, r1, r2, r3, sbB_h + boff);
            bh[2 * j2][0] = r0; bh[2 * j2][1] = r2;
            bh[2 * j2 + 1][0] = r1; bh[2 * j2 + 1][1] = r3;
            ldsm4(r0, r1, r2, r3, sbB_l + boff);
            bl[2 * j2][0] = r0; bl[2 * j2][1] = r2;
            bl[2 * j2 + 1][0] = r1; bl[2 * j2 + 1][1] = r3;
        }
#pragma unroll
        for (int i = 0; i < 2; i++)
#pragma unroll
            for (int j = 0; j < NFRAG; j++) {
                mma16816(c[i][j], ah[i], bh[j]);
                mma16816(c[i][j], ah[i], bl[j]);
                mma16816(c[i][j], al[i], bh[j]);
            }
    }
}

// epilogue: bias + relu + bsplit -> NHWC hi/lo
template <int NFRAG, int COUT>
__device__ __forceinline__ void epilogue(float (&c)[2][NFRAG][4], const float* __restrict__ bias,
                                         int tile0, int cob, int lane, int warpM, int warpN,
                                         bf16* __restrict__ yh, bf16* __restrict__ yl) {
#pragma unroll
    for (int i = 0; i < 2; i++) {
        const int r0 = tile0 + warpM * 32 + i * 16 + (lane >> 2);
#pragma unroll
        for (int j = 0; j < NFRAG; j++) {
            const int col = cob + warpN * (NFRAG * 8) + j * 8 + (lane & 3) * 2;
            const float b0 = bias[col], b1 = bias[col + 1];
#pragma unroll
            for (int h = 0; h < 2; h++) {
                const int r = r0 + h * 8;
                float v0 = c[i][j][2 * h + 0] + b0; if (v0 < 0.0f) v0 = 0.0f;
                float v1 = c[i][j][2 * h + 1] + b1; if (v1 < 0.0f) v1 = 0.0f;
                bf16 h0, l0, h1, l1;
                bsplit(v0, h0, l0); bsplit(v1, h1, l1);
                const size_t o = (size_t)r * COUT + col;
                __nv_bfloat162 ph, pl;
                ph.x = h0; ph.y = h1; pl.x = l0; pl.y = l1;
                *(__nv_bfloat162*)(yh + o) = ph;
                *(__nv_bfloat162*)(yl + o) = pl;
            }
        }
    }
}

// ============================ conv2/3/4: implicit GEMM ============================
// K-chunk 32, cp.async 2-stage pipeline, 80KB smem -> 2 CTAs/SM
template <int CIN, int COUT, int HIN, int WIN>
__global__ void __launch_bounds__(256, 2)
convmm_k(const bf16* __restrict__ xh, const bf16* __restrict__ xl,
         const bf16* __restrict__ wth, const bf16* __restrict__ wtl,
         const float* __restrict__ bias,
         bf16* __restrict__ yh, bf16* __restrict__ yl) {
    constexpr int HOUT = HIN / 2, WOUT = WIN / 2;
    constexpr int CPT = CIN / 32;
    constexpr int NCH = 9 * CPT;
    constexpr int NFRAG = 8;

    extern __shared__ char sb[];
    const uint32_t sb32 = smem_u32(sb);

    const int tid = threadIdx.x, lane = tid & 31, wid = tid >> 5;
    const int warpM = wid >> 1, warpN = wid & 1;
    const int tile0 = blockIdx.x * 128;
    const int cob = blockIdx.y * 128;

    // staging coords: rows (tid>>2) and (tid>>2)+64, 16B segment seg = tid&3
    const int seg = tid & 3;
    int baseoff[2]; bool xe[2], ye[2];
#pragma unroll
    for (int r2 = 0; r2 < 2; r2++) {
        const int row = (tid >> 2) + 64 * r2;
        const int s = tile0 + row;
        const int n = s / (HOUT * WOUT);
        const int rem = s - n * (HOUT * WOUT);
        const int y = rem / WOUT;
        const int x = rem - y * WOUT;
        baseoff[r2] = ((n * HIN + 2 * y) * WIN + 2 * x) * CIN;
        xe[r2] = (2 * x + 2 >= WIN);
        ye[r2] = (2 * y + 2 >= HIN);
    }

    // stage chunk ch into buffer ch&1 via cp.async (4 tiles: Ah, Al, Bh, Bl)
    auto stage = [&](int ch) {
        const int buf = ch & 1;
        const int t = ch / CPT;
        const int cb = (ch - t * CPT) * 32;
        const int ky = t / 3, kx = t - ky * 3;
        const uint32_t base = sb32 + buf * (4 * TB32);
#pragma unroll
        for (int r2 = 0; r2 < 2; r2++) {
            const int row = (tid >> 2) + 64 * r2;
            const uint32_t soff = (row * PIT32 + seg * 8) * 2;
            const bool valid = !((kx == 2 && xe[r2]) || (ky == 2 && ye[r2]));
            const uint32_t vsz = valid ? 16u : 0u;
            const size_t src = (size_t)baseoff[r2] + (ky * WIN + kx) * CIN + cb + seg * 8;
            cp16(base + 0 * TB32 + soff, xh + src, vsz);
            cp16(base + 1 * TB32 + soff, xl + src, vsz);
            const size_t wsrc = ((size_t)t * COUT + cob + row) * CIN + cb + seg * 8;
            cp16(base + 2 * TB32 + soff, wth + wsrc, 16u);
            cp16(base + 3 * TB32 + soff, wtl + wsrc, 16u);
        }
        CP_COMMIT();
    };

    float c[2][NFRAG][4];
#pragma unroll
    for (int i = 0; i < 2; i++)
#pragma unroll
        for (int j = 0; j < NFRAG; j++)
#pragma unroll
            for (int q = 0; q < 4; q++) c[i][j][q] = 0.0f;

    stage(0);
    for (int ch = 0; ch < NCH; ch++) {
        if (ch + 1 < NCH) { stage(ch + 1); CP_WAIT(1); }
        else              { CP_WAIT(0); }
        __syncthreads();
        const uint32_t base = sb32 + (ch & 1) * (4 * TB32);
        chunk_mma<NFRAG, 2, PIT32>(base, base + TB32, base + 2 * TB32, base + 3 * TB32,
                                   lane, warpM, warpN, c);
        __syncthreads();   // buffer safe to overwrite when restaged 2 chunks later
    }

    epilogue<NFRAG, COUT>(c, bias, tile0, cob, lane, warpM, warpN, yh, yl);
}

// ============================ conv1: implicit GEMM, K=27 (padded 64) ============================
__global__ void __launch_bounds__(256, 2)
conv1mm_k(const float* __restrict__ images,
          const bf16* __restrict__ wh, const bf16* __restrict__ wl,
          const float* __restrict__ bias,
          bf16* __restrict__ yh, bf16* __restrict__ yl) {
    constexpr int HOUT = 112, WOUT = 112, HIN = 224, WIN = 224;
    constexpr int NFRAG = 4;   // 64 couts: warp tile 32x32

    extern __shared__ char sb[];
    const uint32_t sb32 = smem_u32(sb);
    const uint32_t oAh = 0, oAl = ATILE_B, oBh = 2 * ATILE_B;
    const uint32_t oBl = 2 * ATILE_B + 64 * PITCH * 2;

    const int tid = threadIdx.x, lane = tid & 31, wid = tid >> 5;
    const int warpM = wid >> 1, warpN = wid & 1;
    const int tile0 = blockIdx.x * 128;

    // A staging: thread owns k = tid&63, rows (tid>>6)+4i
    {
        const int k = tid & 63;
        const int r0 = tid >> 6;
        int ci = 0, ky = 0, kx = 0;
        const bool kvalid = (k < 27);
        if (kvalid) { ci = k / 9; int r = k - ci * 9; ky = r / 3; kx = r - ky * 3; }
        for (int i = 0; i < 32; i++) {
            const int row = r0 + 4 * i;
            bf16 h = __float2bfloat16(0.0f), l = __float2bfloat16(0.0f);
            if (kvalid) {
                const int s = tile0 + row;
                const int n = s / (HOUT * WOUT);
                const int rem = s - n * (HOUT * WOUT);
                const int y = rem / WOUT;
                const int x = rem - y * WOUT;
                const int iy = 2 * y + ky, ix = 2 * x + kx;
                if (iy < HIN && ix < WIN) {
                    float v = images[((size_t)(n * 3 + ci) * HIN + iy) * WIN + ix];
                    bsplit(v, h, l);
                }
            }
            const uint32_t soff = (row * PITCH + k) * 2;
            *(bf16*)(sb + oAh + soff) = h;
            *(bf16*)(sb + oAl + soff) = l;
        }
    }
    // B staging: 64 rows x 8 c16
    for (int idx = tid; idx < 512; idx += 256) {
        const int row = idx >> 3, c16 = idx & 7;
        const uint32_t soff = (row * PITCH + c16 * 8) * 2;
        *(uint4*)(sb + oBh + soff) = *(const uint4*)(wh + row * 64 + c16 * 8);
        *(uint4*)(sb + oBl + soff) = *(const uint4*)(wl + row * 64 + c16 * 8);
    }
    __syncthreads();

    float c[2][NFRAG][4];
#pragma unroll
    for (int i = 0; i < 2; i++)
#pragma unroll
        for (int j = 0; j < NFRAG; j++)
#pragma unroll
            for (int q = 0; q < 4; q++) c[i][j][q] = 0.0f;

    chunk_mma<NFRAG, 4, PITCH>(sb32 + oAh, sb32 + oAl, sb32 + oBh, sb32 + oBl,
                               lane, warpM, warpN, c);

    epilogue<NFRAG, 64>(c, bias, tile0, 0, lane, warpM, warpN, yh, yl);
}

// ============================ misc kernels ============================
__global__ void embed_mean_k(const int* __restrict__ seq, const int* __restrict__ len,
                             const float* __restrict__ emb, float* __restrict__ mean) {
    const int b = blockIdx.x;
    const int L = len[b];
    __shared__ int s_idx[128];
    for (int i = threadIdx.x; i < 128; i += blockDim.x) s_idx[i] = seq[b * 128 + i];
    __syncthreads();
    const float inv = 1.0f / (float)L;
    for (int d = threadIdx.x; d < 512; d += blockDim.x) {
        float acc = 0.0f;
        for (int s = 0; s < L; s++) acc += emb[(size_t)s_idx[s] * 512 + d];
        mean[b * 512 + d] = acc * inv;
    }
}

__global__ void linear_k(const float* __restrict__ X, const float* __restrict__ W,
                         const float* __restrict__ bias, float* __restrict__ Y,
                         int K, int N, int relu) {
    const int j = blockIdx.x * blockDim.x + threadIdx.x;
    const int b = blockIdx.y;
    if (j >= N) return;
    const float* x = X + (size_t)b * K;
    float acc = bias[j];
    for (int k = 0; k < K; k++) acc = fmaf(x[k], W[(size_t)k * N + j], acc);
    if (relu && acc < 0.0f) acc = 0.0f;
    Y[(size_t)b * N + j] = acc;
}

// pool over 196 spatial (NHWC hi/lo), thread per (n,c)
__global__ void pool2_k(const bf16* __restrict__ xh, const bf16* __restrict__ xl,
                        float* __restrict__ y) {
    const int idx = blockIdx.x * 256 + threadIdx.x;   // 64*512
    const int n = idx >> 9, c = idx & 511;
    const bf16* ph = xh + (size_t)n * 196 * 512 + c;
    const bf16* pl = xl + (size_t)n * 196 * 512 + c;
    float s = 0.0f;
    for (int p = 0; p < 196; p++)
        s += __bfloat162float(ph[(size_t)p * 512]) + __bfloat162float(pl[(size_t)p * 512]);
    y[idx] = s * (1.0f / 196.0f);
}

__global__ void concat_k(const float* __restrict__ img, const float* __restrict__ sent,
                         float* __restrict__ feats) {
    const int i = blockIdx.x * blockDim.x + threadIdx.x;
    const int b = i >> 10, j = i & 1023;
    feats[i] = (j < 512) ? img[b * 512 + j] : sent[b * 512 + (j - 512)];
}

// ============================ launch ============================
extern "C" void kernel_launch(void* const* d_in, const int* in_sizes, int n_in,
                              void* d_out, int out_size) {
    const float* images = (const float*)d_in[0];
    const int*   seq    = (const int*)d_in[1];
    const int*   len    = (const int*)d_in[2];
    const float* emb    = (const float*)d_in[4];
    const float* cw1 = (const float*)d_in[5],  *cb1 = (const float*)d_in[6];
    const float* cw2 = (const float*)d_in[7],  *cb2 = (const float*)d_in[8];
    const float* cw3 = (const float*)d_in[9],  *cb3 = (const float*)d_in[10];
    const float* cw4 = (const float*)d_in[11], *cb4 = (const float*)d_in[12];
    const float* rnn_w = (const float*)d_in[13], *rnn_b = (const float*)d_in[14];
    const float* fc1_w = (const float*)d_in[15], *fc1_b = (const float*)d_in[16];
    const float* fc2_w = (const float*)d_in[17], *fc2_b = (const float*)d_in[18];
    const float* clf_w = (const float*)d_in[19], *clf_b = (const float*)d_in[20];
    float* out = (float*)d_out;

    bf16 *x1h, *x1l, *x2h, *x2l, *x3h, *x3l, *x4h, *x4l;
    bf16 *w1h, *w1l, *w2h, *w2l, *w3h, *w3l, *w4h, *w4l;
    float *mean, *sent, *img, *feats, *h1, *h2;
    cudaGetSymbolAddress((void**)&x1h, g_x1h); cudaGetSymbolAddress((void**)&x1l, g_x1l);
    cudaGetSymbolAddress((void**)&x2h, g_x2h); cudaGetSymbolAddress((void**)&x2l, g_x2l);
    cudaGetSymbolAddress((void**)&x3h, g_x3h); cudaGetSymbolAddress((void**)&x3l, g_x3l);
    cudaGetSymbolAddress((void**)&x4h, g_x4h); cudaGetSymbolAddress((void**)&x4l, g_x4l);
    cudaGetSymbolAddress((void**)&w1h, g_w1h); cudaGetSymbolAddress((void**)&w1l, g_w1l);
    cudaGetSymbolAddress((void**)&w2h, g_w2h); cudaGetSymbolAddress((void**)&w2l, g_w2l);
    cudaGetSymbolAddress((void**)&w3h, g_w3h); cudaGetSymbolAddress((void**)&w3l, g_w3l);
    cudaGetSymbolAddress((void**)&w4h, g_w4h); cudaGetSymbolAddress((void**)&w4l, g_w4l);
    cudaGetSymbolAddress((void**)&mean, g_mean); cudaGetSymbolAddress((void**)&sent, g_sent);
    cudaGetSymbolAddress((void**)&img, g_img);   cudaGetSymbolAddress((void**)&feats, g_feats);
    cudaGetSymbolAddress((void**)&h1, g_h1);     cudaGetSymbolAddress((void**)&h2, g_h2);

    const int smem234 = 2 * 4 * TB32;                   // 81920 (double-buffered, 2 CTAs/SM)
    const int smem1 = 2 * ATILE_B + 2 * 64 * PITCH * 2; // 55296
    cudaFuncSetAttribute(conv1mm_k, cudaFuncAttributeMaxDynamicSharedMemorySize, smem1);
    cudaFuncSetAttribute(convmm_k<64, 128, 112, 112>, cudaFuncAttributeMaxDynamicSharedMemorySize, smem234);
    cudaFuncSetAttribute(convmm_k<128, 256, 56, 56>,  cudaFuncAttributeMaxDynamicSharedMemorySize, smem234);
    cudaFuncSetAttribute(convmm_k<256, 512, 28, 28>,  cudaFuncAttributeMaxDynamicSharedMemorySize, smem234);

    // weight prep
    wprep1_k<<<16, 256>>>(cw1, w1h, w1l);
    wprepT_k<<<(128 * 64 * 9 + 255) / 256, 256>>>(cw2, w2h, w2l, 128, 64);
    wprepT_k<<<(256 * 128 * 9 + 255) / 256, 256>>>(cw3, w3h, w3l, 256, 128);
    wprepT_k<<<(512 * 256 * 9 + 255) / 256, 256>>>(cw4, w4h, w4l, 512, 256);

    // text branch
    embed_mean_k<<<64, 512>>>(seq, len, emb, mean);
    linear_k<<<dim3(2, 64), 256>>>(mean, rnn_w, rnn_b, sent, 512, 512, 0);

    // vision branch (implicit GEMM, NHWC bf16 hi/lo, mma.sync + cp.async pipeline)
    conv1mm_k<<<6272, 256, smem1>>>(images, w1h, w1l, cb1, x1h, x1l);
    convmm_k<64, 128, 112, 112><<<dim3(1568, 1), 256, smem234>>>(x1h, x1l, w2h, w2l, cb2, x2h, x2l);
    convmm_k<128, 256, 56, 56><<<dim3(392, 2), 256, smem234>>>(x2h, x2l, w3h, w3l, cb3, x3h, x3l);
    convmm_k<256, 512, 28, 28><<<dim3(98, 4), 256, smem234>>>(x3h, x3l, w4h, w4l, cb4, x4h, x4l);
    pool2_k<<<128, 256>>>(x4h, x4l, img);

    // head
    concat_k<<<(64 * 1024) / 256, 256>>>(img, sent, feats);
    linear_k<<<dim3(2, 64), 256>>>(feats, fc1_w, fc1_b, h1, 1024, 512, 1);
    linear_k<<<dim3(2, 64), 256>>>(h1, fc2_w, fc2_b, h2, 512, 512, 1);
    linear_k<<<dim3(4, 64), 256>>>(h2, clf_w, clf_b, out, 512, 1000, 0);
}

// round 9
// speedup vs baseline: 1.3749x; 1.3560x over previous
#include <cuda_runtime.h>
#include <cuda_fp16.h>
#include <cstdint>
#include <cstddef>

typedef __half h16;

// ============================ helpers ============================
__device__ __forceinline__ uint32_t smem_u32(const void* p) {
    uint32_t a;
    asm("{ .reg .u64 t; cvta.to.shared.u64 t, %1; cvt.u32.u64 %0, t; }" : "=r"(a) : "l"(p));
    return a;
}
__device__ __forceinline__ void ldsm4(uint32_t& r0, uint32_t& r1, uint32_t& r2, uint32_t& r3,
                                      uint32_t addr) {
    asm volatile("ldmatrix.sync.aligned.m8n8.x4.shared.b16 {%0,%1,%2,%3}, [%4];"
                 : "=r"(r0), "=r"(r1), "=r"(r2), "=r"(r3) : "r"(addr));
}
__device__ __forceinline__ void mma16816(float c[4], const uint32_t a[4], const uint32_t b[2]) {
    asm volatile(
        "mma.sync.aligned.m16n8k16.row.col.f32.f16.f16.f32 "
        "{%0,%1,%2,%3}, {%4,%5,%6,%7}, {%8,%9}, {%0,%1,%2,%3};"
        : "+f"(c[0]), "+f"(c[1]), "+f"(c[2]), "+f"(c[3])
        : "r"(a[0]), "r"(a[1]), "r"(a[2]), "r"(a[3]), "r"(b[0]), "r"(b[1]));
}
// split fp32 into fp16 hi + lo (hi+lo captures ~22 mantissa bits)
__device__ __forceinline__ void hsplit(float v, h16& h, h16& l) {
    h = __float2half_rn(v);
    l = __float2half_rn(v - __half2float(h));
}

// smem tile pitch: 72 h16 (144 B) -> row stride 36 words -> ldmatrix conflict-free
static constexpr int PITCH = 72;
static constexpr int ATILE_B = 128 * PITCH * 2;   // 18432 bytes per 128x64 tile

// ============================ scratch ============================
__device__ h16 g_x1h[(size_t)64 * 112 * 112 * 64];
__device__ h16 g_x1l[(size_t)64 * 112 * 112 * 64];
__device__ h16 g_x2h[(size_t)64 * 56 * 56 * 128];
__device__ h16 g_x2l[(size_t)64 * 56 * 56 * 128];
__device__ h16 g_x3h[(size_t)64 * 28 * 28 * 256];
__device__ h16 g_x3l[(size_t)64 * 28 * 28 * 256];
__device__ h16 g_x4h[(size_t)64 * 14 * 14 * 512];
__device__ h16 g_x4l[(size_t)64 * 14 * 14 * 512];
__device__ h16 g_w1h[64 * 64];               // conv1 padded [co][64]
__device__ h16 g_w2h[9 * 128 * 64];          // [t][co][ci]
__device__ h16 g_w3h[9 * 256 * 128];
__device__ h16 g_w4h[9 * 512 * 256];
__device__ float g_mean[64 * 512];
__device__ float g_sent[64 * 512];
__device__ float g_img[64 * 512];
__device__ float g_feats[64 * 1024];
__device__ float g_h1[64 * 512];
__device__ float g_h2[64 * 512];

// ============================ weight prep (hi only) ============================
__global__ void wprep1_k(const float* __restrict__ w, h16* __restrict__ wh) {
    int idx = blockIdx.x * 256 + threadIdx.x;      // 64*64
    if (idx >= 64 * 64) return;
    int co = idx >> 6, k = idx & 63;
    float v = (k < 27) ? w[co * 27 + k] : 0.0f;
    wh[idx] = __float2half_rn(v);
}
__global__ void wprepT_k(const float* __restrict__ w, h16* __restrict__ wh,
                         int COUT, int CIN) {
    int idx = blockIdx.x * 256 + threadIdx.x;      // COUT*CIN*9
    if (idx >= COUT * CIN * 9) return;
    int co = idx / (CIN * 9);
    int rem = idx - co * (CIN * 9);
    int ci = rem / 9, t = rem - ci * 9;
    wh[(t * COUT + co) * CIN + ci] = __float2half_rn(w[idx]);
}

// ============================ warp-level GEMM core ============================
// one 64-wide k chunk, 2-term split: c += Ah*Bh^T + Al*Bh^T   (A exact h+l, B fp16-rounded)
template <int NFRAG>
__device__ __forceinline__ void chunk_mma(uint32_t sbA_h, uint32_t sbA_l, uint32_t sbB_h,
                                          int lane, int warpM, int warpN,
                                          float (&c)[2][NFRAG][4]) {
    const int arow = warpM * 32 + (lane & 15);
    const int akoff = (lane >> 4) * 8;
    const int brow = warpN * (NFRAG * 8) + (lane & 7) + ((lane >> 3) & 1) * 8;
    const int bkoff = (lane >> 4) * 8;
#pragma unroll
    for (int ks = 0; ks < 4; ks++) {
        const int k0 = ks * 16;
        uint32_t ah[2][4], al[2][4];
#pragma unroll
        for (int i = 0; i < 2; i++) {
            const uint32_t aoff = (((arow + i * 16) * PITCH) + k0 + akoff) * 2;
            ldsm4(ah[i][0], ah[i][1], ah[i][2], ah[i][3], sbA_h + aoff);
            ldsm4(al[i][0], al[i][1], al[i][2], al[i][3], sbA_l + aoff);
        }
        uint32_t bh[NFRAG][2];
#pragma unroll
        for (int j2 = 0; j2 < NFRAG / 2; j2++) {
            const uint32_t boff = (((brow + j2 * 16) * PITCH) + k0 + bkoff) * 2;
            uint32_t r0, r1, r2, r3;
            ldsm4(r0, r1, r2, r3, sbB_h + boff);
            bh[2 * j2][0] = r0; bh[2 * j2][1] = r2;
            bh[2 * j2 + 1][0] = r1; bh[2 * j2 + 1][1] = r3;
        }
#pragma unroll
        for (int i = 0; i < 2; i++)
#pragma unroll
            for (int j = 0; j < NFRAG; j++) {
                mma16816(c[i][j], ah[i], bh[j]);
                mma16816(c[i][j], al[i], bh[j]);
            }
    }
}

// epilogue: bias + relu + hsplit -> NHWC hi/lo
template <int NFRAG, int COUT>
__device__ __forceinline__ void epilogue(float (&c)[2][NFRAG][4], const float* __restrict__ bias,
                                         int tile0, int cob, int lane, int warpM, int warpN,
                                         h16* __restrict__ yh, h16* __restrict__ yl) {
#pragma unroll
    for (int i = 0; i < 2; i++) {
        const int r0 = tile0 + warpM * 32 + i * 16 + (lane >> 2);
#pragma unroll
        for (int j = 0; j < NFRAG; j++) {
            const int col = cob + warpN * (NFRAG * 8) + j * 8 + (lane & 3) * 2;
            const float b0 = bias[col], b1 = bias[col + 1];
#pragma unroll
            for (int h = 0; h < 2; h++) {
                const int r = r0 + h * 8;
                float v0 = c[i][j][2 * h + 0] + b0; if (v0 < 0.0f) v0 = 0.0f;
                float v1 = c[i][j][2 * h + 1] + b1; if (v1 < 0.0f) v1 = 0.0f;
                h16 h0, l0, h1, l1;
                hsplit(v0, h0, l0); hsplit(v1, h1, l1);
                const size_t o = (size_t)r * COUT + col;
                __half2 ph, pl;
                ph.x = h0; ph.y = h1; pl.x = l0; pl.y = l1;
                *(__half2*)(yh + o) = ph;
                *(__half2*)(yl + o) = pl;
            }
        }
    }
}

// ============================ conv2/3/4: implicit GEMM (sync staging, 2 CTAs/SM) ============================
template <int CIN, int COUT, int HIN, int WIN>
__global__ void __launch_bounds__(256, 2)
convmm_k(const h16* __restrict__ xh, const h16* __restrict__ xl,
         const h16* __restrict__ wth,
         const float* __restrict__ bias,
         h16* __restrict__ yh, h16* __restrict__ yl) {
    constexpr int HOUT = HIN / 2, WOUT = WIN / 2;
    constexpr int CPT = CIN / 64;
    constexpr int NCH = 9 * CPT;
    constexpr int NFRAG = 8;

    extern __shared__ char sb[];
    const uint32_t sb32 = smem_u32(sb);
    const uint32_t oAh = 0, oAl = ATILE_B, oBh = 2 * ATILE_B;

    const int tid = threadIdx.x, lane = tid & 31, wid = tid >> 5;
    const int warpM = wid >> 1, warpN = wid & 1;
    const int tile0 = blockIdx.x * 128;
    const int cob = blockIdx.y * 128;

    // staging coords: 4 slots per thread; row = (tid>>3)+32*r4, c16 = tid&7
    const int c16 = tid & 7;
    int baseoff[4]; bool xe[4], ye[4];
#pragma unroll
    for (int r4 = 0; r4 < 4; r4++) {
        const int row = (tid >> 3) + 32 * r4;
        const int s = tile0 + row;
        const int n = s / (HOUT * WOUT);
        const int rem = s - n * (HOUT * WOUT);
        const int y = rem / WOUT;
        const int x = rem - y * WOUT;
        baseoff[r4] = ((n * HIN + 2 * y) * WIN + 2 * x) * CIN;
        xe[r4] = (2 * x + 2 >= WIN);
        ye[r4] = (2 * y + 2 >= HIN);
    }

    float c[2][NFRAG][4];
#pragma unroll
    for (int i = 0; i < 2; i++)
#pragma unroll
        for (int j = 0; j < NFRAG; j++)
#pragma unroll
            for (int q = 0; q < 4; q++) c[i][j][q] = 0.0f;

    for (int ch = 0; ch < NCH; ch++) {
        const int t = ch / CPT;
        const int cb = (ch - t * CPT) * 64;
        const int ky = t / 3, kx = t - ky * 3;
        __syncthreads();   // protect smem from previous chunk's readers
#pragma unroll
        for (int r4 = 0; r4 < 4; r4++) {
            const int row = (tid >> 3) + 32 * r4;
            const uint32_t soff = (row * PITCH + c16 * 8) * 2;
            const bool valid = !((kx == 2 && xe[r4]) || (ky == 2 && ye[r4]));
            const size_t src = (size_t)baseoff[r4] + (ky * WIN + kx) * CIN + cb + c16 * 8;
            uint4 vh = make_uint4(0, 0, 0, 0), vl = make_uint4(0, 0, 0, 0);
            if (valid) { vh = *(const uint4*)(xh + src); vl = *(const uint4*)(xl + src); }
            *(uint4*)(sb + oAh + soff) = vh;
            *(uint4*)(sb + oAl + soff) = vl;
            const size_t wsrc = ((size_t)t * COUT + cob + row) * CIN + cb + c16 * 8;
            *(uint4*)(sb + oBh + soff) = *(const uint4*)(wth + wsrc);
        }
        __syncthreads();
        chunk_mma<NFRAG>(sb32 + oAh, sb32 + oAl, sb32 + oBh, lane, warpM, warpN, c);
    }

    epilogue<NFRAG, COUT>(c, bias, tile0, cob, lane, warpM, warpN, yh, yl);
}

// ============================ conv1: implicit GEMM, K=27 (padded 64) ============================
__global__ void __launch_bounds__(256, 2)
conv1mm_k(const float* __restrict__ images,
          const h16* __restrict__ wh,
          const float* __restrict__ bias,
          h16* __restrict__ yh, h16* __restrict__ yl) {
    constexpr int HOUT = 112, WOUT = 112, HIN = 224, WIN = 224;
    constexpr int NFRAG = 4;   // 64 couts: warp tile 32x32

    extern __shared__ char sb[];
    const uint32_t sb32 = smem_u32(sb);
    const uint32_t oAh = 0, oAl = ATILE_B, oBh = 2 * ATILE_B;

    const int tid = threadIdx.x, lane = tid & 31, wid = tid >> 5;
    const int warpM = wid >> 1, warpN = wid & 1;
    const int tile0 = blockIdx.x * 128;

    // A staging: thread owns k = tid&63, rows (tid>>6)+4i
    {
        const int k = tid & 63;
        const int r0 = tid >> 6;
        int ci = 0, ky = 0, kx = 0;
        const bool kvalid = (k < 27);
        if (kvalid) { ci = k / 9; int r = k - ci * 9; ky = r / 3; kx = r - ky * 3; }
        for (int i = 0; i < 32; i++) {
            const int row = r0 + 4 * i;
            h16 h = __float2half_rn(0.0f), l = __float2half_rn(0.0f);
            if (kvalid) {
                const int s = tile0 + row;
                const int n = s / (HOUT * WOUT);
                const int rem = s - n * (HOUT * WOUT);
                const int y = rem / WOUT;
                const int x = rem - y * WOUT;
                const int iy = 2 * y + ky, ix = 2 * x + kx;
                if (iy < HIN && ix < WIN) {
                    float v = images[((size_t)(n * 3 + ci) * HIN + iy) * WIN + ix];
                    hsplit(v, h, l);
                }
            }
            const uint32_t soff = (row * PITCH + k) * 2;
            *(h16*)(sb + oAh + soff) = h;
            *(h16*)(sb + oAl + soff) = l;
        }
    }
    // B staging: 64 rows x 8 c16
    for (int idx = tid; idx < 512; idx += 256) {
        const int row = idx >> 3, c16 = idx & 7;
        const uint32_t soff = (row * PITCH + c16 * 8) * 2;
        *(uint4*)(sb + oBh + soff) = *(const uint4*)(wh + row * 64 + c16 * 8);
    }
    __syncthreads();

    float c[2][NFRAG][4];
#pragma unroll
    for (int i = 0; i < 2; i++)
#pragma unroll
        for (int j = 0; j < NFRAG; j++)
#pragma unroll
            for (int q = 0; q < 4; q++) c[i][j][q] = 0.0f;

    chunk_mma<NFRAG>(sb32 + oAh, sb32 + oAl, sb32 + oBh, lane, warpM, warpN, c);

    epilogue<NFRAG, 64>(c, bias, tile0, 0, lane, warpM, warpN, yh, yl);
}

// ============================ misc kernels ============================
__global__ void embed_mean_k(const int* __restrict__ seq, const int* __restrict__ len,
                             const float* __restrict__ emb, float* __restrict__ mean) {
    const int b = blockIdx.x;
    const int L = len[b];
    __shared__ int s_idx[128];
    for (int i = threadIdx.x; i < 128; i += blockDim.x) s_idx[i] = seq[b * 128 + i];
    __syncthreads();
    const float inv = 1.0f / (float)L;
    for (int d = threadIdx.x; d < 512; d += blockDim.x) {
        float acc = 0.0f;
        for (int s = 0; s < L; s++) acc += emb[(size_t)s_idx[s] * 512 + d];
        mean[b * 512 + d] = acc * inv;
    }
}

__global__ void linear_k(const float* __restrict__ X, const float* __restrict__ W,
                         const float* __restrict__ bias, float* __restrict__ Y,
                         int K, int N, int relu) {
    const int j = blockIdx.x * blockDim.x + threadIdx.x;
    const int b = blockIdx.y;
    if (j >= N) return;
    const float* x = X + (size_t)b * K;
    float acc = bias[j];
    for (int k = 0; k < K; k++) acc = fmaf(x[k], W[(size_t)k * N + j], acc);
    if (relu && acc < 0.0f) acc = 0.0f;
    Y[(size_t)b * N + j] = acc;
}

// pool over 196 spatial (NHWC hi/lo), thread per (n,c)
__global__ void pool2_k(const h16* __restrict__ xh, const h16* __restrict__ xl,
                        float* __restrict__ y) {
    const int idx = blockIdx.x * 256 + threadIdx.x;   // 64*512
    const int n = idx >> 9, c = idx & 511;
    const h16* ph = xh + (size_t)n * 196 * 512 + c;
    const h16* pl = xl + (size_t)n * 196 * 512 + c;
    float s = 0.0f;
    for (int p = 0; p < 196; p++)
        s += __half2float(ph[(size_t)p * 512]) + __half2float(pl[(size_t)p * 512]);
    y[idx] = s * (1.0f / 196.0f);
}

__global__ void concat_k(const float* __restrict__ img, const float* __restrict__ sent,
                         float* __restrict__ feats) {
    const int i = blockIdx.x * blockDim.x + threadIdx.x;
    const int b = i >> 10, j = i & 1023;
    feats[i] = (j < 512) ? img[b * 512 + j] : sent[b * 512 + (j - 512)];
}

// ============================ launch ============================
extern "C" void kernel_launch(void* const* d_in, const int* in_sizes, int n_in,
                              void* d_out, int out_size) {
    const float* images = (const float*)d_in[0];
    const int*   seq    = (const int*)d_in[1];
    const int*   len    = (const int*)d_in[2];
    const float* emb    = (const float*)d_in[4];
    const float* cw1 = (const float*)d_in[5],  *cb1 = (const float*)d_in[6];
    const float* cw2 = (const float*)d_in[7],  *cb2 = (const float*)d_in[8];
    const float* cw3 = (const float*)d_in[9],  *cb3 = (const float*)d_in[10];
    const float* cw4 = (const float*)d_in[11], *cb4 = (const float*)d_in[12];
    const float* rnn_w = (const float*)d_in[13], *rnn_b = (const float*)d_in[14];
    const float* fc1_w = (const float*)d_in[15], *fc1_b = (const float*)d_in[16];
    const float* fc2_w = (const float*)d_in[17], *fc2_b = (const float*)d_in[18];
    const float* clf_w = (const float*)d_in[19], *clf_b = (const float*)d_in[20];
    float* out = (float*)d_out;

    h16 *x1h, *x1l, *x2h, *x2l, *x3h, *x3l, *x4h, *x4l;
    h16 *w1h, *w2h, *w3h, *w4h;
    float *mean, *sent, *img, *feats, *h1, *h2;
    cudaGetSymbolAddress((void**)&x1h, g_x1h); cudaGetSymbolAddress((void**)&x1l, g_x1l);
    cudaGetSymbolAddress((void**)&x2h, g_x2h); cudaGetSymbolAddress((void**)&x2l, g_x2l);
    cudaGetSymbolAddress((void**)&x3h, g_x3h); cudaGetSymbolAddress((void**)&x3l, g_x3l);
    cudaGetSymbolAddress((void**)&x4h, g_x4h); cudaGetSymbolAddress((void**)&x4l, g_x4l);
    cudaGetSymbolAddress((void**)&w1h, g_w1h); cudaGetSymbolAddress((void**)&w2h, g_w2h);
    cudaGetSymbolAddress((void**)&w3h, g_w3h); cudaGetSymbolAddress((void**)&w4h, g_w4h);
    cudaGetSymbolAddress((void**)&mean, g_mean); cudaGetSymbolAddress((void**)&sent, g_sent);
    cudaGetSymbolAddress((void**)&img, g_img);   cudaGetSymbolAddress((void**)&feats, g_feats);
    cudaGetSymbolAddress((void**)&h1, g_h1);     cudaGetSymbolAddress((void**)&h2, g_h2);

    const int smem234 = 3 * ATILE_B;   // 55296 -> 2 CTAs/SM
    const int smem1 = 3 * ATILE_B;
    cudaFuncSetAttribute(conv1mm_k, cudaFuncAttributeMaxDynamicSharedMemorySize, smem1);
    cudaFuncSetAttribute(convmm_k<64, 128, 112, 112>, cudaFuncAttributeMaxDynamicSharedMemorySize, smem234);
    cudaFuncSetAttribute(convmm_k<128, 256, 56, 56>,  cudaFuncAttributeMaxDynamicSharedMemorySize, smem234);
    cudaFuncSetAttribute(convmm_k<256, 512, 28, 28>,  cudaFuncAttributeMaxDynamicSharedMemorySize, smem234);

    // weight prep (launches 1-4)
    wprep1_k<<<16, 256>>>(cw1, w1h);
    wprepT_k<<<(128 * 64 * 9 + 255) / 256, 256>>>(cw2, w2h, 128, 64);
    wprepT_k<<<(256 * 128 * 9 + 255) / 256, 256>>>(cw3, w3h, 256, 128);
    wprepT_k<<<(512 * 256 * 9 + 255) / 256, 256>>>(cw4, w4h, 512, 256);

    // vision branch (launches 5-9; conv2 is launch #6 for ncu -s 5)
    conv1mm_k<<<6272, 256, smem1>>>(images, w1h, cb1, x1h, x1l);
    convmm_k<64, 128, 112, 112><<<dim3(1568, 1), 256, smem234>>>(x1h, x1l, w2h, cb2, x2h, x2l);
    convmm_k<128, 256, 56, 56><<<dim3(392, 2), 256, smem234>>>(x2h, x2l, w3h, cb3, x3h, x3l);
    convmm_k<256, 512, 28, 28><<<dim3(98, 4), 256, smem234>>>(x3h, x3l, w4h, cb4, x4h, x4l);
    pool2_k<<<128, 256>>>(x4h, x4l, img);

    // text branch
    embed_mean_k<<<64, 512>>>(seq, len, emb, mean);
    linear_k<<<dim3(2, 64), 256>>>(mean, rnn_w, rnn_b, sent, 512, 512, 0);

    // head
    concat_k<<<(64 * 1024) / 256, 256>>>(img, sent, feats);
    linear_k<<<dim3(2, 64), 256>>>(feats, fc1_w, fc1_b, h1, 1024, 512, 1);
    linear_k<<<dim3(2, 64), 256>>>(h1, fc2_w, fc2_b, h2, 512, 512, 1);
    linear_k<<<dim3(4, 64), 256>>>(h2, clf_w, clf_b, out, 512, 1000, 0);
}

// round 10
// speedup vs baseline: 1.8830x; 1.3695x over previous
#include <cuda_runtime.h>
#include <cuda_fp16.h>
#include <cstdint>
#include <cstddef>

typedef __half h16;

// ============================ helpers ============================
__device__ __forceinline__ uint32_t smem_u32(const void* p) {
    uint32_t a;
    asm("{ .reg .u64 t; cvta.to.shared.u64 t, %1; cvt.u32.u64 %0, t; }" : "=r"(a) : "l"(p));
    return a;
}
__device__ __forceinline__ void ldsm4(uint32_t& r0, uint32_t& r1, uint32_t& r2, uint32_t& r3,
                                      uint32_t addr) {
    asm volatile("ldmatrix.sync.aligned.m8n8.x4.shared.b16 {%0,%1,%2,%3}, [%4];"
                 : "=r"(r0), "=r"(r1), "=r"(r2), "=r"(r3) : "r"(addr));
}
__device__ __forceinline__ void mma16816(float c[4], const uint32_t a[4], const uint32_t b[2]) {
    asm volatile(
        "mma.sync.aligned.m16n8k16.row.col.f32.f16.f16.f32 "
        "{%0,%1,%2,%3}, {%4,%5,%6,%7}, {%8,%9}, {%0,%1,%2,%3};"
        : "+f"(c[0]), "+f"(c[1]), "+f"(c[2]), "+f"(c[3])
        : "r"(a[0]), "r"(a[1]), "r"(a[2]), "r"(a[3]), "r"(b[0]), "r"(b[1]));
}

// smem tile pitch: 72 h16 (144 B) -> row stride 36 words -> ldmatrix conflict-free
static constexpr int PITCH = 72;
static constexpr int ATILE_B = 128 * PITCH * 2;   // 18432 bytes per 128x64 tile

// ============================ scratch ============================
__device__ h16 g_x1[(size_t)64 * 112 * 112 * 64];
__device__ h16 g_x2[(size_t)64 * 56 * 56 * 128];
__device__ h16 g_x3[(size_t)64 * 28 * 28 * 256];
__device__ h16 g_x4[(size_t)64 * 14 * 14 * 512];
__device__ h16 g_w1[64 * 64];               // conv1 padded [co][64]
__device__ h16 g_w2[9 * 128 * 64];          // [t][co][ci]
__device__ h16 g_w3[9 * 256 * 128];
__device__ h16 g_w4[9 * 512 * 256];
__device__ float g_mean[64 * 512];
__device__ float g_sent[64 * 512];
__device__ float g_img[64 * 512];
__device__ float g_feats[64 * 1024];
__device__ float g_h1[64 * 512];
__device__ float g_h2[64 * 512];

// ============================ weight prep ============================
__global__ void wprep1_k(const float* __restrict__ w, h16* __restrict__ wh) {
    int idx = blockIdx.x * 256 + threadIdx.x;      // 64*64
    if (idx >= 64 * 64) return;
    int co = idx >> 6, k = idx & 63;
    float v = (k < 27) ? w[co * 27 + k] : 0.0f;
    wh[idx] = __float2half_rn(v);
}
__global__ void wprepT_k(const float* __restrict__ w, h16* __restrict__ wh,
                         int COUT, int CIN) {
    int idx = blockIdx.x * 256 + threadIdx.x;      // COUT*CIN*9
    if (idx >= COUT * CIN * 9) return;
    int co = idx / (CIN * 9);
    int rem = idx - co * (CIN * 9);
    int ci = rem / 9, t = rem - ci * 9;
    wh[(t * COUT + co) * CIN + ci] = __float2half_rn(w[idx]);
}

// ============================ warp-level GEMM core ============================
// one 64-wide k chunk, 1-term: c += A*B^T  (both fp16-rounded, fp32 accum)
template <int NFRAG>
__device__ __forceinline__ void chunk_mma(uint32_t sbA, uint32_t sbB,
                                          int lane, int warpM, int warpN,
                                          float (&c)[2][NFRAG][4]) {
    const int arow = warpM * 32 + (lane & 15);
    const int akoff = (lane >> 4) * 8;
    const int brow = warpN * (NFRAG * 8) + (lane & 7) + ((lane >> 3) & 1) * 8;
    const int bkoff = (lane >> 4) * 8;
#pragma unroll
    for (int ks = 0; ks < 4; ks++) {
        const int k0 = ks * 16;
        uint32_t ah[2][4];
#pragma unroll
        for (int i = 0; i < 2; i++) {
            const uint32_t aoff = (((arow + i * 16) * PITCH) + k0 + akoff) * 2;
            ldsm4(ah[i][0], ah[i][1], ah[i][2], ah[i][3], sbA + aoff);
        }
        uint32_t bh[NFRAG][2];
#pragma unroll
        for (int j2 = 0; j2 < NFRAG / 2; j2++) {
            const uint32_t boff = (((brow + j2 * 16) * PITCH) + k0 + bkoff) * 2;
            uint32_t r0, r1, r2, r3;
            ldsm4(r0, r1, r2, r3, sbB + boff);
            bh[2 * j2][0] = r0; bh[2 * j2][1] = r2;
            bh[2 * j2 + 1][0] = r1; bh[2 * j2 + 1][1] = r3;
        }
#pragma unroll
        for (int i = 0; i < 2; i++)
#pragma unroll
            for (int j = 0; j < NFRAG; j++)
                mma16816(c[i][j], ah[i], bh[j]);
    }
}

// epilogue: bias + relu + cvt -> NHWC fp16
template <int NFRAG, int COUT>
__device__ __forceinline__ void epilogue(float (&c)[2][NFRAG][4], const float* __restrict__ bias,
                                         int tile0, int cob, int lane, int warpM, int warpN,
                                         h16* __restrict__ y) {
#pragma unroll
    for (int i = 0; i < 2; i++) {
        const int r0 = tile0 + warpM * 32 + i * 16 + (lane >> 2);
#pragma unroll
        for (int j = 0; j < NFRAG; j++) {
            const int col = cob + warpN * (NFRAG * 8) + j * 8 + (lane & 3) * 2;
            const float b0 = bias[col], b1 = bias[col + 1];
#pragma unroll
            for (int h = 0; h < 2; h++) {
                const int r = r0 + h * 8;
                float v0 = c[i][j][2 * h + 0] + b0; if (v0 < 0.0f) v0 = 0.0f;
                float v1 = c[i][j][2 * h + 1] + b1; if (v1 < 0.0f) v1 = 0.0f;
                __half2 p;
                p.x = __float2half_rn(v0); p.y = __float2half_rn(v1);
                *(__half2*)(y + (size_t)r * COUT + col) = p;
            }
        }
    }
}

// ============================ conv2/3/4: implicit GEMM (sync staging, 2 CTAs/SM) ============================
template <int CIN, int COUT, int HIN, int WIN>
__global__ void __launch_bounds__(256, 2)
convmm_k(const h16* __restrict__ x, const h16* __restrict__ wt,
         const float* __restrict__ bias, h16* __restrict__ y) {
    constexpr int HOUT = HIN / 2, WOUT = WIN / 2;
    constexpr int CPT = CIN / 64;
    constexpr int NCH = 9 * CPT;
    constexpr int NFRAG = 8;

    extern __shared__ char sb[];
    const uint32_t sb32 = smem_u32(sb);
    const uint32_t oA = 0, oB = ATILE_B;

    const int tid = threadIdx.x, lane = tid & 31, wid = tid >> 5;
    const int warpM = wid >> 1, warpN = wid & 1;
    const int tile0 = blockIdx.x * 128;
    const int cob = blockIdx.y * 128;

    // staging coords: 4 slots per thread; row = (tid>>3)+32*r4, c16 = tid&7
    const int c16 = tid & 7;
    int baseoff[4]; bool xe[4], ye[4];
#pragma unroll
    for (int r4 = 0; r4 < 4; r4++) {
        const int row = (tid >> 3) + 32 * r4;
        const int s = tile0 + row;
        const int n = s / (HOUT * WOUT);
        const int rem = s - n * (HOUT * WOUT);
        const int y2 = rem / WOUT;
        const int x2 = rem - y2 * WOUT;
        baseoff[r4] = ((n * HIN + 2 * y2) * WIN + 2 * x2) * CIN;
        xe[r4] = (2 * x2 + 2 >= WIN);
        ye[r4] = (2 * y2 + 2 >= HIN);
    }

    float c[2][NFRAG][4];
#pragma unroll
    for (int i = 0; i < 2; i++)
#pragma unroll
        for (int j = 0; j < NFRAG; j++)
#pragma unroll
            for (int q = 0; q < 4; q++) c[i][j][q] = 0.0f;

    for (int ch = 0; ch < NCH; ch++) {
        const int t = ch / CPT;
        const int cb = (ch - t * CPT) * 64;
        const int ky = t / 3, kx = t - ky * 3;
        __syncthreads();   // protect smem from previous chunk's readers
#pragma unroll
        for (int r4 = 0; r4 < 4; r4++) {
            const int row = (tid >> 3) + 32 * r4;
            const uint32_t soff = (row * PITCH + c16 * 8) * 2;
            const bool valid = !((kx == 2 && xe[r4]) || (ky == 2 && ye[r4]));
            const size_t src = (size_t)baseoff[r4] + (ky * WIN + kx) * CIN + cb + c16 * 8;
            uint4 v = make_uint4(0, 0, 0, 0);
            if (valid) v = *(const uint4*)(x + src);
            *(uint4*)(sb + oA + soff) = v;
            const size_t wsrc = ((size_t)t * COUT + cob + row) * CIN + cb + c16 * 8;
            *(uint4*)(sb + oB + soff) = *(const uint4*)(wt + wsrc);
        }
        __syncthreads();
        chunk_mma<NFRAG>(sb32 + oA, sb32 + oB, lane, warpM, warpN, c);
    }

    epilogue<NFRAG, COUT>(c, bias, tile0, cob, lane, warpM, warpN, y);
}

// ============================ conv1: implicit GEMM, K=27 (padded 64) ============================
__global__ void __launch_bounds__(256, 2)
conv1mm_k(const float* __restrict__ images,
          const h16* __restrict__ wh,
          const float* __restrict__ bias,
          h16* __restrict__ y) {
    constexpr int HOUT = 112, WOUT = 112, HIN = 224, WIN = 224;
    constexpr int NFRAG = 4;   // 64 couts: warp tile 32x32

    extern __shared__ char sb[];
    const uint32_t sb32 = smem_u32(sb);
    const uint32_t oA = 0, oB = ATILE_B;

    const int tid = threadIdx.x, lane = tid & 31, wid = tid >> 5;
    const int warpM = wid >> 1, warpN = wid & 1;
    const int tile0 = blockIdx.x * 128;

    // A staging: thread owns k = tid&63, rows (tid>>6)+4i
    {
        const int k = tid & 63;
        const int r0 = tid >> 6;
        int ci = 0, ky = 0, kx = 0;
        const bool kvalid = (k < 27);
        if (kvalid) { ci = k / 9; int r = k - ci * 9; ky = r / 3; kx = r - ky * 3; }
        for (int i = 0; i < 32; i++) {
            const int row = r0 + 4 * i;
            h16 h = __float2half_rn(0.0f);
            if (kvalid) {
                const int s = tile0 + row;
                const int n = s / (HOUT * WOUT);
                const int rem = s - n * (HOUT * WOUT);
                const int y2 = rem / WOUT;
                const int x2 = rem - y2 * WOUT;
                const int iy = 2 * y2 + ky, ix = 2 * x2 + kx;
                if (iy < HIN && ix < WIN)
                    h = __float2half_rn(images[((size_t)(n * 3 + ci) * HIN + iy) * WIN + ix]);
            }
            *(h16*)(sb + oA + (row * PITCH + k) * 2) = h;
        }
    }
    // B staging: 64 rows x 8 c16
    for (int idx = tid; idx < 512; idx += 256) {
        const int row = idx >> 3, c16 = idx & 7;
        const uint32_t soff = (row * PITCH + c16 * 8) * 2;
        *(uint4*)(sb + oB + soff) = *(const uint4*)(wh + row * 64 + c16 * 8);
    }
    __syncthreads();

    float c[2][NFRAG][4];
#pragma unroll
    for (int i = 0; i < 2; i++)
#pragma unroll
        for (int j = 0; j < NFRAG; j++)
#pragma unroll
            for (int q = 0; q < 4; q++) c[i][j][q] = 0.0f;

    chunk_mma<NFRAG>(sb32 + oA, sb32 + oB, lane, warpM, warpN, c);

    epilogue<NFRAG, 64>(c, bias, tile0, 0, lane, warpM, warpN, y);
}

// ============================ misc kernels ============================
__global__ void embed_mean_k(const int* __restrict__ seq, const int* __restrict__ len,
                             const float* __restrict__ emb, float* __restrict__ mean) {
    const int b = blockIdx.x;
    const int L = len[b];
    __shared__ int s_idx[128];
    for (int i = threadIdx.x; i < 128; i += blockDim.x) s_idx[i] = seq[b * 128 + i];
    __syncthreads();
    const float inv = 1.0f / (float)L;
    for (int d = threadIdx.x; d < 512; d += blockDim.x) {
        float acc = 0.0f;
        for (int s = 0; s < L; s++) acc += emb[(size_t)s_idx[s] * 512 + d];
        mean[b * 512 + d] = acc * inv;
    }
}

__global__ void linear_k(const float* __restrict__ X, const float* __restrict__ W,
                         const float* __restrict__ bias, float* __restrict__ Y,
                         int K, int N, int relu) {
    const int j = blockIdx.x * blockDim.x + threadIdx.x;
    const int b = blockIdx.y;
    if (j >= N) return;
    const float* x = X + (size_t)b * K;
    float acc = bias[j];
    for (int k = 0; k < K; k++) acc = fmaf(x[k], W[(size_t)k * N + j], acc);
    if (relu && acc < 0.0f) acc = 0.0f;
    Y[(size_t)b * N + j] = acc;
}

// pool over 196 spatial (NHWC fp16), thread per (n,c)
__global__ void pool2_k(const h16* __restrict__ x, float* __restrict__ y) {
    const int idx = blockIdx.x * 256 + threadIdx.x;   // 64*512
    const int n = idx >> 9, c = idx & 511;
    const h16* p = x + (size_t)n * 196 * 512 + c;
    float s = 0.0f;
    for (int i = 0; i < 196; i++) s += __half2float(p[(size_t)i * 512]);
    y[idx] = s * (1.0f / 196.0f);
}

__global__ void concat_k(const float* __restrict__ img, const float* __restrict__ sent,
                         float* __restrict__ feats) {
    const int i = blockIdx.x * blockDim.x + threadIdx.x;
    const int b = i >> 10, j = i & 1023;
    feats[i] = (j < 512) ? img[b * 512 + j] : sent[b * 512 + (j - 512)];
}

// ============================ launch ============================
extern "C" void kernel_launch(void* const* d_in, const int* in_sizes, int n_in,
                              void* d_out, int out_size) {
    const float* images = (const float*)d_in[0];
    const int*   seq    = (const int*)d_in[1];
    const int*   len    = (const int*)d_in[2];
    const float* emb    = (const float*)d_in[4];
    const float* cw1 = (const float*)d_in[5],  *cb1 = (const float*)d_in[6];
    const float* cw2 = (const float*)d_in[7],  *cb2 = (const float*)d_in[8];
    const float* cw3 = (const float*)d_in[9],  *cb3 = (const float*)d_in[10];
    const float* cw4 = (const float*)d_in[11], *cb4 = (const float*)d_in[12];
    const float* rnn_w = (const float*)d_in[13], *rnn_b = (const float*)d_in[14];
    const float* fc1_w = (const float*)d_in[15], *fc1_b = (const float*)d_in[16];
    const float* fc2_w = (const float*)d_in[17], *fc2_b = (const float*)d_in[18];
    const float* clf_w = (const float*)d_in[19], *clf_b = (const float*)d_in[20];
    float* out = (float*)d_out;

    h16 *x1, *x2, *x3, *x4, *w1, *w2, *w3, *w4;
    float *mean, *sent, *img, *feats, *h1, *h2;
    cudaGetSymbolAddress((void**)&x1, g_x1); cudaGetSymbolAddress((void**)&x2, g_x2);
    cudaGetSymbolAddress((void**)&x3, g_x3); cudaGetSymbolAddress((void**)&x4, g_x4);
    cudaGetSymbolAddress((void**)&w1, g_w1); cudaGetSymbolAddress((void**)&w2, g_w2);
    cudaGetSymbolAddress((void**)&w3, g_w3); cudaGetSymbolAddress((void**)&w4, g_w4);
    cudaGetSymbolAddress((void**)&mean, g_mean); cudaGetSymbolAddress((void**)&sent, g_sent);
    cudaGetSymbolAddress((void**)&img, g_img);   cudaGetSymbolAddress((void**)&feats, g_feats);
    cudaGetSymbolAddress((void**)&h1, g_h1);     cudaGetSymbolAddress((void**)&h2, g_h2);

    const int smem2 = 2 * ATILE_B;   // 36864 -> 2 CTAs/SM
    cudaFuncSetAttribute(conv1mm_k, cudaFuncAttributeMaxDynamicSharedMemorySize, smem2);
    cudaFuncSetAttribute(convmm_k<64, 128, 112, 112>, cudaFuncAttributeMaxDynamicSharedMemorySize, smem2);
    cudaFuncSetAttribute(convmm_k<128, 256, 56, 56>,  cudaFuncAttributeMaxDynamicSharedMemorySize, smem2);
    cudaFuncSetAttribute(convmm_k<256, 512, 28, 28>,  cudaFuncAttributeMaxDynamicSharedMemorySize, smem2);

    // weight prep (launches 1-4)
    wprep1_k<<<16, 256>>>(cw1, w1);
    wprepT_k<<<(128 * 64 * 9 + 255) / 256, 256>>>(cw2, w2, 128, 64);
    wprepT_k<<<(256 * 128 * 9 + 255) / 256, 256>>>(cw3, w3, 256, 128);
    wprepT_k<<<(512 * 256 * 9 + 255) / 256, 256>>>(cw4, w4, 512, 256);

    // vision branch (launches 5-9; conv2 is launch #6 for ncu -s 5)
    conv1mm_k<<<6272, 256, smem2>>>(images, w1, cb1, x1);
    convmm_k<64, 128, 112, 112><<<dim3(1568, 1), 256, smem2>>>(x1, w2, cb2, x2);
    convmm_k<128, 256, 56, 56><<<dim3(392, 2), 256, smem2>>>(x2, w3, cb3, x3);
    convmm_k<256, 512, 28, 28><<<dim3(98, 4), 256, smem2>>>(x3, w4, cb4, x4);
    pool2_k<<<128, 256>>>(x4, img);

    // text branch
    embed_mean_k<<<64, 512>>>(seq, len, emb, mean);
    linear_k<<<dim3(2, 64), 256>>>(mean, rnn_w, rnn_b, sent, 512, 512, 0);

    // head
    concat_k<<<(64 * 1024) / 256, 256>>>(img, sent, feats);
    linear_k<<<dim3(2, 64), 256>>>(feats, fc1_w, fc1_b, h1, 1024, 512, 1);
    linear_k<<<dim3(2, 64), 256>>>(h1, fc2_w, fc2_b, h2, 512, 512, 1);
    linear_k<<<dim3(4, 64), 256>>>(h2, clf_w, clf_b, out, 512, 1000, 0);
}

// round 11
// speedup vs baseline: 2.2783x; 1.2099x over previous
#include <cuda_runtime.h>
#include <cuda_fp16.h>
#include <cstdint>
#include <cstddef>

typedef __half h16;

// ============================ helpers ============================
__device__ __forceinline__ uint32_t smem_u32(const void* p) {
    uint32_t a;
    asm("{ .reg .u64 t; cvta.to.shared.u64 t, %1; cvt.u32.u64 %0, t; }" : "=r"(a) : "l"(p));
    return a;
}
__device__ __forceinline__ void ldsm4(uint32_t& r0, uint32_t& r1, uint32_t& r2, uint32_t& r3,
                                      uint32_t addr) {
    asm volatile("ldmatrix.sync.aligned.m8n8.x4.shared.b16 {%0,%1,%2,%3}, [%4];"
                 : "=r"(r0), "=r"(r1), "=r"(r2), "=r"(r3) : "r"(addr));
}
__device__ __forceinline__ void mma16816(float c[4], const uint32_t a[4], const uint32_t b[2]) {
    asm volatile(
        "mma.sync.aligned.m16n8k16.row.col.f32.f16.f16.f32 "
        "{%0,%1,%2,%3}, {%4,%5,%6,%7}, {%8,%9}, {%0,%1,%2,%3};"
        : "+f"(c[0]), "+f"(c[1]), "+f"(c[2]), "+f"(c[3])
        : "r"(a[0]), "r"(a[1]), "r"(a[2]), "r"(a[3]), "r"(b[0]), "r"(b[1]));
}

// smem tile pitch: 72 h16 (144 B) -> row stride 36 words -> ldmatrix conflict-free
static constexpr int PITCH = 72;
static constexpr int ATILE_B = 128 * PITCH * 2;   // 18432 bytes per 128x64 tile

// ============================ scratch ============================
__device__ h16 g_x1[(size_t)64 * 112 * 112 * 64];
__device__ h16 g_x2[(size_t)64 * 56 * 56 * 128];
__device__ h16 g_x3[(size_t)64 * 28 * 28 * 256];
__device__ h16 g_x4[(size_t)64 * 14 * 14 * 512];
__device__ h16 g_w1[64 * 64];               // conv1 padded [co][64]
__device__ h16 g_w2[9 * 128 * 64];          // [t][co][ci]
__device__ h16 g_w3[9 * 256 * 128];
__device__ h16 g_w4[9 * 512 * 256];
__device__ float g_mean[64 * 512];
__device__ float g_sent[64 * 512];
__device__ float g_img[64 * 512];
__device__ float g_h1[64 * 512];
__device__ float g_h2[64 * 512];

// ============================ merged weight prep ============================
// w1: 64*64=4096 | w2: 9*128*64=73728 | w3: 9*256*128=294912 | w4: 9*512*256=1179648
__global__ void wprep_all_k(const float* __restrict__ cw1, const float* __restrict__ cw2,
                            const float* __restrict__ cw3, const float* __restrict__ cw4,
                            h16* __restrict__ w1, h16* __restrict__ w2,
                            h16* __restrict__ w3, h16* __restrict__ w4) {
    int idx = blockIdx.x * 256 + threadIdx.x;
    if (idx < 4096) {
        int co = idx >> 6, k = idx & 63;
        w1[idx] = __float2half_rn((k < 27) ? cw1[co * 27 + k] : 0.0f);
        return;
    }
    idx -= 4096;
    const float* src; h16* dst; int COUT, CIN;
    if (idx < 73728)        { src = cw2; dst = w2; COUT = 128; CIN = 64; }
    else if (idx < 73728 + 294912) { idx -= 73728; src = cw3; dst = w3; COUT = 256; CIN = 128; }
    else                    { idx -= 73728 + 294912; if (idx >= 1179648) return;
                              src = cw4; dst = w4; COUT = 512; CIN = 256; }
    int co = idx / (CIN * 9);
    int rem = idx - co * (CIN * 9);
    int ci = rem / 9, t = rem - ci * 9;
    dst[(t * COUT + co) * CIN + ci] = __float2half_rn(src[idx]);
}

// ============================ warp-level GEMM core ============================
template <int NFRAG>
__device__ __forceinline__ void chunk_mma(uint32_t sbA, uint32_t sbB,
                                          int lane, int warpM, int warpN,
                                          float (&c)[2][NFRAG][4]) {
    const int arow = warpM * 32 + (lane & 15);
    const int akoff = (lane >> 4) * 8;
    const int brow = warpN * (NFRAG * 8) + (lane & 7) + ((lane >> 3) & 1) * 8;
    const int bkoff = (lane >> 4) * 8;
#pragma unroll
    for (int ks = 0; ks < 4; ks++) {
        const int k0 = ks * 16;
        uint32_t ah[2][4];
#pragma unroll
        for (int i = 0; i < 2; i++) {
            const uint32_t aoff = (((arow + i * 16) * PITCH) + k0 + akoff) * 2;
            ldsm4(ah[i][0], ah[i][1], ah[i][2], ah[i][3], sbA + aoff);
        }
        uint32_t bh[NFRAG][2];
#pragma unroll
        for (int j2 = 0; j2 < NFRAG / 2; j2++) {
            const uint32_t boff = (((brow + j2 * 16) * PITCH) + k0 + bkoff) * 2;
            uint32_t r0, r1, r2, r3;
            ldsm4(r0, r1, r2, r3, sbB + boff);
            bh[2 * j2][0] = r0; bh[2 * j2][1] = r2;
            bh[2 * j2 + 1][0] = r1; bh[2 * j2 + 1][1] = r3;
        }
#pragma unroll
        for (int i = 0; i < 2; i++)
#pragma unroll
            for (int j = 0; j < NFRAG; j++)
                mma16816(c[i][j], ah[i], bh[j]);
    }
}

// epilogue: bias + relu + cvt -> NHWC fp16
template <int NFRAG, int COUT>
__device__ __forceinline__ void epilogue(float (&c)[2][NFRAG][4], const float* __restrict__ bias,
                                         int tile0, int cob, int lane, int warpM, int warpN,
                                         h16* __restrict__ y) {
#pragma unroll
    for (int i = 0; i < 2; i++) {
        const int r0 = tile0 + warpM * 32 + i * 16 + (lane >> 2);
#pragma unroll
        for (int j = 0; j < NFRAG; j++) {
            const int col = cob + warpN * (NFRAG * 8) + j * 8 + (lane & 3) * 2;
            const float b0 = bias[col], b1 = bias[col + 1];
#pragma unroll
            for (int h = 0; h < 2; h++) {
                const int r = r0 + h * 8;
                float v0 = c[i][j][2 * h + 0] + b0; if (v0 < 0.0f) v0 = 0.0f;
                float v1 = c[i][j][2 * h + 1] + b1; if (v1 < 0.0f) v1 = 0.0f;
                __half2 p;
                p.x = __float2half_rn(v0); p.y = __float2half_rn(v1);
                *(__half2*)(y + (size_t)r * COUT + col) = p;
            }
        }
    }
}

// ============================ conv2/3/4: implicit GEMM ============================
// M tile 128 spatial, N tile = NTILE couts (128 or 64), K chunk 64, sync staging
template <int CIN, int COUT, int HIN, int WIN, int NTILE>
__global__ void __launch_bounds__(256, 2)
convmm_k(const h16* __restrict__ x, const h16* __restrict__ wt,
         const float* __restrict__ bias, h16* __restrict__ y) {
    constexpr int HOUT = HIN / 2, WOUT = WIN / 2;
    constexpr int CPT = CIN / 64;
    constexpr int NCH = 9 * CPT;
    constexpr int NFRAG = NTILE / 16;
    constexpr int BSLOTS = NTILE / 32;

    extern __shared__ char sb[];
    const uint32_t sb32 = smem_u32(sb);
    const uint32_t oA = 0, oB = ATILE_B;

    const int tid = threadIdx.x, lane = tid & 31, wid = tid >> 5;
    const int warpM = wid >> 1, warpN = wid & 1;
    const int tile0 = blockIdx.x * 128;
    const int cob = blockIdx.y * NTILE;

    const int c16 = tid & 7;
    int baseoff[4]; bool xe[4], ye[4];
#pragma unroll
    for (int r4 = 0; r4 < 4; r4++) {
        const int row = (tid >> 3) + 32 * r4;
        const int s = tile0 + row;
        const int n = s / (HOUT * WOUT);
        const int rem = s - n * (HOUT * WOUT);
        const int y2 = rem / WOUT;
        const int x2 = rem - y2 * WOUT;
        baseoff[r4] = ((n * HIN + 2 * y2) * WIN + 2 * x2) * CIN;
        xe[r4] = (2 * x2 + 2 >= WIN);
        ye[r4] = (2 * y2 + 2 >= HIN);
    }

    float c[2][NFRAG][4];
#pragma unroll
    for (int i = 0; i < 2; i++)
#pragma unroll
        for (int j = 0; j < NFRAG; j++)
#pragma unroll
            for (int q = 0; q < 4; q++) c[i][j][q] = 0.0f;

    for (int ch = 0; ch < NCH; ch++) {
        const int t = ch / CPT;
        const int cb = (ch - t * CPT) * 64;
        const int ky = t / 3, kx = t - ky * 3;
        __syncthreads();
#pragma unroll
        for (int r4 = 0; r4 < 4; r4++) {
            const int row = (tid >> 3) + 32 * r4;
            const uint32_t soff = (row * PITCH + c16 * 8) * 2;
            const bool valid = !((kx == 2 && xe[r4]) || (ky == 2 && ye[r4]));
            const size_t src = (size_t)baseoff[r4] + (ky * WIN + kx) * CIN + cb + c16 * 8;
            uint4 v = make_uint4(0, 0, 0, 0);
            if (valid) v = *(const uint4*)(x + src);
            *(uint4*)(sb + oA + soff) = v;
            if (r4 < BSLOTS) {
                const size_t wsrc = ((size_t)t * COUT + cob + row) * CIN + cb + c16 * 8;
                *(uint4*)(sb + oB + soff) = *(const uint4*)(wt + wsrc);
            }
        }
        __syncthreads();
        chunk_mma<NFRAG>(sb32 + oA, sb32 + oB, lane, warpM, warpN, c);
    }

    epilogue<NFRAG, COUT>(c, bias, tile0, cob, lane, warpM, warpN, y);
}

// ============================ conv1: implicit GEMM, K=27 (padded 64) ============================
__global__ void __launch_bounds__(256, 2)
conv1mm_k(const float* __restrict__ images,
          const h16* __restrict__ wh,
          const float* __restrict__ bias,
          h16* __restrict__ y) {
    constexpr int HOUT = 112, WOUT = 112, HIN = 224, WIN = 224;
    constexpr int NFRAG = 4;

    extern __shared__ char sb[];
    const uint32_t sb32 = smem_u32(sb);
    const uint32_t oA = 0, oB = ATILE_B;

    const int tid = threadIdx.x, lane = tid & 31, wid = tid >> 5;
    const int warpM = wid >> 1, warpN = wid & 1;
    const int tile0 = blockIdx.x * 128;

    // zero the whole A tile (covers pad region k=27..63)
    for (int i = tid; i < ATILE_B / 16; i += 256)
        ((uint4*)sb)[i] = make_uint4(0, 0, 0, 0);
    __syncthreads();

    // A staging: lanes span ROWS (coalesced); warps 0-3 handle k 0..13, warps 4-7 k 14..26,
    // each warp owns row group (wid&3)*32 + lane.
    {
        const int row = (wid & 3) * 32 + lane;
        const int s = tile0 + row;
        const int n = s / (HOUT * WOUT);
        const int rem = s - n * (HOUT * WOUT);
        const int y2 = rem / WOUT;
        const int x2 = rem - y2 * WOUT;
        const int k0 = (wid < 4) ? 0 : 14;
        const int k1 = (wid < 4) ? 14 : 27;
        for (int k = k0; k < k1; k++) {
            const int ci = k / 9;
            const int r = k - ci * 9;
            const int ky = r / 3, kx = r - ky * 3;
            const int iy = 2 * y2 + ky, ix = 2 * x2 + kx;
            h16 h = __float2half_rn(0.0f);
            if (iy < HIN && ix < WIN)
                h = __float2half_rn(images[((size_t)(n * 3 + ci) * HIN + iy) * WIN + ix]);
            *(h16*)(sb + oA + (row * PITCH + k) * 2) = h;
        }
    }
    // B staging: 64 rows x 8 c16
    for (int idx = tid; idx < 512; idx += 256) {
        const int row = idx >> 3, c16 = idx & 7;
        const uint32_t soff = (row * PITCH + c16 * 8) * 2;
        *(uint4*)(sb + oB + soff) = *(const uint4*)(wh + row * 64 + c16 * 8);
    }
    __syncthreads();

    float c[2][NFRAG][4];
#pragma unroll
    for (int i = 0; i < 2; i++)
#pragma unroll
        for (int j = 0; j < NFRAG; j++)
#pragma unroll
            for (int q = 0; q < 4; q++) c[i][j][q] = 0.0f;

    chunk_mma<NFRAG>(sb32 + oA, sb32 + oB, lane, warpM, warpN, c);

    epilogue<NFRAG, 64>(c, bias, tile0, 0, lane, warpM, warpN, y);
}

// ============================ misc kernels ============================
__global__ void embed_mean_k(const int* __restrict__ seq, const int* __restrict__ len,
                             const float* __restrict__ emb, float* __restrict__ mean) {
    const int b = blockIdx.x;
    const int L = len[b];
    __shared__ int s_idx[128];
    for (int i = threadIdx.x; i < 128; i += blockDim.x) s_idx[i] = seq[b * 128 + i];
    __syncthreads();
    const float inv = 1.0f / (float)L;
    for (int d = threadIdx.x; d < 512; d += blockDim.x) {
        float acc = 0.0f;
        for (int s = 0; s < L; s++) acc += emb[(size_t)s_idx[s] * 512 + d];
        mean[b * 512 + d] = acc * inv;
    }
}

__global__ void linear_k(const float* __restrict__ X, const float* __restrict__ W,
                         const float* __restrict__ bias, float* __restrict__ Y,
                         int K, int N, int relu) {
    const int j = blockIdx.x * blockDim.x + threadIdx.x;
    const int b = blockIdx.y;
    if (j >= N) return;
    const float* x = X + (size_t)b * K;
    float acc = bias[j];
    for (int k = 0; k < K; k++) acc = fmaf(x[k], W[(size_t)k * N + j], acc);
    if (relu && acc < 0.0f) acc = 0.0f;
    Y[(size_t)b * N + j] = acc;
}

// fused concat+fc1: Y[b,j] = relu( sum_k img[b,k]W[k,j] + sum_k sent[b,k]W[512+k,j] + b[j] )
__global__ void fc1_k(const float* __restrict__ img, const float* __restrict__ sent,
                      const float* __restrict__ W, const float* __restrict__ bias,
                      float* __restrict__ Y) {
    const int j = blockIdx.x * blockDim.x + threadIdx.x;   // 0..511
    const int b = blockIdx.y;
    const float* x1 = img + (size_t)b * 512;
    const float* x2 = sent + (size_t)b * 512;
    float acc = bias[j];
    for (int k = 0; k < 512; k++) acc = fmaf(x1[k], W[(size_t)k * 512 + j], acc);
    for (int k = 0; k < 512; k++) acc = fmaf(x2[k], W[(size_t)(512 + k) * 512 + j], acc);
    Y[(size_t)b * 512 + j] = acc > 0.0f ? acc : 0.0f;
}

// pool over 196 spatial (NHWC fp16), thread per (n,c)
__global__ void pool2_k(const h16* __restrict__ x, float* __restrict__ y) {
    const int idx = blockIdx.x * 256 + threadIdx.x;   // 64*512
    const int n = idx >> 9, c = idx & 511;
    const h16* p = x + (size_t)n * 196 * 512 + c;
    float s = 0.0f;
    for (int i = 0; i < 196; i++) s += __half2float(p[(size_t)i * 512]);
    y[idx] = s * (1.0f / 196.0f);
}

// ============================ launch ============================
extern "C" void kernel_launch(void* const* d_in, const int* in_sizes, int n_in,
                              void* d_out, int out_size) {
    const float* images = (const float*)d_in[0];
    const int*   seq    = (const int*)d_in[1];
    const int*   len    = (const int*)d_in[2];
    const float* emb    = (const float*)d_in[4];
    const float* cw1 = (const float*)d_in[5],  *cb1 = (const float*)d_in[6];
    const float* cw2 = (const float*)d_in[7],  *cb2 = (const float*)d_in[8];
    const float* cw3 = (const float*)d_in[9],  *cb3 = (const float*)d_in[10];
    const float* cw4 = (const float*)d_in[11], *cb4 = (const float*)d_in[12];
    const float* rnn_w = (const float*)d_in[13], *rnn_b = (const float*)d_in[14];
    const float* fc1_w = (const float*)d_in[15], *fc1_b = (const float*)d_in[16];
    const float* fc2_w = (const float*)d_in[17], *fc2_b = (const float*)d_in[18];
    const float* clf_w = (const float*)d_in[19], *clf_b = (const float*)d_in[20];
    float* out = (float*)d_out;

    h16 *x1, *x2, *x3, *x4, *w1, *w2, *w3, *w4;
    float *mean, *sent, *img, *h1, *h2;
    cudaGetSymbolAddress((void**)&x1, g_x1); cudaGetSymbolAddress((void**)&x2, g_x2);
    cudaGetSymbolAddress((void**)&x3, g_x3); cudaGetSymbolAddress((void**)&x4, g_x4);
    cudaGetSymbolAddress((void**)&w1, g_w1); cudaGetSymbolAddress((void**)&w2, g_w2);
    cudaGetSymbolAddress((void**)&w3, g_w3); cudaGetSymbolAddress((void**)&w4, g_w4);
    cudaGetSymbolAddress((void**)&mean, g_mean); cudaGetSymbolAddress((void**)&sent, g_sent);
    cudaGetSymbolAddress((void**)&img, g_img);
    cudaGetSymbolAddress((void**)&h1, g_h1);     cudaGetSymbolAddress((void**)&h2, g_h2);

    const int smemN128 = ATILE_B + 128 * PITCH * 2;   // 36864
    const int smemN64  = ATILE_B + 64 * PITCH * 2;    // 27648
    cudaFuncSetAttribute(conv1mm_k, cudaFuncAttributeMaxDynamicSharedMemorySize, smemN64);
    cudaFuncSetAttribute(convmm_k<64, 128, 112, 112, 128>, cudaFuncAttributeMaxDynamicSharedMemorySize, smemN128);
    cudaFuncSetAttribute(convmm_k<128, 256, 56, 56, 64>,   cudaFuncAttributeMaxDynamicSharedMemorySize, smemN64);
    cudaFuncSetAttribute(convmm_k<256, 512, 28, 28, 64>,   cudaFuncAttributeMaxDynamicSharedMemorySize, smemN64);

    // text branch (launches 1-2)
    embed_mean_k<<<64, 512>>>(seq, len, emb, mean);
    linear_k<<<dim3(2, 64), 256>>>(mean, rnn_w, rnn_b, sent, 512, 512, 0);

    // merged weight prep (launch 3): total 1552384 elems
    wprep_all_k<<<(4096 + 73728 + 294912 + 1179648 + 255) / 256, 256>>>(
        cw1, cw2, cw3, cw4, w1, w2, w3, w4);

    // vision branch (launches 4-8)
    conv1mm_k<<<6272, 256, smemN64>>>(images, w1, cb1, x1);
    convmm_k<64, 128, 112, 112, 128><<<dim3(1568, 1), 256, smemN128>>>(x1, w2, cb2, x2);
    convmm_k<128, 256, 56, 56, 64><<<dim3(392, 4), 256, smemN64>>>(x2, w3, cb3, x3);
    convmm_k<256, 512, 28, 28, 64><<<dim3(98, 8), 256, smemN64>>>(x3, w4, cb4, x4);
    pool2_k<<<128, 256>>>(x4, img);

    // head (launches 9-11)
    fc1_k<<<dim3(2, 64), 256>>>(img, sent, fc1_w, fc1_b, h1);
    linear_k<<<dim3(2, 64), 256>>>(h1, fc2_w, fc2_b, h2, 512, 512, 1);
    linear_k<<<dim3(4, 64), 256>>>(h2, clf_w, clf_b, out, 512, 1000, 0);
}

// round 12
// speedup vs baseline: 2.3269x; 1.0213x over previous
#include <cuda_runtime.h>
#include <cuda_fp16.h>
#include <cstdint>
#include <cstddef>

typedef __half h16;

// ============================ helpers ============================
__device__ __forceinline__ uint32_t smem_u32(const void* p) {
    uint32_t a;
    asm("{ .reg .u64 t; cvta.to.shared.u64 t, %1; cvt.u32.u64 %0, t; }" : "=r"(a) : "l"(p));
    return a;
}
__device__ __forceinline__ void ldsm4(uint32_t& r0, uint32_t& r1, uint32_t& r2, uint32_t& r3,
                                      uint32_t addr) {
    asm volatile("ldmatrix.sync.aligned.m8n8.x4.shared.b16 {%0,%1,%2,%3}, [%4];"
                 : "=r"(r0), "=r"(r1), "=r"(r2), "=r"(r3) : "r"(addr));
}
__device__ __forceinline__ void mma16816(float c[4], const uint32_t a[4], const uint32_t b[2]) {
    asm volatile(
        "mma.sync.aligned.m16n8k16.row.col.f32.f16.f16.f32 "
        "{%0,%1,%2,%3}, {%4,%5,%6,%7}, {%8,%9}, {%0,%1,%2,%3};"
        : "+f"(c[0]), "+f"(c[1]), "+f"(c[2]), "+f"(c[3])
        : "r"(a[0]), "r"(a[1]), "r"(a[2]), "r"(a[3]), "r"(b[0]), "r"(b[1]));
}

// smem tile pitch: 72 h16 (144 B) -> row stride 36 words -> ldmatrix conflict-free
static constexpr int PITCH = 72;
static constexpr int ATILE_B = 128 * PITCH * 2;   // 18432 bytes per 128x64 tile

// ============================ scratch ============================
__device__ h16 g_x1[(size_t)64 * 112 * 112 * 64];
__device__ h16 g_x2[(size_t)64 * 56 * 56 * 128];
__device__ h16 g_x3[(size_t)64 * 28 * 28 * 256];
__device__ h16 g_x4[(size_t)64 * 14 * 14 * 512];
__device__ h16 g_w1[64 * 32];               // conv1 padded [co][32]
__device__ h16 g_w2[9 * 128 * 64];          // [t][co][ci]
__device__ h16 g_w3[9 * 256 * 128];
__device__ h16 g_w4[9 * 512 * 256];
__device__ float g_mean[64 * 512];
__device__ float g_sent[64 * 512];
__device__ float g_img[64 * 512];
__device__ float g_h1[64 * 512];
__device__ float g_h2[64 * 512];

// ============================ merged weight prep ============================
// w1: 64*32=2048 | w2: 9*128*64=73728 | w3: 9*256*128=294912 | w4: 9*512*256=1179648
__global__ void wprep_all_k(const float* __restrict__ cw1, const float* __restrict__ cw2,
                            const float* __restrict__ cw3, const float* __restrict__ cw4,
                            h16* __restrict__ w1, h16* __restrict__ w2,
                            h16* __restrict__ w3, h16* __restrict__ w4) {
    int idx = blockIdx.x * 256 + threadIdx.x;
    if (idx < 2048) {
        int co = idx >> 5, k = idx & 31;
        w1[idx] = __float2half_rn((k < 27) ? cw1[co * 27 + k] : 0.0f);
        return;
    }
    idx -= 2048;
    const float* src; h16* dst; int COUT, CIN;
    if (idx < 73728)        { src = cw2; dst = w2; COUT = 128; CIN = 64; }
    else if (idx < 73728 + 294912) { idx -= 73728; src = cw3; dst = w3; COUT = 256; CIN = 128; }
    else                    { idx -= 73728 + 294912; if (idx >= 1179648) return;
                              src = cw4; dst = w4; COUT = 512; CIN = 256; }
    int co = idx / (CIN * 9);
    int rem = idx - co * (CIN * 9);
    int ci = rem / 9, t = rem - ci * 9;
    dst[(t * COUT + co) * CIN + ci] = __float2half_rn(src[idx]);
}

// ============================ warp-level GEMM core ============================
template <int NFRAG, int KSTEPS>
__device__ __forceinline__ void chunk_mma(uint32_t sbA, uint32_t sbB,
                                          int lane, int warpM, int warpN,
                                          float (&c)[2][NFRAG][4]) {
    const int arow = warpM * 32 + (lane & 15);
    const int akoff = (lane >> 4) * 8;
    const int brow = warpN * (NFRAG * 8) + (lane & 7) + ((lane >> 3) & 1) * 8;
    const int bkoff = (lane >> 4) * 8;
#pragma unroll
    for (int ks = 0; ks < KSTEPS; ks++) {
        const int k0 = ks * 16;
        uint32_t ah[2][4];
#pragma unroll
        for (int i = 0; i < 2; i++) {
            const uint32_t aoff = (((arow + i * 16) * PITCH) + k0 + akoff) * 2;
            ldsm4(ah[i][0], ah[i][1], ah[i][2], ah[i][3], sbA + aoff);
        }
        uint32_t bh[NFRAG][2];
#pragma unroll
        for (int j2 = 0; j2 < NFRAG / 2; j2++) {
            const uint32_t boff = (((brow + j2 * 16) * PITCH) + k0 + bkoff) * 2;
            uint32_t r0, r1, r2, r3;
            ldsm4(r0, r1, r2, r3, sbB + boff);
            bh[2 * j2][0] = r0; bh[2 * j2][1] = r2;
            bh[2 * j2 + 1][0] = r1; bh[2 * j2 + 1][1] = r3;
        }
#pragma unroll
        for (int i = 0; i < 2; i++)
#pragma unroll
            for (int j = 0; j < NFRAG; j++)
                mma16816(c[i][j], ah[i], bh[j]);
    }
}

// epilogue: bias + relu + cvt -> NHWC fp16
template <int NFRAG, int COUT>
__device__ __forceinline__ void epilogue(float (&c)[2][NFRAG][4], const float* __restrict__ bias,
                                         int tile0, int cob, int lane, int warpM, int warpN,
                                         h16* __restrict__ y) {
#pragma unroll
    for (int i = 0; i < 2; i++) {
        const int r0 = tile0 + warpM * 32 + i * 16 + (lane >> 2);
#pragma unroll
        for (int j = 0; j < NFRAG; j++) {
            const int col = cob + warpN * (NFRAG * 8) + j * 8 + (lane & 3) * 2;
            const float b0 = bias[col], b1 = bias[col + 1];
#pragma unroll
            for (int h = 0; h < 2; h++) {
                const int r = r0 + h * 8;
                float v0 = c[i][j][2 * h + 0] + b0; if (v0 < 0.0f) v0 = 0.0f;
                float v1 = c[i][j][2 * h + 1] + b1; if (v1 < 0.0f) v1 = 0.0f;
                __half2 p;
                p.x = __float2half_rn(v0); p.y = __float2half_rn(v1);
                *(__half2*)(y + (size_t)r * COUT + col) = p;
            }
        }
    }
}

// ============================ conv2/3/4: implicit GEMM ============================
template <int CIN, int COUT, int HIN, int WIN, int NTILE>
__global__ void __launch_bounds__(256, 2)
convmm_k(const h16* __restrict__ x, const h16* __restrict__ wt,
         const float* __restrict__ bias, h16* __restrict__ y) {
    constexpr int HOUT = HIN / 2, WOUT = WIN / 2;
    constexpr int CPT = CIN / 64;
    constexpr int NCH = 9 * CPT;
    constexpr int NFRAG = NTILE / 16;
    constexpr int BSLOTS = NTILE / 32;

    extern __shared__ char sb[];
    const uint32_t sb32 = smem_u32(sb);
    const uint32_t oA = 0, oB = ATILE_B;

    const int tid = threadIdx.x, lane = tid & 31, wid = tid >> 5;
    const int warpM = wid >> 1, warpN = wid & 1;
    const int tile0 = blockIdx.x * 128;
    const int cob = blockIdx.y * NTILE;

    const int c16 = tid & 7;
    int baseoff[4]; bool xe[4], ye[4];
#pragma unroll
    for (int r4 = 0; r4 < 4; r4++) {
        const int row = (tid >> 3) + 32 * r4;
        const int s = tile0 + row;
        const int n = s / (HOUT * WOUT);
        const int rem = s - n * (HOUT * WOUT);
        const int y2 = rem / WOUT;
        const int x2 = rem - y2 * WOUT;
        baseoff[r4] = ((n * HIN + 2 * y2) * WIN + 2 * x2) * CIN;
        xe[r4] = (2 * x2 + 2 >= WIN);
        ye[r4] = (2 * y2 + 2 >= HIN);
    }

    float c[2][NFRAG][4];
#pragma unroll
    for (int i = 0; i < 2; i++)
#pragma unroll
        for (int j = 0; j < NFRAG; j++)
#pragma unroll
            for (int q = 0; q < 4; q++) c[i][j][q] = 0.0f;

    for (int ch = 0; ch < NCH; ch++) {
        const int t = ch / CPT;
        const int cb = (ch - t * CPT) * 64;
        const int ky = t / 3, kx = t - ky * 3;
        __syncthreads();
#pragma unroll
        for (int r4 = 0; r4 < 4; r4++) {
            const int row = (tid >> 3) + 32 * r4;
            const uint32_t soff = (row * PITCH + c16 * 8) * 2;
            const bool valid = !((kx == 2 && xe[r4]) || (ky == 2 && ye[r4]));
            const size_t src = (size_t)baseoff[r4] + (ky * WIN + kx) * CIN + cb + c16 * 8;
            uint4 v = make_uint4(0, 0, 0, 0);
            if (valid) v = *(const uint4*)(x + src);
            *(uint4*)(sb + oA + soff) = v;
            if (r4 < BSLOTS) {
                const size_t wsrc = ((size_t)t * COUT + cob + row) * CIN + cb + c16 * 8;
                *(uint4*)(sb + oB + soff) = *(const uint4*)(wt + wsrc);
            }
        }
        __syncthreads();
        chunk_mma<NFRAG, 4>(sb32 + oA, sb32 + oB, lane, warpM, warpN, c);
    }

    epilogue<NFRAG, COUT>(c, bias, tile0, cob, lane, warpM, warpN, y);
}

// ============================ conv1: implicit GEMM, K=27 (padded 32) ============================
__global__ void __launch_bounds__(256, 2)
conv1mm_k(const float* __restrict__ images,
          const h16* __restrict__ wh,
          const float* __restrict__ bias,
          h16* __restrict__ y) {
    constexpr int HOUT = 112, WOUT = 112, HIN = 224, WIN = 224;
    constexpr int NFRAG = 4;

    extern __shared__ char sb[];
    const uint32_t sb32 = smem_u32(sb);
    const uint32_t oA = 0, oB = ATILE_B;

    const int tid = threadIdx.x, lane = tid & 31, wid = tid >> 5;
    const int warpM = wid >> 1, warpN = wid & 1;
    const int tile0 = blockIdx.x * 128;

    // A staging: thread owns (row, k-half). Register-accumulate 16 taps with
    // compile-time k->(ci,ky,kx), then 2x STS.128 (conflict-free: banks 4r..4r+3).
    {
        const int g = wid >> 2;                 // 0: k0..15, 1: k16..31
        const int row = ((wid & 3) << 5) + lane;
        const int s = tile0 + row;
        const int n = s / (HOUT * WOUT);
        const int rem = s - n * (HOUT * WOUT);
        const int y2 = rem / WOUT;
        const int x2 = rem - y2 * WOUT;
        const float* p0 = images + ((size_t)(n * 3) * HIN + 2 * y2) * WIN + 2 * x2;
        const bool xok = (x2 < 111);            // ix=2*x2+2 in range?
        const bool yok = (y2 < 111);            // iy=2*y2+2 in range?
        union { h16 h[16]; uint4 u[2]; } pk;
#pragma unroll
        for (int i = 0; i < 16; i++) pk.h[i] = __float2half_rn(0.0f);
        if (g == 0) {
#pragma unroll
            for (int kk = 0; kk < 16; kk++) {
                const int ci = kk / 9, r = kk - ci * 9, ky = r / 3, kx = r - ky * 3;
                const bool ok = (kx < 2 || xok) && (ky < 2 || yok);
                if (ok) pk.h[kk] = __float2half_rn(p0[(size_t)ci * (HIN * WIN) + ky * WIN + kx]);
            }
        } else {
#pragma unroll
            for (int kk = 0; kk < 11; kk++) {
                const int k = 16 + kk;
                const int ci = k / 9, r = k - ci * 9, ky = r / 3, kx = r - ky * 3;
                const bool ok = (kx < 2 || xok) && (ky < 2 || yok);
                if (ok) pk.h[kk] = __float2half_rn(p0[(size_t)ci * (HIN * WIN) + ky * WIN + kx]);
            }
        }
        char* dst = sb + oA + row * (PITCH * 2) + g * 32;
        *(uint4*)dst = pk.u[0];
        *(uint4*)(dst + 16) = pk.u[1];
    }
    // B staging: 64 couts x 32 k (w1 is [co][32])
    if (tid < 256) {
        const int r = tid >> 2, c16 = tid & 3;
        *(uint4*)(sb + oB + (r * PITCH + c16 * 8) * 2) = *(const uint4*)(wh + r * 32 + c16 * 8);
    }
    __syncthreads();

    float c[2][NFRAG][4];
#pragma unroll
    for (int i = 0; i < 2; i++)
#pragma unroll
        for (int j = 0; j < NFRAG; j++)
#pragma unroll
            for (int q = 0; q < 4; q++) c[i][j][q] = 0.0f;

    chunk_mma<NFRAG, 2>(sb32 + oA, sb32 + oB, lane, warpM, warpN, c);

    epilogue<NFRAG, 64>(c, bias, tile0, 0, lane, warpM, warpN, y);
}

// ============================ misc kernels ============================
__global__ void embed_mean_k(const int* __restrict__ seq, const int* __restrict__ len,
                             const float* __restrict__ emb, float* __restrict__ mean) {
    const int b = blockIdx.x;
    const int L = len[b];
    __shared__ int s_idx[128];
    if (threadIdx.x < 128) s_idx[threadIdx.x] = seq[b * 128 + threadIdx.x];
    __syncthreads();
    const int d4 = threadIdx.x;   // 0..127, 4 floats each
    float4 acc = make_float4(0.f, 0.f, 0.f, 0.f);
    for (int s = 0; s < L; s++) {
        float4 v = *(const float4*)(emb + (size_t)s_idx[s] * 512 + d4 * 4);
        acc.x += v.x; acc.y += v.y; acc.z += v.z; acc.w += v.w;
    }
    const float inv = 1.0f / (float)L;
    acc.x *= inv; acc.y *= inv; acc.z *= inv; acc.w *= inv;
    *(float4*)(mean + (size_t)b * 512 + d4 * 4) = acc;
}

__global__ void linear_k(const float* __restrict__ X, const float* __restrict__ W,
                         const float* __restrict__ bias, float* __restrict__ Y,
                         int K, int N, int relu) {
    const int j = blockIdx.x * blockDim.x + threadIdx.x;
    const int b = blockIdx.y;
    if (j >= N) return;
    const float* x = X + (size_t)b * K;
    float acc = bias[j];
    for (int k = 0; k < K; k++) acc = fmaf(x[k], W[(size_t)k * N + j], acc);
    if (relu && acc < 0.0f) acc = 0.0f;
    Y[(size_t)b * N + j] = acc;
}

// fused concat+fc1
__global__ void fc1_k(const float* __restrict__ img, const float* __restrict__ sent,
                      const float* __restrict__ W, const float* __restrict__ bias,
                      float* __restrict__ Y) {
    const int j = blockIdx.x * blockDim.x + threadIdx.x;   // 0..511
    const int b = blockIdx.y;
    const float* x1 = img + (size_t)b * 512;
    const float* x2 = sent + (size_t)b * 512;
    float acc = bias[j];
    for (int k = 0; k < 512; k++) acc = fmaf(x1[k], W[(size_t)k * 512 + j], acc);
    for (int k = 0; k < 512; k++) acc = fmaf(x2[k], W[(size_t)(512 + k) * 512 + j], acc);
    Y[(size_t)b * 512 + j] = acc > 0.0f ? acc : 0.0f;
}

// pool: one block per image; thread = (c8, iq); uint4 loads + shfl reduce over iq
__global__ void pool2_k(const h16* __restrict__ x, float* __restrict__ y) {
    const int n = blockIdx.x;
    const int tid = threadIdx.x;
    const int c8 = tid >> 2;     // 0..63
    const int iq = tid & 3;      // 0..3
    const h16* p = x + (size_t)n * 196 * 512 + c8 * 8;
    float s[8];
#pragma unroll
    for (int j = 0; j < 8; j++) s[j] = 0.0f;
    for (int i = iq; i < 196; i += 4) {
        uint4 v = *(const uint4*)(p + (size_t)i * 512);
        const h16* hv = (const h16*)&v;
#pragma unroll
        for (int j = 0; j < 8; j++) s[j] += __half2float(hv[j]);
    }
#pragma unroll
    for (int j = 0; j < 8; j++) {
        s[j] += __shfl_down_sync(0xFFFFFFFFu, s[j], 1);
        s[j] += __shfl_down_sync(0xFFFFFFFFu, s[j], 2);
    }
    if (iq == 0) {
#pragma unroll
        for (int j = 0; j < 8; j++)
            y[(size_t)n * 512 + c8 * 8 + j] = s[j] * (1.0f / 196.0f);
    }
}

// ============================ launch ============================
extern "C" void kernel_launch(void* const* d_in, const int* in_sizes, int n_in,
                              void* d_out, int out_size) {
    const float* images = (const float*)d_in[0];
    const int*   seq    = (const int*)d_in[1];
    const int*   len    = (const int*)d_in[2];
    const float* emb    = (const float*)d_in[4];
    const float* cw1 = (const float*)d_in[5],  *cb1 = (const float*)d_in[6];
    const float* cw2 = (const float*)d_in[7],  *cb2 = (const float*)d_in[8];
    const float* cw3 = (const float*)d_in[9],  *cb3 = (const float*)d_in[10];
    const float* cw4 = (const float*)d_in[11], *cb4 = (const float*)d_in[12];
    const float* rnn_w = (const float*)d_in[13], *rnn_b = (const float*)d_in[14];
    const float* fc1_w = (const float*)d_in[15], *fc1_b = (const float*)d_in[16];
    const float* fc2_w = (const float*)d_in[17], *fc2_b = (const float*)d_in[18];
    const float* clf_w = (const float*)d_in[19], *clf_b = (const float*)d_in[20];
    float* out = (float*)d_out;

    h16 *x1, *x2, *x3, *x4, *w1, *w2, *w3, *w4;
    float *mean, *sent, *img, *h1, *h2;
    cudaGetSymbolAddress((void**)&x1, g_x1); cudaGetSymbolAddress((void**)&x2, g_x2);
    cudaGetSymbolAddress((void**)&x3, g_x3); cudaGetSymbolAddress((void**)&x4, g_x4);
    cudaGetSymbolAddress((void**)&w1, g_w1); cudaGetSymbolAddress((void**)&w2, g_w2);
    cudaGetSymbolAddress((void**)&w3, g_w3); cudaGetSymbolAddress((void**)&w4, g_w4);
    cudaGetSymbolAddress((void**)&mean, g_mean); cudaGetSymbolAddress((void**)&sent, g_sent);
    cudaGetSymbolAddress((void**)&img, g_img);
    cudaGetSymbolAddress((void**)&h1, g_h1);     cudaGetSymbolAddress((void**)&h2, g_h2);

    const int smemN128 = ATILE_B + 128 * PITCH * 2;   // 36864
    const int smemN64  = ATILE_B + 64 * PITCH * 2;    // 27648
    cudaFuncSetAttribute(conv1mm_k, cudaFuncAttributeMaxDynamicSharedMemorySize, smemN64);
    cudaFuncSetAttribute(convmm_k<64, 128, 112, 112, 128>, cudaFuncAttributeMaxDynamicSharedMemorySize, smemN128);
    cudaFuncSetAttribute(convmm_k<128, 256, 56, 56, 64>,   cudaFuncAttributeMaxDynamicSharedMemorySize, smemN64);
    cudaFuncSetAttribute(convmm_k<256, 512, 28, 28, 64>,   cudaFuncAttributeMaxDynamicSharedMemorySize, smemN64);

    // text branch
    embed_mean_k<<<64, 128>>>(seq, len, emb, mean);
    linear_k<<<dim3(2, 64), 256>>>(mean, rnn_w, rnn_b, sent, 512, 512, 0);

    // merged weight prep
    wprep_all_k<<<(2048 + 73728 + 294912 + 1179648 + 255) / 256, 256>>>(
        cw1, cw2, cw3, cw4, w1, w2, w3, w4);

    // vision branch
    conv1mm_k<<<6272, 256, smemN64>>>(images, w1, cb1, x1);
    convmm_k<64, 128, 112, 112, 128><<<dim3(1568, 1), 256, smemN128>>>(x1, w2, cb2, x2);
    convmm_k<128, 256, 56, 56, 64><<<dim3(392, 4), 256, smemN64>>>(x2, w3, cb3, x3);
    convmm_k<256, 512, 28, 28, 64><<<dim3(98, 8), 256, smemN64>>>(x3, w4, cb4, x4);
    pool2_k<<<64, 256>>>(x4, img);

    // head
    fc1_k<<<dim3(2, 64), 256>>>(img, sent, fc1_w, fc1_b, h1);
    linear_k<<<dim3(2, 64), 256>>>(h1, fc2_w, fc2_b, h2, 512, 512, 1);
    linear_k<<<dim3(4, 64), 256>>>(h2, clf_w, clf_b, out, 512, 1000, 0);
}

// round 13
// speedup vs baseline: 2.5300x; 1.0873x over previous
#include <cuda_runtime.h>
#include <cuda_fp16.h>
#include <cstdint>
#include <cstddef>

typedef __half h16;

// ============================ helpers ============================
__device__ __forceinline__ uint32_t smem_u32(const void* p) {
    uint32_t a;
    asm("{ .reg .u64 t; cvta.to.shared.u64 t, %1; cvt.u32.u64 %0, t; }" : "=r"(a) : "l"(p));
    return a;
}
__device__ __forceinline__ void ldsm4(uint32_t& r0, uint32_t& r1, uint32_t& r2, uint32_t& r3,
                                      uint32_t addr) {
    asm volatile("ldmatrix.sync.aligned.m8n8.x4.shared.b16 {%0,%1,%2,%3}, [%4];"
                 : "=r"(r0), "=r"(r1), "=r"(r2), "=r"(r3) : "r"(addr));
}
__device__ __forceinline__ void mma16816(float c[4], const uint32_t a[4], const uint32_t b[2]) {
    asm volatile(
        "mma.sync.aligned.m16n8k16.row.col.f32.f16.f16.f32 "
        "{%0,%1,%2,%3}, {%4,%5,%6,%7}, {%8,%9}, {%0,%1,%2,%3};"
        : "+f"(c[0]), "+f"(c[1]), "+f"(c[2]), "+f"(c[3])
        : "r"(a[0]), "r"(a[1]), "r"(a[2]), "r"(a[3]), "r"(b[0]), "r"(b[1]));
}
// 16B async copy, zero-fill when srcsize==0
__device__ __forceinline__ void cp16(uint32_t dst, const void* src, uint32_t srcsize) {
    asm volatile("cp.async.cg.shared.global [%0], [%1], 16, %2;"
                 :: "r"(dst), "l"(src), "r"(srcsize) : "memory");
}
#define CP_COMMIT() asm volatile("cp.async.commit_group;" ::: "memory")
#define CP_WAIT(n)  asm volatile("cp.async.wait_group %0;" :: "n"(n) : "memory")

// smem tile pitch: 72 h16 (144 B) -> row stride 36 words -> ldmatrix conflict-free
static constexpr int PITCH = 72;
static constexpr int ATILE_B = 128 * PITCH * 2;   // 18432 bytes per 128x64 tile

// ============================ scratch ============================
__device__ h16 g_x1[(size_t)64 * 112 * 112 * 64];
__device__ h16 g_x2[(size_t)64 * 56 * 56 * 128];
__device__ h16 g_x3[(size_t)64 * 28 * 28 * 256];
__device__ h16 g_x4[(size_t)64 * 14 * 14 * 512];
__device__ h16 g_w1[64 * 32];               // conv1 padded [co][32]
__device__ h16 g_w2[9 * 128 * 64];          // [t][co][ci]
__device__ h16 g_w3[9 * 256 * 128];
__device__ h16 g_w4[9 * 512 * 256];
__device__ float g_mean[64 * 512];
__device__ float g_sent[64 * 512];
__device__ float g_img[64 * 512];
__device__ float g_h1[64 * 512];
__device__ float g_h2[64 * 512];

// ============================ merged weight prep ============================
__global__ void wprep_all_k(const float* __restrict__ cw1, const float* __restrict__ cw2,
                            const float* __restrict__ cw3, const float* __restrict__ cw4,
                            h16* __restrict__ w1, h16* __restrict__ w2,
                            h16* __restrict__ w3, h16* __restrict__ w4) {
    int idx = blockIdx.x * 256 + threadIdx.x;
    if (idx < 2048) {
        int co = idx >> 5, k = idx & 31;
        w1[idx] = __float2half_rn((k < 27) ? cw1[co * 27 + k] : 0.0f);
        return;
    }
    idx -= 2048;
    const float* src; h16* dst; int COUT, CIN;
    if (idx < 73728)        { src = cw2; dst = w2; COUT = 128; CIN = 64; }
    else if (idx < 73728 + 294912) { idx -= 73728; src = cw3; dst = w3; COUT = 256; CIN = 128; }
    else                    { idx -= 73728 + 294912; if (idx >= 1179648) return;
                              src = cw4; dst = w4; COUT = 512; CIN = 256; }
    int co = idx / (CIN * 9);
    int rem = idx - co * (CIN * 9);
    int ci = rem / 9, t = rem - ci * 9;
    dst[(t * COUT + co) * CIN + ci] = __float2half_rn(src[idx]);
}

// ============================ warp-level GEMM core ============================
template <int NFRAG, int KSTEPS>
__device__ __forceinline__ void chunk_mma(uint32_t sbA, uint32_t sbB,
                                          int lane, int warpM, int warpN,
                                          float (&c)[2][NFRAG][4]) {
    const int arow = warpM * 32 + (lane & 15);
    const int akoff = (lane >> 4) * 8;
    const int brow = warpN * (NFRAG * 8) + (lane & 7) + ((lane >> 3) & 1) * 8;
    const int bkoff = (lane >> 4) * 8;
#pragma unroll
    for (int ks = 0; ks < KSTEPS; ks++) {
        const int k0 = ks * 16;
        uint32_t ah[2][4];
#pragma unroll
        for (int i = 0; i < 2; i++) {
            const uint32_t aoff = (((arow + i * 16) * PITCH) + k0 + akoff) * 2;
            ldsm4(ah[i][0], ah[i][1], ah[i][2], ah[i][3], sbA + aoff);
        }
        uint32_t bh[NFRAG][2];
#pragma unroll
        for (int j2 = 0; j2 < NFRAG / 2; j2++) {
            const uint32_t boff = (((brow + j2 * 16) * PITCH) + k0 + bkoff) * 2;
            uint32_t r0, r1, r2, r3;
            ldsm4(r0, r1, r2, r3, sbB + boff);
            bh[2 * j2][0] = r0; bh[2 * j2][1] = r2;
            bh[2 * j2 + 1][0] = r1; bh[2 * j2 + 1][1] = r3;
        }
#pragma unroll
        for (int i = 0; i < 2; i++)
#pragma unroll
            for (int j = 0; j < NFRAG; j++)
                mma16816(c[i][j], ah[i], bh[j]);
    }
}

// epilogue: bias + relu + cvt -> NHWC fp16
template <int NFRAG, int COUT>
__device__ __forceinline__ void epilogue(float (&c)[2][NFRAG][4], const float* __restrict__ bias,
                                         int tile0, int cob, int lane, int warpM, int warpN,
                                         h16* __restrict__ y) {
#pragma unroll
    for (int i = 0; i < 2; i++) {
        const int r0 = tile0 + warpM * 32 + i * 16 + (lane >> 2);
#pragma unroll
        for (int j = 0; j < NFRAG; j++) {
            const int col = cob + warpN * (NFRAG * 8) + j * 8 + (lane & 3) * 2;
            const float b0 = bias[col], b1 = bias[col + 1];
#pragma unroll
            for (int h = 0; h < 2; h++) {
                const int r = r0 + h * 8;
                float v0 = c[i][j][2 * h + 0] + b0; if (v0 < 0.0f) v0 = 0.0f;
                float v1 = c[i][j][2 * h + 1] + b1; if (v1 < 0.0f) v1 = 0.0f;
                __half2 p;
                p.x = __float2half_rn(v0); p.y = __float2half_rn(v1);
                *(__half2*)(y + (size_t)r * COUT + col) = p;
            }
        }
    }
}

// ============================ conv2/3/4: implicit GEMM, cp.async double-buffer, 2 CTAs/SM ============================
template <int CIN, int COUT, int HIN, int WIN, int NTILE>
__global__ void __launch_bounds__(256, 2)
convmm_k(const h16* __restrict__ x, const h16* __restrict__ wt,
         const float* __restrict__ bias, h16* __restrict__ y) {
    constexpr int HOUT = HIN / 2, WOUT = WIN / 2;
    constexpr int CPT = CIN / 64;
    constexpr int NCH = 9 * CPT;
    constexpr int NFRAG = NTILE / 16;
    constexpr int BSLOTS = NTILE / 32;
    constexpr int BUF_B = ATILE_B + NTILE * PITCH * 2;   // A tile + B tile

    extern __shared__ char sb[];
    const uint32_t sb32 = smem_u32(sb);

    const int tid = threadIdx.x, lane = tid & 31, wid = tid >> 5;
    const int warpM = wid >> 1, warpN = wid & 1;
    const int tile0 = blockIdx.x * 128;
    const int cob = blockIdx.y * NTILE;

    const int c16 = tid & 7;
    int baseoff[4]; bool xe[4], ye[4];
#pragma unroll
    for (int r4 = 0; r4 < 4; r4++) {
        const int row = (tid >> 3) + 32 * r4;
        const int s = tile0 + row;
        const int n = s / (HOUT * WOUT);
        const int rem = s - n * (HOUT * WOUT);
        const int y2 = rem / WOUT;
        const int x2 = rem - y2 * WOUT;
        baseoff[r4] = ((n * HIN + 2 * y2) * WIN + 2 * x2) * CIN;
        xe[r4] = (2 * x2 + 2 >= WIN);
        ye[r4] = (2 * y2 + 2 >= HIN);
    }

    // stage chunk ch into buffer ch&1 via cp.async (A + B tiles)
    auto stage = [&](int ch) {
        const int t = ch / CPT;
        const int cb = (ch - t * CPT) * 64;
        const int ky = t / 3, kx = t - ky * 3;
        const uint32_t base = sb32 + (ch & 1) * BUF_B;
#pragma unroll
        for (int r4 = 0; r4 < 4; r4++) {
            const int row = (tid >> 3) + 32 * r4;
            const uint32_t soff = (row * PITCH + c16 * 8) * 2;
            const bool valid = !((kx == 2 && xe[r4]) || (ky == 2 && ye[r4]));
            const size_t src = (size_t)baseoff[r4] + (ky * WIN + kx) * CIN + cb + c16 * 8;
            cp16(base + soff, x + src, valid ? 16u : 0u);
            if (r4 < BSLOTS) {
                const size_t wsrc = ((size_t)t * COUT + cob + row) * CIN + cb + c16 * 8;
                cp16(base + ATILE_B + soff, wt + wsrc, 16u);
            }
        }
        CP_COMMIT();
    };

    float c[2][NFRAG][4];
#pragma unroll
    for (int i = 0; i < 2; i++)
#pragma unroll
        for (int j = 0; j < NFRAG; j++)
#pragma unroll
            for (int q = 0; q < 4; q++) c[i][j][q] = 0.0f;

    stage(0);
    for (int ch = 0; ch < NCH; ch++) {
        if (ch + 1 < NCH) { stage(ch + 1); CP_WAIT(1); }
        else              { CP_WAIT(0); }
        __syncthreads();                               // chunk ch's data visible to all
        const uint32_t base = sb32 + (ch & 1) * BUF_B;
        chunk_mma<NFRAG, 4>(base, base + ATILE_B, lane, warpM, warpN, c);
        __syncthreads();                               // mma reads done before restage
    }

    epilogue<NFRAG, COUT>(c, bias, tile0, cob, lane, warpM, warpN, y);
}

// ============================ conv1: implicit GEMM, K=27 (padded 32), 4 CTAs/SM ============================
__global__ void __launch_bounds__(256, 4)
conv1mm_k(const float* __restrict__ images,
          const h16* __restrict__ wh,
          const float* __restrict__ bias,
          h16* __restrict__ y) {
    constexpr int HOUT = 112, WOUT = 112, HIN = 224, WIN = 224;
    constexpr int NFRAG = 4;

    extern __shared__ char sb[];
    const uint32_t sb32 = smem_u32(sb);
    const uint32_t oA = 0, oB = ATILE_B;

    const int tid = threadIdx.x, lane = tid & 31, wid = tid >> 5;
    const int warpM = wid >> 1, warpN = wid & 1;
    const int tile0 = blockIdx.x * 128;

    // A staging: thread owns (row, k-half). Register-accumulate 16 taps with
    // compile-time k->(ci,ky,kx), then 2x STS.128 (conflict-free).
    {
        const int g = wid >> 2;                 // 0: k0..15, 1: k16..31
        const int row = ((wid & 3) << 5) + lane;
        const int s = tile0 + row;
        const int n = s / (HOUT * WOUT);
        const int rem = s - n * (HOUT * WOUT);
        const int y2 = rem / WOUT;
        const int x2 = rem - y2 * WOUT;
        const float* p0 = images + ((size_t)(n * 3) * HIN + 2 * y2) * WIN + 2 * x2;
        const bool xok = (x2 < 111);
        const bool yok = (y2 < 111);
        union { h16 h[16]; uint4 u[2]; } pk;
#pragma unroll
        for (int i = 0; i < 16; i++) pk.h[i] = __float2half_rn(0.0f);
        if (g == 0) {
#pragma unroll
            for (int kk = 0; kk < 16; kk++) {
                const int ci = kk / 9, r = kk - ci * 9, ky = r / 3, kx = r - ky * 3;
                const bool ok = (kx < 2 || xok) && (ky < 2 || yok);
                if (ok) pk.h[kk] = __float2half_rn(p0[(size_t)ci * (HIN * WIN) + ky * WIN + kx]);
            }
        } else {
#pragma unroll
            for (int kk = 0; kk < 11; kk++) {
                const int k = 16 + kk;
                const int ci = k / 9, r = k - ci * 9, ky = r / 3, kx = r - ky * 3;
                const bool ok = (kx < 2 || xok) && (ky < 2 || yok);
                if (ok) pk.h[kk] = __float2half_rn(p0[(size_t)ci * (HIN * WIN) + ky * WIN + kx]);
            }
        }
        char* dst = sb + oA + row * (PITCH * 2) + g * 32;
        *(uint4*)dst = pk.u[0];
        *(uint4*)(dst + 16) = pk.u[1];
    }
    // B staging: 64 couts x 32 k (w1 is [co][32])
    if (tid < 256) {
        const int r = tid >> 2, c16 = tid & 3;
        *(uint4*)(sb + oB + (r * PITCH + c16 * 8) * 2) = *(const uint4*)(wh + r * 32 + c16 * 8);
    }
    __syncthreads();

    float c[2][NFRAG][4];
#pragma unroll
    for (int i = 0; i < 2; i++)
#pragma unroll
        for (int j = 0; j < NFRAG; j++)
#pragma unroll
            for (int q = 0; q < 4; q++) c[i][j][q] = 0.0f;

    chunk_mma<NFRAG, 2>(sb32 + oA, sb32 + oB, lane, warpM, warpN, c);

    epilogue<NFRAG, 64>(c, bias, tile0, 0, lane, warpM, warpN, y);
}

// ============================ misc kernels ============================
__global__ void embed_mean_k(const int* __restrict__ seq, const int* __restrict__ len,
                             const float* __restrict__ emb, float* __restrict__ mean) {
    const int b = blockIdx.x;
    const int L = len[b];
    __shared__ int s_idx[128];
    if (threadIdx.x < 128) s_idx[threadIdx.x] = seq[b * 128 + threadIdx.x];
    __syncthreads();
    const int d4 = threadIdx.x;
    float4 acc = make_float4(0.f, 0.f, 0.f, 0.f);
    for (int s = 0; s < L; s++) {
        float4 v = *(const float4*)(emb + (size_t)s_idx[s] * 512 + d4 * 4);
        acc.x += v.x; acc.y += v.y; acc.z += v.z; acc.w += v.w;
    }
    const float inv = 1.0f / (float)L;
    acc.x *= inv; acc.y *= inv; acc.z *= inv; acc.w *= inv;
    *(float4*)(mean + (size_t)b * 512 + d4 * 4) = acc;
}

__global__ void linear_k(const float* __restrict__ X, const float* __restrict__ W,
                         const float* __restrict__ bias, float* __restrict__ Y,
                         int K, int N, int relu) {
    const int j = blockIdx.x * blockDim.x + threadIdx.x;
    const int b = blockIdx.y;
    if (j >= N) return;
    const float* x = X + (size_t)b * K;
    float acc = bias[j];
    for (int k = 0; k < K; k++) acc = fmaf(x[k], W[(size_t)k * N + j], acc);
    if (relu && acc < 0.0f) acc = 0.0f;
    Y[(size_t)b * N + j] = acc;
}

// fused concat+fc1
__global__ void fc1_k(const float* __restrict__ img, const float* __restrict__ sent,
                      const float* __restrict__ W, const float* __restrict__ bias,
                      float* __restrict__ Y) {
    const int j = blockIdx.x * blockDim.x + threadIdx.x;
    const int b = blockIdx.y;
    const float* x1 = img + (size_t)b * 512;
    const float* x2 = sent + (size_t)b * 512;
    float acc = bias[j];
    for (int k = 0; k < 512; k++) acc = fmaf(x1[k], W[(size_t)k * 512 + j], acc);
    for (int k = 0; k < 512; k++) acc = fmaf(x2[k], W[(size_t)(512 + k) * 512 + j], acc);
    Y[(size_t)b * 512 + j] = acc > 0.0f ? acc : 0.0f;
}

// pool: one block per image; thread = (c8, iq); uint4 loads + shfl reduce over iq
__global__ void pool2_k(const h16* __restrict__ x, float* __restrict__ y) {
    const int n = blockIdx.x;
    const int tid = threadIdx.x;
    const int c8 = tid >> 2;
    const int iq = tid & 3;
    const h16* p = x + (size_t)n * 196 * 512 + c8 * 8;
    float s[8];
#pragma unroll
    for (int j = 0; j < 8; j++) s[j] = 0.0f;
    for (int i = iq; i < 196; i += 4) {
        uint4 v = *(const uint4*)(p + (size_t)i * 512);
        const h16* hv = (const h16*)&v;
#pragma unroll
        for (int j = 0; j < 8; j++) s[j] += __half2float(hv[j]);
    }
#pragma unroll
    for (int j = 0; j < 8; j++) {
        s[j] += __shfl_down_sync(0xFFFFFFFFu, s[j], 1);
        s[j] += __shfl_down_sync(0xFFFFFFFFu, s[j], 2);
    }
    if (iq == 0) {
#pragma unroll
        for (int j = 0; j < 8; j++)
            y[(size_t)n * 512 + c8 * 8 + j] = s[j] * (1.0f / 196.0f);
    }
}

// ============================ launch ============================
extern "C" void kernel_launch(void* const* d_in, const int* in_sizes, int n_in,
                              void* d_out, int out_size) {
    const float* images = (const float*)d_in[0];
    const int*   seq    = (const int*)d_in[1];
    const int*   len    = (const int*)d_in[2];
    const float* emb    = (const float*)d_in[4];
    const float* cw1 = (const float*)d_in[5],  *cb1 = (const float*)d_in[6];
    const float* cw2 = (const float*)d_in[7],  *cb2 = (const float*)d_in[8];
    const float* cw3 = (const float*)d_in[9],  *cb3 = (const float*)d_in[10];
    const float* cw4 = (const float*)d_in[11], *cb4 = (const float*)d_in[12];
    const float* rnn_w = (const float*)d_in[13], *rnn_b = (const float*)d_in[14];
    const float* fc1_w = (const float*)d_in[15], *fc1_b = (const float*)d_in[16];
    const float* fc2_w = (const float*)d_in[17], *fc2_b = (const float*)d_in[18];
    const float* clf_w = (const float*)d_in[19], *clf_b = (const float*)d_in[20];
    float* out = (float*)d_out;

    h16 *x1, *x2, *x3, *x4, *w1, *w2, *w3, *w4;
    float *mean, *sent, *img, *h1, *h2;
    cudaGetSymbolAddress((void**)&x1, g_x1); cudaGetSymbolAddress((void**)&x2, g_x2);
    cudaGetSymbolAddress((void**)&x3, g_x3); cudaGetSymbolAddress((void**)&x4, g_x4);
    cudaGetSymbolAddress((void**)&w1, g_w1); cudaGetSymbolAddress((void**)&w2, g_w2);
    cudaGetSymbolAddress((void**)&w3, g_w3); cudaGetSymbolAddress((void**)&w4, g_w4);
    cudaGetSymbolAddress((void**)&mean, g_mean); cudaGetSymbolAddress((void**)&sent, g_sent);
    cudaGetSymbolAddress((void**)&img, g_img);
    cudaGetSymbolAddress((void**)&h1, g_h1);     cudaGetSymbolAddress((void**)&h2, g_h2);

    const int smemN128 = 2 * (ATILE_B + 128 * PITCH * 2);   // 73728 (double buffer)
    const int smemN64  = 2 * (ATILE_B + 64 * PITCH * 2);    // 55296 (double buffer)
    const int smem1    = ATILE_B + 64 * PITCH * 2;          // 27648 (single, conv1)
    cudaFuncSetAttribute(conv1mm_k, cudaFuncAttributeMaxDynamicSharedMemorySize, smem1);
    cudaFuncSetAttribute(convmm_k<64, 128, 112, 112, 128>, cudaFuncAttributeMaxDynamicSharedMemorySize, smemN128);
    cudaFuncSetAttribute(convmm_k<128, 256, 56, 56, 64>,   cudaFuncAttributeMaxDynamicSharedMemorySize, smemN64);
    cudaFuncSetAttribute(convmm_k<256, 512, 28, 28, 64>,   cudaFuncAttributeMaxDynamicSharedMemorySize, smemN64);

    // text branch
    embed_mean_k<<<64, 128>>>(seq, len, emb, mean);
    linear_k<<<dim3(2, 64), 256>>>(mean, rnn_w, rnn_b, sent, 512, 512, 0);

    // merged weight prep
    wprep_all_k<<<(2048 + 73728 + 294912 + 1179648 + 255) / 256, 256>>>(
        cw1, cw2, cw3, cw4, w1, w2, w3, w4);

    // vision branch
    conv1mm_k<<<6272, 256, smem1>>>(images, w1, cb1, x1);
    convmm_k<64, 128, 112, 112, 128><<<dim3(1568, 1), 256, smemN128>>>(x1, w2, cb2, x2);
    convmm_k<128, 256, 56, 56, 64><<<dim3(392, 4), 256, smemN64>>>(x2, w3, cb3, x3);
    convmm_k<256, 512, 28, 28, 64><<<dim3(98, 8), 256, smemN64>>>(x3, w4, cb4, x4);
    pool2_k<<<64, 256>>>(x4, img);

    // head
    fc1_k<<<dim3(2, 64), 256>>>(img, sent, fc1_w, fc1_b, h1);
    linear_k<<<dim3(2, 64), 256>>>(h1, fc2_w, fc2_b, h2, 512, 512, 1);
    linear_k<<<dim3(4, 64), 256>>>(h2, clf_w, clf_b, out, 512, 1000, 0);
}

// round 14
// speedup vs baseline: 2.9999x; 1.1857x over previous
#include <cuda_runtime.h>
#include <cuda_fp16.h>
#include <cstdint>
#include <cstddef>

typedef __half h16;

// ============================ helpers ============================
__device__ __forceinline__ uint32_t smem_u32(const void* p) {
    uint32_t a;
    asm("{ .reg .u64 t; cvta.to.shared.u64 t, %1; cvt.u32.u64 %0, t; }" : "=r"(a) : "l"(p));
    return a;
}
__device__ __forceinline__ void ldsm4(uint32_t& r0, uint32_t& r1, uint32_t& r2, uint32_t& r3,
                                      uint32_t addr) {
    asm volatile("ldmatrix.sync.aligned.m8n8.x4.shared.b16 {%0,%1,%2,%3}, [%4];"
                 : "=r"(r0), "=r"(r1), "=r"(r2), "=r"(r3) : "r"(addr));
}
__device__ __forceinline__ void mma16816(float c[4], const uint32_t a[4], const uint32_t b[2]) {
    asm volatile(
        "mma.sync.aligned.m16n8k16.row.col.f32.f16.f16.f32 "
        "{%0,%1,%2,%3}, {%4,%5,%6,%7}, {%8,%9}, {%0,%1,%2,%3};"
        : "+f"(c[0]), "+f"(c[1]), "+f"(c[2]), "+f"(c[3])
        : "r"(a[0]), "r"(a[1]), "r"(a[2]), "r"(a[3]), "r"(b[0]), "r"(b[1]));
}
// 16B async copy, zero-fill when srcsize==0
__device__ __forceinline__ void cp16(uint32_t dst, const void* src, uint32_t srcsize) {
    asm volatile("cp.async.cg.shared.global [%0], [%1], 16, %2;"
                 :: "r"(dst), "l"(src), "r"(srcsize) : "memory");
}
#define CP_COMMIT() asm volatile("cp.async.commit_group;" ::: "memory")
#define CP_WAIT(n)  asm volatile("cp.async.wait_group %0;" :: "n"(n) : "memory")

// smem tile pitch: 72 h16 (144 B) -> row stride 36 words -> ldmatrix conflict-free
static constexpr int PITCH = 72;
static constexpr int ATILE_B = 128 * PITCH * 2;   // 18432 bytes per 128x64 tile

// ============================ scratch ============================
__device__ h16 g_x1[(size_t)64 * 112 * 112 * 64];
__device__ h16 g_x2[(size_t)64 * 56 * 56 * 128];
__device__ h16 g_x3[(size_t)64 * 28 * 28 * 256];
__device__ h16 g_x4[(size_t)64 * 14 * 14 * 512];
__device__ h16 g_w1[64 * 32];               // conv1 padded [co][32]
__device__ h16 g_w2[9 * 128 * 64];          // [t][co][ci]
__device__ h16 g_w3[9 * 256 * 128];
__device__ h16 g_w4[9 * 512 * 256];
__device__ float g_sent[64 * 512];

// ============================ merged weight prep ============================
__global__ void wprep_all_k(const float* __restrict__ cw1, const float* __restrict__ cw2,
                            const float* __restrict__ cw3, const float* __restrict__ cw4,
                            h16* __restrict__ w1, h16* __restrict__ w2,
                            h16* __restrict__ w3, h16* __restrict__ w4) {
    int idx = blockIdx.x * 256 + threadIdx.x;
    if (idx < 2048) {
        int co = idx >> 5, k = idx & 31;
        w1[idx] = __float2half_rn((k < 27) ? cw1[co * 27 + k] : 0.0f);
        return;
    }
    idx -= 2048;
    const float* src; h16* dst; int COUT, CIN;
    if (idx < 73728)        { src = cw2; dst = w2; COUT = 128; CIN = 64; }
    else if (idx < 73728 + 294912) { idx -= 73728; src = cw3; dst = w3; COUT = 256; CIN = 128; }
    else                    { idx -= 73728 + 294912; if (idx >= 1179648) return;
                              src = cw4; dst = w4; COUT = 512; CIN = 256; }
    int co = idx / (CIN * 9);
    int rem = idx - co * (CIN * 9);
    int ci = rem / 9, t = rem - ci * 9;
    dst[(t * COUT + co) * CIN + ci] = __float2half_rn(src[idx]);
}

// ============================ warp-level GEMM core ============================
template <int NFRAG, int KSTEPS>
__device__ __forceinline__ void chunk_mma(uint32_t sbA, uint32_t sbB,
                                          int lane, int warpM, int warpN,
                                          float (&c)[2][NFRAG][4]) {
    const int arow = warpM * 32 + (lane & 15);
    const int akoff = (lane >> 4) * 8;
    const int brow = warpN * (NFRAG * 8) + (lane & 7) + ((lane >> 3) & 1) * 8;
    const int bkoff = (lane >> 4) * 8;
#pragma unroll
    for (int ks = 0; ks < KSTEPS; ks++) {
        const int k0 = ks * 16;
        uint32_t ah[2][4];
#pragma unroll
        for (int i = 0; i < 2; i++) {
            const uint32_t aoff = (((arow + i * 16) * PITCH) + k0 + akoff) * 2;
            ldsm4(ah[i][0], ah[i][1], ah[i][2], ah[i][3], sbA + aoff);
        }
        uint32_t bh[NFRAG][2];
#pragma unroll
        for (int j2 = 0; j2 < NFRAG / 2; j2++) {
            const uint32_t boff = (((brow + j2 * 16) * PITCH) + k0 + bkoff) * 2;
            uint32_t r0, r1, r2, r3;
            ldsm4(r0, r1, r2, r3, sbB + boff);
            bh[2 * j2][0] = r0; bh[2 * j2][1] = r2;
            bh[2 * j2 + 1][0] = r1; bh[2 * j2 + 1][1] = r3;
        }
#pragma unroll
        for (int i = 0; i < 2; i++)
#pragma unroll
            for (int j = 0; j < NFRAG; j++)
                mma16816(c[i][j], ah[i], bh[j]);
    }
}

// epilogue: bias + relu + cvt -> NHWC fp16
template <int NFRAG, int COUT>
__device__ __forceinline__ void epilogue(float (&c)[2][NFRAG][4], const float* __restrict__ bias,
                                         int tile0, int cob, int lane, int warpM, int warpN,
                                         h16* __restrict__ y) {
#pragma unroll
    for (int i = 0; i < 2; i++) {
        const int r0 = tile0 + warpM * 32 + i * 16 + (lane >> 2);
#pragma unroll
        for (int j = 0; j < NFRAG; j++) {
            const int col = cob + warpN * (NFRAG * 8) + j * 8 + (lane & 3) * 2;
            const float b0 = bias[col], b1 = bias[col + 1];
#pragma unroll
            for (int h = 0; h < 2; h++) {
                const int r = r0 + h * 8;
                float v0 = c[i][j][2 * h + 0] + b0; if (v0 < 0.0f) v0 = 0.0f;
                float v1 = c[i][j][2 * h + 1] + b1; if (v1 < 0.0f) v1 = 0.0f;
                __half2 p;
                p.x = __float2half_rn(v0); p.y = __float2half_rn(v1);
                *(__half2*)(y + (size_t)r * COUT + col) = p;
            }
        }
    }
}

// ============================ conv2/3/4: implicit GEMM, cp.async double-buffer, 2 CTAs/SM ============================
template <int CIN, int COUT, int HIN, int WIN, int NTILE>
__global__ void __launch_bounds__(256, 2)
convmm_k(const h16* __restrict__ x, const h16* __restrict__ wt,
         const float* __restrict__ bias, h16* __restrict__ y) {
    constexpr int HOUT = HIN / 2, WOUT = WIN / 2;
    constexpr int CPT = CIN / 64;
    constexpr int NCH = 9 * CPT;
    constexpr int NFRAG = NTILE / 16;
    constexpr int BSLOTS = NTILE / 32;
    constexpr int BUF_B = ATILE_B + NTILE * PITCH * 2;   // A tile + B tile

    extern __shared__ char sb[];
    const uint32_t sb32 = smem_u32(sb);

    const int tid = threadIdx.x, lane = tid & 31, wid = tid >> 5;
    const int warpM = wid >> 1, warpN = wid & 1;
    const int tile0 = blockIdx.x * 128;
    const int cob = blockIdx.y * NTILE;

    const int c16 = tid & 7;
    int baseoff[4]; bool xe[4], ye[4];
#pragma unroll
    for (int r4 = 0; r4 < 4; r4++) {
        const int row = (tid >> 3) + 32 * r4;
        const int s = tile0 + row;
        const int n = s / (HOUT * WOUT);
        const int rem = s - n * (HOUT * WOUT);
        const int y2 = rem / WOUT;
        const int x2 = rem - y2 * WOUT;
        baseoff[r4] = ((n * HIN + 2 * y2) * WIN + 2 * x2) * CIN;
        xe[r4] = (2 * x2 + 2 >= WIN);
        ye[r4] = (2 * y2 + 2 >= HIN);
    }

    auto stage = [&](int ch) {
        const int t = ch / CPT;
        const int cb = (ch - t * CPT) * 64;
        const int ky = t / 3, kx = t - ky * 3;
        const uint32_t base = sb32 + (ch & 1) * BUF_B;
#pragma unroll
        for (int r4 = 0; r4 < 4; r4++) {
            const int row = (tid >> 3) + 32 * r4;
            const uint32_t soff = (row * PITCH + c16 * 8) * 2;
            const bool valid = !((kx == 2 && xe[r4]) || (ky == 2 && ye[r4]));
            const size_t src = (size_t)baseoff[r4] + (ky * WIN + kx) * CIN + cb + c16 * 8;
            cp16(base + soff, x + src, valid ? 16u : 0u);
            if (r4 < BSLOTS) {
                const size_t wsrc = ((size_t)t * COUT + cob + row) * CIN + cb + c16 * 8;
                cp16(base + ATILE_B + soff, wt + wsrc, 16u);
            }
        }
        CP_COMMIT();
    };

    float c[2][NFRAG][4];
#pragma unroll
    for (int i = 0; i < 2; i++)
#pragma unroll
        for (int j = 0; j < NFRAG; j++)
#pragma unroll
            for (int q = 0; q < 4; q++) c[i][j][q] = 0.0f;

    stage(0);
    for (int ch = 0; ch < NCH; ch++) {
        if (ch + 1 < NCH) { stage(ch + 1); CP_WAIT(1); }
        else              { CP_WAIT(0); }
        __syncthreads();
        const uint32_t base = sb32 + (ch & 1) * BUF_B;
        chunk_mma<NFRAG, 4>(base, base + ATILE_B, lane, warpM, warpN, c);
        __syncthreads();
    }

    epilogue<NFRAG, COUT>(c, bias, tile0, cob, lane, warpM, warpN, y);
}

// ============================ conv1: implicit GEMM, K=27 (padded 32), 4 CTAs/SM ============================
__global__ void __launch_bounds__(256, 4)
conv1mm_k(const float* __restrict__ images,
          const h16* __restrict__ wh,
          const float* __restrict__ bias,
          h16* __restrict__ y) {
    constexpr int HOUT = 112, WOUT = 112, HIN = 224, WIN = 224;
    constexpr int NFRAG = 4;

    extern __shared__ char sb[];
    const uint32_t sb32 = smem_u32(sb);
    const uint32_t oA = 0, oB = ATILE_B;

    const int tid = threadIdx.x, lane = tid & 31, wid = tid >> 5;
    const int warpM = wid >> 1, warpN = wid & 1;
    const int tile0 = blockIdx.x * 128;

    // A staging: thread owns (row, k-half); register-pack 16 taps, 2x STS.128
    {
        const int g = wid >> 2;                 // 0: k0..15, 1: k16..31
        const int row = ((wid & 3) << 5) + lane;
        const int s = tile0 + row;
        const int n = s / (HOUT * WOUT);
        const int rem = s - n * (HOUT * WOUT);
        const int y2 = rem / WOUT;
        const int x2 = rem - y2 * WOUT;
        const float* p0 = images + ((size_t)(n * 3) * HIN + 2 * y2) * WIN + 2 * x2;
        const bool xok = (x2 < 111);
        const bool yok = (y2 < 111);
        union { h16 h[16]; uint4 u[2]; } pk;
#pragma unroll
        for (int i = 0; i < 16; i++) pk.h[i] = __float2half_rn(0.0f);
        if (g == 0) {
#pragma unroll
            for (int kk = 0; kk < 16; kk++) {
                const int ci = kk / 9, r = kk - ci * 9, ky = r / 3, kx = r - ky * 3;
                const bool ok = (kx < 2 || xok) && (ky < 2 || yok);
                if (ok) pk.h[kk] = __float2half_rn(p0[(size_t)ci * (HIN * WIN) + ky * WIN + kx]);
            }
        } else {
#pragma unroll
            for (int kk = 0; kk < 11; kk++) {
                const int k = 16 + kk;
                const int ci = k / 9, r = k - ci * 9, ky = r / 3, kx = r - ky * 3;
                const bool ok = (kx < 2 || xok) && (ky < 2 || yok);
                if (ok) pk.h[kk] = __float2half_rn(p0[(size_t)ci * (HIN * WIN) + ky * WIN + kx]);
            }
        }
        char* dst = sb + oA + row * (PITCH * 2) + g * 32;
        *(uint4*)dst = pk.u[0];
        *(uint4*)(dst + 16) = pk.u[1];
    }
    // B staging: 64 couts x 32 k (w1 is [co][32])
    if (tid < 256) {
        const int r = tid >> 2, c16 = tid & 3;
        *(uint4*)(sb + oB + (r * PITCH + c16 * 8) * 2) = *(const uint4*)(wh + r * 32 + c16 * 8);
    }
    __syncthreads();

    float c[2][NFRAG][4];
#pragma unroll
    for (int i = 0; i < 2; i++)
#pragma unroll
        for (int j = 0; j < NFRAG; j++)
#pragma unroll
            for (int q = 0; q < 4; q++) c[i][j][q] = 0.0f;

    chunk_mma<NFRAG, 2>(sb32 + oA, sb32 + oB, lane, warpM, warpN, c);

    epilogue<NFRAG, 64>(c, bias, tile0, 0, lane, warpM, warpN, y);
}

// ============================ fused text branch: embed mean + rnn linear ============================
__global__ void __launch_bounds__(512)
text_k(const int* __restrict__ seq, const int* __restrict__ len,
       const float* __restrict__ emb,
       const float* __restrict__ rnn_w, const float* __restrict__ rnn_b,
       float* __restrict__ sent) {
    const int b = blockIdx.x;
    const int tid = threadIdx.x;   // 0..511
    __shared__ int s_idx[128];
    __shared__ float s_m[512];
    if (tid < 128) s_idx[tid] = seq[b * 128 + tid];
    __syncthreads();
    const int L = len[b];
    float acc = 0.0f;
    for (int s = 0; s < L; s++) acc += emb[(size_t)s_idx[s] * 512 + tid];
    s_m[tid] = acc / (float)L;
    __syncthreads();
    float o = rnn_b[tid];
    for (int k = 0; k < 512; k++) o = fmaf(s_m[k], rnn_w[(size_t)k * 512 + tid], o);
    sent[(size_t)b * 512 + tid] = o;
}

// ============================ fused head: pool + fc1(concat) + fc2 + clf ============================
__global__ void __launch_bounds__(512)
head_k(const h16* __restrict__ x4, const float* __restrict__ sent,
       const float* __restrict__ fc1_w, const float* __restrict__ fc1_b,
       const float* __restrict__ fc2_w, const float* __restrict__ fc2_b,
       const float* __restrict__ clf_w, const float* __restrict__ clf_b,
       float* __restrict__ out) {
    const int b = blockIdx.x;
    const int tid = threadIdx.x;   // 0..511
    __shared__ float s_a[512], s_s[512], s_h1[512], s_h2[512];

    // pool: channel tid, mean over 196 positions
    const h16* p = x4 + (size_t)b * 196 * 512 + tid;
    float sum = 0.0f;
    for (int i = 0; i < 196; i++) sum += __half2float(p[(size_t)i * 512]);
    s_a[tid] = sum * (1.0f / 196.0f);
    s_s[tid] = sent[(size_t)b * 512 + tid];
    __syncthreads();

    // fc1 (concat fused) + relu
    float a1 = fc1_b[tid];
    for (int k = 0; k < 512; k++) a1 = fmaf(s_a[k], fc1_w[(size_t)k * 512 + tid], a1);
    for (int k = 0; k < 512; k++) a1 = fmaf(s_s[k], fc1_w[(size_t)(512 + k) * 512 + tid], a1);
    s_h1[tid] = a1 > 0.0f ? a1 : 0.0f;
    __syncthreads();

    // fc2 + relu
    float a2 = fc2_b[tid];
    for (int k = 0; k < 512; k++) a2 = fmaf(s_h1[k], fc2_w[(size_t)k * 512 + tid], a2);
    s_h2[tid] = a2 > 0.0f ? a2 : 0.0f;
    __syncthreads();

    // clf (N=1000)
    for (int n = tid; n < 1000; n += 512) {
        float o = clf_b[n];
        for (int k = 0; k < 512; k++) o = fmaf(s_h2[k], clf_w[(size_t)k * 1000 + n], o);
        out[(size_t)b * 1000 + n] = o;
    }
}

// ============================ launch ============================
extern "C" void kernel_launch(void* const* d_in, const int* in_sizes, int n_in,
                              void* d_out, int out_size) {
    const float* images = (const float*)d_in[0];
    const int*   seq    = (const int*)d_in[1];
    const int*   len    = (const int*)d_in[2];
    const float* emb    = (const float*)d_in[4];
    const float* cw1 = (const float*)d_in[5],  *cb1 = (const float*)d_in[6];
    const float* cw2 = (const float*)d_in[7],  *cb2 = (const float*)d_in[8];
    const float* cw3 = (const float*)d_in[9],  *cb3 = (const float*)d_in[10];
    const float* cw4 = (const float*)d_in[11], *cb4 = (const float*)d_in[12];
    const float* rnn_w = (const float*)d_in[13], *rnn_b = (const float*)d_in[14];
    const float* fc1_w = (const float*)d_in[15], *fc1_b = (const float*)d_in[16];
    const float* fc2_w = (const float*)d_in[17], *fc2_b = (const float*)d_in[18];
    const float* clf_w = (const float*)d_in[19], *clf_b = (const float*)d_in[20];
    float* out = (float*)d_out;

    h16 *x1, *x2, *x3, *x4, *w1, *w2, *w3, *w4;
    float *sent;
    cudaGetSymbolAddress((void**)&x1, g_x1); cudaGetSymbolAddress((void**)&x2, g_x2);
    cudaGetSymbolAddress((void**)&x3, g_x3); cudaGetSymbolAddress((void**)&x4, g_x4);
    cudaGetSymbolAddress((void**)&w1, g_w1); cudaGetSymbolAddress((void**)&w2, g_w2);
    cudaGetSymbolAddress((void**)&w3, g_w3); cudaGetSymbolAddress((void**)&w4, g_w4);
    cudaGetSymbolAddress((void**)&sent, g_sent);

    const int smemN128 = 2 * (ATILE_B + 128 * PITCH * 2);   // 73728 (double buffer)
    const int smemN64  = 2 * (ATILE_B + 64 * PITCH * 2);    // 55296 (double buffer)
    const int smem1    = ATILE_B + 64 * PITCH * 2;          // 27648 (single, conv1)
    cudaFuncSetAttribute(conv1mm_k, cudaFuncAttributeMaxDynamicSharedMemorySize, smem1);
    cudaFuncSetAttribute(convmm_k<64, 128, 112, 112, 128>, cudaFuncAttributeMaxDynamicSharedMemorySize, smemN128);
    cudaFuncSetAttribute(convmm_k<128, 256, 56, 56, 64>,   cudaFuncAttributeMaxDynamicSharedMemorySize, smemN64);
    cudaFuncSetAttribute(convmm_k<256, 512, 28, 28, 64>,   cudaFuncAttributeMaxDynamicSharedMemorySize, smemN64);

    // 1: text branch (fused)
    text_k<<<64, 512>>>(seq, len, emb, rnn_w, rnn_b, sent);

    // 2: merged weight prep
    wprep_all_k<<<(2048 + 73728 + 294912 + 1179648 + 255) / 256, 256>>>(
        cw1, cw2, cw3, cw4, w1, w2, w3, w4);

    // 3-6: vision branch
    conv1mm_k<<<6272, 256, smem1>>>(images, w1, cb1, x1);
    convmm_k<64, 128, 112, 112, 128><<<dim3(1568, 1), 256, smemN128>>>(x1, w2, cb2, x2);
    convmm_k<128, 256, 56, 56, 64><<<dim3(392, 4), 256, smemN64>>>(x2, w3, cb3, x3);
    convmm_k<256, 512, 28, 28, 64><<<dim3(98, 8), 256, smemN64>>>(x3, w4, cb4, x4);

    // 7: fused head (pool + fc1 + fc2 + clf)
    head_k<<<64, 512>>>(x4, sent, fc1_w, fc1_b, fc2_w, fc2_b, clf_w, clf_b, out);
}

// round 15
// speedup vs baseline: 3.0422x; 1.0141x over previous
#include <cuda_runtime.h>
#include <cuda_fp16.h>
#include <cstdint>
#include <cstddef>

typedef __half h16;

// ============================ helpers ============================
__device__ __forceinline__ uint32_t smem_u32(const void* p) {
    uint32_t a;
    asm("{ .reg .u64 t; cvta.to.shared.u64 t, %1; cvt.u32.u64 %0, t; }" : "=r"(a) : "l"(p));
    return a;
}
__device__ __forceinline__ void ldsm4(uint32_t& r0, uint32_t& r1, uint32_t& r2, uint32_t& r3,
                                      uint32_t addr) {
    asm volatile("ldmatrix.sync.aligned.m8n8.x4.shared.b16 {%0,%1,%2,%3}, [%4];"
                 : "=r"(r0), "=r"(r1), "=r"(r2), "=r"(r3) : "r"(addr));
}
__device__ __forceinline__ void mma16816(float c[4], const uint32_t a[4], const uint32_t b[2]) {
    asm volatile(
        "mma.sync.aligned.m16n8k16.row.col.f32.f16.f16.f32 "
        "{%0,%1,%2,%3}, {%4,%5,%6,%7}, {%8,%9}, {%0,%1,%2,%3};"
        : "+f"(c[0]), "+f"(c[1]), "+f"(c[2]), "+f"(c[3])
        : "r"(a[0]), "r"(a[1]), "r"(a[2]), "r"(a[3]), "r"(b[0]), "r"(b[1]));
}
// 16B async copy, zero-fill when srcsize==0
__device__ __forceinline__ void cp16(uint32_t dst, const void* src, uint32_t srcsize) {
    asm volatile("cp.async.cg.shared.global [%0], [%1], 16, %2;"
                 :: "r"(dst), "l"(src), "r"(srcsize) : "memory");
}
#define CP_COMMIT() asm volatile("cp.async.commit_group;" ::: "memory")
#define CP_WAIT(n)  asm volatile("cp.async.wait_group %0;" :: "n"(n) : "memory")

// smem tile pitch: 72 h16 (144 B) -> row stride 36 words -> ldmatrix conflict-free
static constexpr int PITCH = 72;
static constexpr int ATILE_B = 128 * PITCH * 2;   // 18432 bytes per 128x64 tile

// ============================ scratch ============================
__device__ h16 g_x1[(size_t)64 * 112 * 112 * 64];
__device__ h16 g_x2[(size_t)64 * 56 * 56 * 128];
__device__ h16 g_x3[(size_t)64 * 28 * 28 * 256];
__device__ h16 g_x4[(size_t)64 * 14 * 14 * 512];
__device__ h16 g_w1[64 * 32];               // conv1 padded [co][32]
__device__ h16 g_w2[9 * 128 * 64];          // [t][co][ci]
__device__ h16 g_w3[9 * 256 * 128];
__device__ h16 g_w4[9 * 512 * 256];
__device__ float g_sent[64 * 512];

// ============================ merged weight prep ============================
__global__ void wprep_all_k(const float* __restrict__ cw1, const float* __restrict__ cw2,
                            const float* __restrict__ cw3, const float* __restrict__ cw4,
                            h16* __restrict__ w1, h16* __restrict__ w2,
                            h16* __restrict__ w3, h16* __restrict__ w4) {
    int idx = blockIdx.x * 256 + threadIdx.x;
    if (idx < 2048) {
        int co = idx >> 5, k = idx & 31;
        w1[idx] = __float2half_rn((k < 27) ? cw1[co * 27 + k] : 0.0f);
        return;
    }
    idx -= 2048;
    const float* src; h16* dst; int COUT, CIN;
    if (idx < 73728)        { src = cw2; dst = w2; COUT = 128; CIN = 64; }
    else if (idx < 73728 + 294912) { idx -= 73728; src = cw3; dst = w3; COUT = 256; CIN = 128; }
    else                    { idx -= 73728 + 294912; if (idx >= 1179648) return;
                              src = cw4; dst = w4; COUT = 512; CIN = 256; }
    int co = idx / (CIN * 9);
    int rem = idx - co * (CIN * 9);
    int ci = rem / 9, t = rem - ci * 9;
    dst[(t * COUT + co) * CIN + ci] = __float2half_rn(src[idx]);
}

// ============================ warp-level GEMM core ============================
template <int NFRAG, int KSTEPS>
__device__ __forceinline__ void chunk_mma(uint32_t sbA, uint32_t sbB,
                                          int lane, int warpM, int warpN,
                                          float (&c)[2][NFRAG][4]) {
    const int arow = warpM * 32 + (lane & 15);
    const int akoff = (lane >> 4) * 8;
    const int brow = warpN * (NFRAG * 8) + (lane & 7) + ((lane >> 3) & 1) * 8;
    const int bkoff = (lane >> 4) * 8;
#pragma unroll
    for (int ks = 0; ks < KSTEPS; ks++) {
        const int k0 = ks * 16;
        uint32_t ah[2][4];
#pragma unroll
        for (int i = 0; i < 2; i++) {
            const uint32_t aoff = (((arow + i * 16) * PITCH) + k0 + akoff) * 2;
            ldsm4(ah[i][0], ah[i][1], ah[i][2], ah[i][3], sbA + aoff);
        }
        uint32_t bh[NFRAG][2];
#pragma unroll
        for (int j2 = 0; j2 < NFRAG / 2; j2++) {
            const uint32_t boff = (((brow + j2 * 16) * PITCH) + k0 + bkoff) * 2;
            uint32_t r0, r1, r2, r3;
            ldsm4(r0, r1, r2, r3, sbB + boff);
            bh[2 * j2][0] = r0; bh[2 * j2][1] = r2;
            bh[2 * j2 + 1][0] = r1; bh[2 * j2 + 1][1] = r3;
        }
#pragma unroll
        for (int i = 0; i < 2; i++)
#pragma unroll
            for (int j = 0; j < NFRAG; j++)
                mma16816(c[i][j], ah[i], bh[j]);
    }
}

// epilogue: bias + relu + cvt -> NHWC fp16
template <int NFRAG, int COUT>
__device__ __forceinline__ void epilogue(float (&c)[2][NFRAG][4], const float* __restrict__ bias,
                                         int tile0, int cob, int lane, int warpM, int warpN,
                                         h16* __restrict__ y) {
#pragma unroll
    for (int i = 0; i < 2; i++) {
        const int r0 = tile0 + warpM * 32 + i * 16 + (lane >> 2);
#pragma unroll
        for (int j = 0; j < NFRAG; j++) {
            const int col = cob + warpN * (NFRAG * 8) + j * 8 + (lane & 3) * 2;
            const float b0 = bias[col], b1 = bias[col + 1];
#pragma unroll
            for (int h = 0; h < 2; h++) {
                const int r = r0 + h * 8;
                float v0 = c[i][j][2 * h + 0] + b0; if (v0 < 0.0f) v0 = 0.0f;
                float v1 = c[i][j][2 * h + 1] + b1; if (v1 < 0.0f) v1 = 0.0f;
                __half2 p;
                p.x = __float2half_rn(v0); p.y = __float2half_rn(v1);
                *(__half2*)(y + (size_t)r * COUT + col) = p;
            }
        }
    }
}

// ============================ conv2/3/4: implicit GEMM, cp.async double-buffer, 3 CTAs/SM ============================
template <int CIN, int COUT, int HIN, int WIN>
__global__ void __launch_bounds__(256, 3)
convmm_k(const h16* __restrict__ x, const h16* __restrict__ wt,
         const float* __restrict__ bias, h16* __restrict__ y) {
    constexpr int HOUT = HIN / 2, WOUT = WIN / 2;
    constexpr int CPT = CIN / 64;
    constexpr int NCH = 9 * CPT;
    constexpr int NTILE = 64;
    constexpr int NFRAG = NTILE / 16;        // 4
    constexpr int BSLOTS = NTILE / 32;       // 2
    constexpr int BUF_B = ATILE_B + NTILE * PITCH * 2;   // A tile + B tile = 27648

    extern __shared__ char sb[];
    const uint32_t sb32 = smem_u32(sb);

    const int tid = threadIdx.x, lane = tid & 31, wid = tid >> 5;
    const int warpM = wid >> 1, warpN = wid & 1;
    const int tile0 = blockIdx.x * 128;
    const int cob = blockIdx.y * NTILE;

    const int c16 = tid & 7;
    int baseoff[4]; bool xe[4], ye[4];
#pragma unroll
    for (int r4 = 0; r4 < 4; r4++) {
        const int row = (tid >> 3) + 32 * r4;
        const int s = tile0 + row;
        const int n = s / (HOUT * WOUT);
        const int rem = s - n * (HOUT * WOUT);
        const int y2 = rem / WOUT;
        const int x2 = rem - y2 * WOUT;
        baseoff[r4] = ((n * HIN + 2 * y2) * WIN + 2 * x2) * CIN;
        xe[r4] = (2 * x2 + 2 >= WIN);
        ye[r4] = (2 * y2 + 2 >= HIN);
    }

    auto stage = [&](int ch) {
        const int t = ch / CPT;
        const int cb = (ch - t * CPT) * 64;
        const int ky = t / 3, kx = t - ky * 3;
        const uint32_t base = sb32 + (ch & 1) * BUF_B;
#pragma unroll
        for (int r4 = 0; r4 < 4; r4++) {
            const int row = (tid >> 3) + 32 * r4;
            const uint32_t soff = (row * PITCH + c16 * 8) * 2;
            const bool valid = !((kx == 2 && xe[r4]) || (ky == 2 && ye[r4]));
            const size_t src = (size_t)baseoff[r4] + (ky * WIN + kx) * CIN + cb + c16 * 8;
            cp16(base + soff, x + src, valid ? 16u : 0u);
            if (r4 < BSLOTS) {
                const size_t wsrc = ((size_t)t * COUT + cob + row) * CIN + cb + c16 * 8;
                cp16(base + ATILE_B + soff, wt + wsrc, 16u);
            }
        }
        CP_COMMIT();
    };

    float c[2][NFRAG][4];
#pragma unroll
    for (int i = 0; i < 2; i++)
#pragma unroll
        for (int j = 0; j < NFRAG; j++)
#pragma unroll
            for (int q = 0; q < 4; q++) c[i][j][q] = 0.0f;

    stage(0);
    for (int ch = 0; ch < NCH; ch++) {
        if (ch + 1 < NCH) { stage(ch + 1); CP_WAIT(1); }
        else              { CP_WAIT(0); }
        __syncthreads();
        const uint32_t base = sb32 + (ch & 1) * BUF_B;
        chunk_mma<NFRAG, 4>(base, base + ATILE_B, lane, warpM, warpN, c);
        __syncthreads();
    }

    epilogue<NFRAG, COUT>(c, bias, tile0, cob, lane, warpM, warpN, y);
}

// ============================ conv1: implicit GEMM, K=27 (padded 32), 4 CTAs/SM ============================
__global__ void __launch_bounds__(256, 4)
conv1mm_k(const float* __restrict__ images,
          const h16* __restrict__ wh,
          const float* __restrict__ bias,
          h16* __restrict__ y) {
    constexpr int HOUT = 112, WOUT = 112, HIN = 224, WIN = 224;
    constexpr int NFRAG = 4;

    extern __shared__ char sb[];
    const uint32_t sb32 = smem_u32(sb);
    const uint32_t oA = 0, oB = ATILE_B;

    const int tid = threadIdx.x, lane = tid & 31, wid = tid >> 5;
    const int warpM = wid >> 1, warpN = wid & 1;
    const int tile0 = blockIdx.x * 128;

    // A staging: thread owns (row, k-half); register-pack 16 taps, 2x STS.128
    {
        const int g = wid >> 2;                 // 0: k0..15, 1: k16..31
        const int row = ((wid & 3) << 5) + lane;
        const int s = tile0 + row;
        const int n = s / (HOUT * WOUT);
        const int rem = s - n * (HOUT * WOUT);
        const int y2 = rem / WOUT;
        const int x2 = rem - y2 * WOUT;
        const float* p0 = images + ((size_t)(n * 3) * HIN + 2 * y2) * WIN + 2 * x2;
        const bool xok = (x2 < 111);
        const bool yok = (y2 < 111);
        union { h16 h[16]; uint4 u[2]; } pk;
#pragma unroll
        for (int i = 0; i < 16; i++) pk.h[i] = __float2half_rn(0.0f);
        if (g == 0) {
#pragma unroll
            for (int kk = 0; kk < 16; kk++) {
                const int ci = kk / 9, r = kk - ci * 9, ky = r / 3, kx = r - ky * 3;
                const bool ok = (kx < 2 || xok) && (ky < 2 || yok);
                if (ok) pk.h[kk] = __float2half_rn(p0[(size_t)ci * (HIN * WIN) + ky * WIN + kx]);
            }
        } else {
#pragma unroll
            for (int kk = 0; kk < 11; kk++) {
                const int k = 16 + kk;
                const int ci = k / 9, r = k - ci * 9, ky = r / 3, kx = r - ky * 3;
                const bool ok = (kx < 2 || xok) && (ky < 2 || yok);
                if (ok) pk.h[kk] = __float2half_rn(p0[(size_t)ci * (HIN * WIN) + ky * WIN + kx]);
            }
        }
        char* dst = sb + oA + row * (PITCH * 2) + g * 32;
        *(uint4*)dst = pk.u[0];
        *(uint4*)(dst + 16) = pk.u[1];
    }
    // B staging: 64 couts x 32 k (w1 is [co][32])
    if (tid < 256) {
        const int r = tid >> 2, c16 = tid & 3;
        *(uint4*)(sb + oB + (r * PITCH + c16 * 8) * 2) = *(const uint4*)(wh + r * 32 + c16 * 8);
    }
    __syncthreads();

    float c[2][NFRAG][4];
#pragma unroll
    for (int i = 0; i < 2; i++)
#pragma unroll
        for (int j = 0; j < NFRAG; j++)
#pragma unroll
            for (int q = 0; q < 4; q++) c[i][j][q] = 0.0f;

    chunk_mma<NFRAG, 2>(sb32 + oA, sb32 + oB, lane, warpM, warpN, c);

    epilogue<NFRAG, 64>(c, bias, tile0, 0, lane, warpM, warpN, y);
}

// ============================ fused text branch: embed mean + rnn linear ============================
__global__ void __launch_bounds__(512)
text_k(const int* __restrict__ seq, const int* __restrict__ len,
       const float* __restrict__ emb,
       const float* __restrict__ rnn_w, const float* __restrict__ rnn_b,
       float* __restrict__ sent) {
    const int b = blockIdx.x;
    const int tid = threadIdx.x;   // 0..511
    __shared__ int s_idx[128];
    __shared__ float s_m[512];
    if (tid < 128) s_idx[tid] = seq[b * 128 + tid];
    __syncthreads();
    const int L = len[b];
    float acc = 0.0f;
    for (int s = 0; s < L; s++) acc += emb[(size_t)s_idx[s] * 512 + tid];
    s_m[tid] = acc / (float)L;
    __syncthreads();
    float o = rnn_b[tid];
    for (int k = 0; k < 512; k++) o = fmaf(s_m[k], rnn_w[(size_t)k * 512 + tid], o);
    sent[(size_t)b * 512 + tid] = o;
}

// ============================ fused head: pool + fc1(concat) + fc2 + clf ============================
__global__ void __launch_bounds__(512)
head_k(const h16* __restrict__ x4, const float* __restrict__ sent,
       const float* __restrict__ fc1_w, const float* __restrict__ fc1_b,
       const float* __restrict__ fc2_w, const float* __restrict__ fc2_b,
       const float* __restrict__ clf_w, const float* __restrict__ clf_b,
       float* __restrict__ out) {
    const int b = blockIdx.x;
    const int tid = threadIdx.x;   // 0..511
    __shared__ float s_a[512], s_s[512], s_h1[512], s_h2[512];

    // pool: channel tid, mean over 196 positions
    const h16* p = x4 + (size_t)b * 196 * 512 + tid;
    float sum = 0.0f;
    for (int i = 0; i < 196; i++) sum += __half2float(p[(size_t)i * 512]);
    s_a[tid] = sum * (1.0f / 196.0f);
    s_s[tid] = sent[(size_t)b * 512 + tid];
    __syncthreads();

    // fc1 (concat fused) + relu
    float a1 = fc1_b[tid];
    for (int k = 0; k < 512; k++) a1 = fmaf(s_a[k], fc1_w[(size_t)k * 512 + tid], a1);
    for (int k = 0; k < 512; k++) a1 = fmaf(s_s[k], fc1_w[(size_t)(512 + k) * 512 + tid], a1);
    s_h1[tid] = a1 > 0.0f ? a1 : 0.0f;
    __syncthreads();

    // fc2 + relu
    float a2 = fc2_b[tid];
    for (int k = 0; k < 512; k++) a2 = fmaf(s_h1[k], fc2_w[(size_t)k * 512 + tid], a2);
    s_h2[tid] = a2 > 0.0f ? a2 : 0.0f;
    __syncthreads();

    // clf (N=1000)
    for (int n = tid; n < 1000; n += 512) {
        float o = clf_b[n];
        for (int k = 0; k < 512; k++) o = fmaf(s_h2[k], clf_w[(size_t)k * 1000 + n], o);
        out[(size_t)b * 1000 + n] = o;
    }
}

// ============================ launch ============================
extern "C" void kernel_launch(void* const* d_in, const int* in_sizes, int n_in,
                              void* d_out, int out_size) {
    const float* images = (const float*)d_in[0];
    const int*   seq    = (const int*)d_in[1];
    const int*   len    = (const int*)d_in[2];
    const float* emb    = (const float*)d_in[4];
    const float* cw1 = (const float*)d_in[5],  *cb1 = (const float*)d_in[6];
    const float* cw2 = (const float*)d_in[7],  *cb2 = (const float*)d_in[8];
    const float* cw3 = (const float*)d_in[9],  *cb3 = (const float*)d_in[10];
    const float* cw4 = (const float*)d_in[11], *cb4 = (const float*)d_in[12];
    const float* rnn_w = (const float*)d_in[13], *rnn_b = (const float*)d_in[14];
    const float* fc1_w = (const float*)d_in[15], *fc1_b = (const float*)d_in[16];
    const float* fc2_w = (const float*)d_in[17], *fc2_b = (const float*)d_in[18];
    const float* clf_w = (const float*)d_in[19], *clf_b = (const float*)d_in[20];
    float* out = (float*)d_out;

    h16 *x1, *x2, *x3, *x4, *w1, *w2, *w3, *w4;
    float *sent;
    cudaGetSymbolAddress((void**)&x1, g_x1); cudaGetSymbolAddress((void**)&x2, g_x2);
    cudaGetSymbolAddress((void**)&x3, g_x3); cudaGetSymbolAddress((void**)&x4, g_x4);
    cudaGetSymbolAddress((void**)&w1, g_w1); cudaGetSymbolAddress((void**)&w2, g_w2);
    cudaGetSymbolAddress((void**)&w3, g_w3); cudaGetSymbolAddress((void**)&w4, g_w4);
    cudaGetSymbolAddress((void**)&sent, g_sent);

    const int smemC = 2 * (ATILE_B + 64 * PITCH * 2);   // 55296 (double buffer, NTILE=64)
    const int smem1 = ATILE_B + 64 * PITCH * 2;         // 27648 (single, conv1)
    cudaFuncSetAttribute(conv1mm_k, cudaFuncAttributeMaxDynamicSharedMemorySize, smem1);
    cudaFuncSetAttribute(convmm_k<64, 128, 112, 112>,  cudaFuncAttributeMaxDynamicSharedMemorySize, smemC);
    cudaFuncSetAttribute(convmm_k<128, 256, 56, 56>,   cudaFuncAttributeMaxDynamicSharedMemorySize, smemC);
    cudaFuncSetAttribute(convmm_k<256, 512, 28, 28>,   cudaFuncAttributeMaxDynamicSharedMemorySize, smemC);

    // 1: text branch (fused)
    text_k<<<64, 512>>>(seq, len, emb, rnn_w, rnn_b, sent);

    // 2: merged weight prep
    wprep_all_k<<<(2048 + 73728 + 294912 + 1179648 + 255) / 256, 256>>>(
        cw1, cw2, cw3, cw4, w1, w2, w3, w4);

    // 3-6: vision branch
    conv1mm_k<<<6272, 256, smem1>>>(images, w1, cb1, x1);
    convmm_k<64, 128, 112, 112><<<dim3(1568, 2), 256, smemC>>>(x1, w2, cb2, x2);
    convmm_k<128, 256, 56, 56><<<dim3(392, 4), 256, smemC>>>(x2, w3, cb3, x3);
    convmm_k<256, 512, 28, 28><<<dim3(98, 8), 256, smemC>>>(x3, w4, cb4, x4);

    // 7: fused head (pool + fc1 + fc2 + clf)
    head_k<<<64, 512>>>(x4, sent, fc1_w, fc1_b, fc2_w, fc2_b, clf_w, clf_b, out);
}

// round 16
// speedup vs baseline: 3.0968x; 1.0180x over previous
#include <cuda_runtime.h>
#include <cuda_fp16.h>
#include <cstdint>
#include <cstddef>

typedef __half h16;

// ============================ helpers ============================
__device__ __forceinline__ uint32_t smem_u32(const void* p) {
    uint32_t a;
    asm("{ .reg .u64 t; cvta.to.shared.u64 t, %1; cvt.u32.u64 %0, t; }" : "=r"(a) : "l"(p));
    return a;
}
__device__ __forceinline__ void ldsm4(uint32_t& r0, uint32_t& r1, uint32_t& r2, uint32_t& r3,
                                      uint32_t addr) {
    asm volatile("ldmatrix.sync.aligned.m8n8.x4.shared.b16 {%0,%1,%2,%3}, [%4];"
                 : "=r"(r0), "=r"(r1), "=r"(r2), "=r"(r3) : "r"(addr));
}
__device__ __forceinline__ void mma16816(float c[4], const uint32_t a[4], const uint32_t b[2]) {
    asm volatile(
        "mma.sync.aligned.m16n8k16.row.col.f32.f16.f16.f32 "
        "{%0,%1,%2,%3}, {%4,%5,%6,%7}, {%8,%9}, {%0,%1,%2,%3};"
        : "+f"(c[0]), "+f"(c[1]), "+f"(c[2]), "+f"(c[3])
        : "r"(a[0]), "r"(a[1]), "r"(a[2]), "r"(a[3]), "r"(b[0]), "r"(b[1]));
}
// 16B async copy, zero-fill when srcsize==0
__device__ __forceinline__ void cp16(uint32_t dst, const void* src, uint32_t srcsize) {
    asm volatile("cp.async.cg.shared.global [%0], [%1], 16, %2;"
                 :: "r"(dst), "l"(src), "r"(srcsize) : "memory");
}
#define CP_COMMIT() asm volatile("cp.async.commit_group;" ::: "memory")
#define CP_WAIT(n)  asm volatile("cp.async.wait_group %0;" :: "n"(n) : "memory")

// smem tile pitch: 72 h16 (144 B) -> row stride 36 words -> ldmatrix conflict-free
static constexpr int PITCH = 72;
static constexpr int ATILE_B = 128 * PITCH * 2;   // 18432 bytes per 128x64 tile

// ============================ scratch ============================
__device__ h16 g_x1[(size_t)64 * 112 * 112 * 64];
__device__ h16 g_x2[(size_t)64 * 56 * 56 * 128];
__device__ h16 g_x3[(size_t)64 * 28 * 28 * 256];
__device__ h16 g_x4[(size_t)64 * 14 * 14 * 512];
__device__ h16 g_w1[64 * 32];               // conv1 padded [co][32]
__device__ h16 g_w2[9 * 128 * 64];          // [t][co][ci]
__device__ h16 g_w3[9 * 256 * 128];
__device__ h16 g_w4[9 * 512 * 256];
__device__ float g_sent[64 * 512];

// ============================ merged weight prep ============================
__global__ void wprep_all_k(const float* __restrict__ cw1, const float* __restrict__ cw2,
                            const float* __restrict__ cw3, const float* __restrict__ cw4,
                            h16* __restrict__ w1, h16* __restrict__ w2,
                            h16* __restrict__ w3, h16* __restrict__ w4) {
    int idx = blockIdx.x * 256 + threadIdx.x;
    if (idx < 2048) {
        int co = idx >> 5, k = idx & 31;
        w1[idx] = __float2half_rn((k < 27) ? cw1[co * 27 + k] : 0.0f);
        return;
    }
    idx -= 2048;
    const float* src; h16* dst; int COUT, CIN;
    if (idx < 73728)        { src = cw2; dst = w2; COUT = 128; CIN = 64; }
    else if (idx < 73728 + 294912) { idx -= 73728; src = cw3; dst = w3; COUT = 256; CIN = 128; }
    else                    { idx -= 73728 + 294912; if (idx >= 1179648) return;
                              src = cw4; dst = w4; COUT = 512; CIN = 256; }
    int co = idx / (CIN * 9);
    int rem = idx - co * (CIN * 9);
    int ci = rem / 9, t = rem - ci * 9;
    dst[(t * COUT + co) * CIN + ci] = __float2half_rn(src[idx]);
}

// ============================ warp-level GEMM core ============================
template <int NFRAG, int KSTEPS>
__device__ __forceinline__ void chunk_mma(uint32_t sbA, uint32_t sbB,
                                          int lane, int warpM, int warpN,
                                          float (&c)[2][NFRAG][4]) {
    const int arow = warpM * 32 + (lane & 15);
    const int akoff = (lane >> 4) * 8;
    const int brow = warpN * (NFRAG * 8) + (lane & 7) + ((lane >> 3) & 1) * 8;
    const int bkoff = (lane >> 4) * 8;
#pragma unroll
    for (int ks = 0; ks < KSTEPS; ks++) {
        const int k0 = ks * 16;
        uint32_t ah[2][4];
#pragma unroll
        for (int i = 0; i < 2; i++) {
            const uint32_t aoff = (((arow + i * 16) * PITCH) + k0 + akoff) * 2;
            ldsm4(ah[i][0], ah[i][1], ah[i][2], ah[i][3], sbA + aoff);
        }
        uint32_t bh[NFRAG][2];
#pragma unroll
        for (int j2 = 0; j2 < NFRAG / 2; j2++) {
            const uint32_t boff = (((brow + j2 * 16) * PITCH) + k0 + bkoff) * 2;
            uint32_t r0, r1, r2, r3;
            ldsm4(r0, r1, r2, r3, sbB + boff);
            bh[2 * j2][0] = r0; bh[2 * j2][1] = r2;
            bh[2 * j2 + 1][0] = r1; bh[2 * j2 + 1][1] = r3;
        }
#pragma unroll
        for (int i = 0; i < 2; i++)
#pragma unroll
            for (int j = 0; j < NFRAG; j++)
                mma16816(c[i][j], ah[i], bh[j]);
    }
}

// epilogue: bias + relu + cvt -> NHWC fp16
template <int NFRAG, int COUT>
__device__ __forceinline__ void epilogue(float (&c)[2][NFRAG][4], const float* __restrict__ bias,
                                         int tile0, int cob, int lane, int warpM, int warpN,
                                         h16* __restrict__ y) {
#pragma unroll
    for (int i = 0; i < 2; i++) {
        const int r0 = tile0 + warpM * 32 + i * 16 + (lane >> 2);
#pragma unroll
        for (int j = 0; j < NFRAG; j++) {
            const int col = cob + warpN * (NFRAG * 8) + j * 8 + (lane & 3) * 2;
            const float b0 = bias[col], b1 = bias[col + 1];
#pragma unroll
            for (int h = 0; h < 2; h++) {
                const int r = r0 + h * 8;
                float v0 = c[i][j][2 * h + 0] + b0; if (v0 < 0.0f) v0 = 0.0f;
                float v1 = c[i][j][2 * h + 1] + b1; if (v1 < 0.0f) v1 = 0.0f;
                __half2 p;
                p.x = __float2half_rn(v0); p.y = __float2half_rn(v1);
                *(__half2*)(y + (size_t)r * COUT + col) = p;
            }
        }
    }
}

// ============================ conv2/3/4: implicit GEMM, cp.async double-buffer ============================
template <int CIN, int COUT, int HIN, int WIN, int NTILE, int MINCTA>
__global__ void __launch_bounds__(256, MINCTA)
convmm_k(const h16* __restrict__ x, const h16* __restrict__ wt,
         const float* __restrict__ bias, h16* __restrict__ y) {
    constexpr int HOUT = HIN / 2, WOUT = WIN / 2;
    constexpr int CPT = CIN / 64;
    constexpr int NCH = 9 * CPT;
    constexpr int NFRAG = NTILE / 16;
    constexpr int BSLOTS = NTILE / 32;
    constexpr int BUF_B = ATILE_B + NTILE * PITCH * 2;   // A tile + B tile

    extern __shared__ char sb[];
    const uint32_t sb32 = smem_u32(sb);

    const int tid = threadIdx.x, lane = tid & 31, wid = tid >> 5;
    const int warpM = wid >> 1, warpN = wid & 1;
    const int tile0 = blockIdx.x * 128;
    const int cob = blockIdx.y * NTILE;

    const int c16 = tid & 7;
    int baseoff[4]; bool xe[4], ye[4];
#pragma unroll
    for (int r4 = 0; r4 < 4; r4++) {
        const int row = (tid >> 3) + 32 * r4;
        const int s = tile0 + row;
        const int n = s / (HOUT * WOUT);
        const int rem = s - n * (HOUT * WOUT);
        const int y2 = rem / WOUT;
        const int x2 = rem - y2 * WOUT;
        baseoff[r4] = ((n * HIN + 2 * y2) * WIN + 2 * x2) * CIN;
        xe[r4] = (2 * x2 + 2 >= WIN);
        ye[r4] = (2 * y2 + 2 >= HIN);
    }

    auto stage = [&](int ch) {
        const int t = ch / CPT;
        const int cb = (ch - t * CPT) * 64;
        const int ky = t / 3, kx = t - ky * 3;
        const uint32_t base = sb32 + (ch & 1) * BUF_B;
#pragma unroll
        for (int r4 = 0; r4 < 4; r4++) {
            const int row = (tid >> 3) + 32 * r4;
            const uint32_t soff = (row * PITCH + c16 * 8) * 2;
            const bool valid = !((kx == 2 && xe[r4]) || (ky == 2 && ye[r4]));
            const size_t src = (size_t)baseoff[r4] + (ky * WIN + kx) * CIN + cb + c16 * 8;
            cp16(base + soff, x + src, valid ? 16u : 0u);
            if (r4 < BSLOTS) {
                const size_t wsrc = ((size_t)t * COUT + cob + row) * CIN + cb + c16 * 8;
                cp16(base + ATILE_B + soff, wt + wsrc, 16u);
            }
        }
        CP_COMMIT();
    };

    float c[2][NFRAG][4];
#pragma unroll
    for (int i = 0; i < 2; i++)
#pragma unroll
        for (int j = 0; j < NFRAG; j++)
#pragma unroll
            for (int q = 0; q < 4; q++) c[i][j][q] = 0.0f;

    stage(0);
    for (int ch = 0; ch < NCH; ch++) {
        if (ch + 1 < NCH) { stage(ch + 1); CP_WAIT(1); }
        else              { CP_WAIT(0); }
        __syncthreads();
        const uint32_t base = sb32 + (ch & 1) * BUF_B;
        chunk_mma<NFRAG, 4>(base, base + ATILE_B, lane, warpM, warpN, c);
        __syncthreads();
    }

    epilogue<NFRAG, COUT>(c, bias, tile0, cob, lane, warpM, warpN, y);
}

// ============================ conv1: implicit GEMM, K=27 (padded 32), 4 CTAs/SM ============================
__global__ void __launch_bounds__(256, 4)
conv1mm_k(const float* __restrict__ images,
          const h16* __restrict__ wh,
          const float* __restrict__ bias,
          h16* __restrict__ y) {
    constexpr int HOUT = 112, WOUT = 112, HIN = 224, WIN = 224;
    constexpr int NFRAG = 4;

    extern __shared__ char sb[];
    const uint32_t sb32 = smem_u32(sb);
    const uint32_t oA = 0, oB = ATILE_B;

    const int tid = threadIdx.x, lane = tid & 31, wid = tid >> 5;
    const int warpM = wid >> 1, warpN = wid & 1;
    const int tile0 = blockIdx.x * 128;

    // A staging: thread owns (row, k-half); vectorized tap loads (float2 for kx=0,1
    // + scalar for kx=2), register-pack 16 taps, 2x STS.128 (conflict-free).
    {
        const int g = wid >> 2;                 // 0: k0..15, 1: k16..31
        const int row = ((wid & 3) << 5) + lane;
        const int s = tile0 + row;
        const int n = s / (HOUT * WOUT);
        const int rem = s - n * (HOUT * WOUT);
        const int y2 = rem / WOUT;
        const int x2 = rem - y2 * WOUT;
        const float* p0 = images + ((size_t)(n * 3) * HIN + 2 * y2) * WIN + 2 * x2;
        const bool xok = (x2 < 111);            // ix=2*x2+2 in range?
        const bool yok = (y2 < 111);            // iy=2*y2+2 in range?
        union { h16 h[16]; uint4 u[2]; } pk;
#pragma unroll
        for (int i = 0; i < 16; i++) pk.h[i] = __float2half_rn(0.0f);

        auto fill = [&](const int klo) {
#pragma unroll
            for (int ci = 0; ci < 3; ci++)
#pragma unroll
                for (int ky = 0; ky < 3; ky++) {
                    const int kb = ci * 9 + ky * 3;
                    if (kb + 2 >= klo && kb < klo + 16) {
                        const bool yv = (ky < 2) || yok;
                        const float* gp = p0 + (size_t)ci * (HIN * WIN) + ky * WIN;
                        float2 a = make_float2(0.0f, 0.0f);
                        if (yv) a = *(const float2*)gp;          // kx=0,1 (8B aligned)
                        float b2 = 0.0f;
                        if (yv && xok) b2 = gp[2];               // kx=2
                        if (kb >= klo && kb < klo + 16)         pk.h[kb - klo]     = __float2half_rn(a.x);
                        if (kb + 1 >= klo && kb + 1 < klo + 16) pk.h[kb + 1 - klo] = __float2half_rn(a.y);
                        if (kb + 2 >= klo && kb + 2 < klo + 16) pk.h[kb + 2 - klo] = __float2half_rn(b2);
                    }
                }
        };
        if (g == 0) fill(0); else fill(16);

        char* dst = sb + oA + row * (PITCH * 2) + g * 32;
        *(uint4*)dst = pk.u[0];
        *(uint4*)(dst + 16) = pk.u[1];
    }
    // B staging: 64 couts x 32 k (w1 is [co][32])
    if (tid < 256) {
        const int r = tid >> 2, c16 = tid & 3;
        *(uint4*)(sb + oB + (r * PITCH + c16 * 8) * 2) = *(const uint4*)(wh + r * 32 + c16 * 8);
    }
    __syncthreads();

    float c[2][NFRAG][4];
#pragma unroll
    for (int i = 0; i < 2; i++)
#pragma unroll
        for (int j = 0; j < NFRAG; j++)
#pragma unroll
            for (int q = 0; q < 4; q++) c[i][j][q] = 0.0f;

    chunk_mma<NFRAG, 2>(sb32 + oA, sb32 + oB, lane, warpM, warpN, c);

    epilogue<NFRAG, 64>(c, bias, tile0, 0, lane, warpM, warpN, y);
}

// ============================ fused text branch: embed mean + rnn linear ============================
__global__ void __launch_bounds__(512)
text_k(const int* __restrict__ seq, const int* __restrict__ len,
       const float* __restrict__ emb,
       const float* __restrict__ rnn_w, const float* __restrict__ rnn_b,
       float* __restrict__ sent) {
    const int b = blockIdx.x;
    const int tid = threadIdx.x;   // 0..511
    __shared__ int s_idx[128];
    __shared__ float s_m[512];
    if (tid < 128) s_idx[tid] = seq[b * 128 + tid];
    __syncthreads();
    const int L = len[b];
    float acc = 0.0f;
    for (int s = 0; s < L; s++) acc += emb[(size_t)s_idx[s] * 512 + tid];
    s_m[tid] = acc / (float)L;
    __syncthreads();
    float o = rnn_b[tid];
    for (int k = 0; k < 512; k++) o = fmaf(s_m[k], rnn_w[(size_t)k * 512 + tid], o);
    sent[(size_t)b * 512 + tid] = o;
}

// ============================ fused head: pool + fc1(concat) + fc2 + clf ============================
__global__ void __launch_bounds__(512)
head_k(const h16* __restrict__ x4, const float* __restrict__ sent,
       const float* __restrict__ fc1_w, const float* __restrict__ fc1_b,
       const float* __restrict__ fc2_w, const float* __restrict__ fc2_b,
       const float* __restrict__ clf_w, const float* __restrict__ clf_b,
       float* __restrict__ out) {
    const int b = blockIdx.x;
    const int tid = threadIdx.x;   // 0..511
    __shared__ float s_a[512], s_s[512], s_h1[512], s_h2[512];

    // pool: channel tid, mean over 196 positions
    const h16* p = x4 + (size_t)b * 196 * 512 + tid;
    float sum = 0.0f;
    for (int i = 0; i < 196; i++) sum += __half2float(p[(size_t)i * 512]);
    s_a[tid] = sum * (1.0f / 196.0f);
    s_s[tid] = sent[(size_t)b * 512 + tid];
    __syncthreads();

    // fc1 (concat fused) + relu
    float a1 = fc1_b[tid];
    for (int k = 0; k < 512; k++) a1 = fmaf(s_a[k], fc1_w[(size_t)k * 512 + tid], a1);
    for (int k = 0; k < 512; k++) a1 = fmaf(s_s[k], fc1_w[(size_t)(512 + k) * 512 + tid], a1);
    s_h1[tid] = a1 > 0.0f ? a1 : 0.0f;
    __syncthreads();

    // fc2 + relu
    float a2 = fc2_b[tid];
    for (int k = 0; k < 512; k++) a2 = fmaf(s_h1[k], fc2_w[(size_t)k * 512 + tid], a2);
    s_h2[tid] = a2 > 0.0f ? a2 : 0.0f;
    __syncthreads();

    // clf (N=1000)
    for (int n = tid; n < 1000; n += 512) {
        float o = clf_b[n];
        for (int k = 0; k < 512; k++) o = fmaf(s_h2[k], clf_w[(size_t)k * 1000 + n], o);
        out[(size_t)b * 1000 + n] = o;
    }
}

// ============================ launch ============================
extern "C" void kernel_launch(void* const* d_in, const int* in_sizes, int n_in,
                              void* d_out, int out_size) {
    const float* images = (const float*)d_in[0];
    const int*   seq    = (const int*)d_in[1];
    const int*   len    = (const int*)d_in[2];
    const float* emb    = (const float*)d_in[4];
    const float* cw1 = (const float*)d_in[5],  *cb1 = (const float*)d_in[6];
    const float* cw2 = (const float*)d_in[7],  *cb2 = (const float*)d_in[8];
    const float* cw3 = (const float*)d_in[9],  *cb3 = (const float*)d_in[10];
    const float* cw4 = (const float*)d_in[11], *cb4 = (const float*)d_in[12];
    const float* rnn_w = (const float*)d_in[13], *rnn_b = (const float*)d_in[14];
    const float* fc1_w = (const float*)d_in[15], *fc1_b = (const float*)d_in[16];
    const float* fc2_w = (const float*)d_in[17], *fc2_b = (const float*)d_in[18];
    const float* clf_w = (const float*)d_in[19], *clf_b = (const float*)d_in[20];
    float* out = (float*)d_out;

    h16 *x1, *x2, *x3, *x4, *w1, *w2, *w3, *w4;
    float *sent;
    cudaGetSymbolAddress((void**)&x1, g_x1); cudaGetSymbolAddress((void**)&x2, g_x2);
    cudaGetSymbolAddress((void**)&x3, g_x3); cudaGetSymbolAddress((void**)&x4, g_x4);
    cudaGetSymbolAddress((void**)&w1, g_w1); cudaGetSymbolAddress((void**)&w2, g_w2);
    cudaGetSymbolAddress((void**)&w3, g_w3); cudaGetSymbolAddress((void**)&w4, g_w4);
    cudaGetSymbolAddress((void**)&sent, g_sent);

    const int smem128 = 2 * (ATILE_B + 128 * PITCH * 2);  // 73728 (NTILE=128, 2 CTAs/SM)
    const int smem64  = 2 * (ATILE_B + 64 * PITCH * 2);   // 55296 (NTILE=64, 3 CTAs/SM)
    const int smem1   = ATILE_B + 64 * PITCH * 2;         // 27648 (single, conv1)
    cudaFuncSetAttribute(conv1mm_k, cudaFuncAttributeMaxDynamicSharedMemorySize, smem1);
    cudaFuncSetAttribute(convmm_k<64, 128, 112, 112, 128, 2>, cudaFuncAttributeMaxDynamicSharedMemorySize, smem128);
    cudaFuncSetAttribute(convmm_k<128, 256, 56, 56, 64, 3>,   cudaFuncAttributeMaxDynamicSharedMemorySize, smem64);
    cudaFuncSetAttribute(convmm_k<256, 512, 28, 28, 64, 3>,   cudaFuncAttributeMaxDynamicSharedMemorySize, smem64);

    // 1: text branch (fused)
    text_k<<<64, 512>>>(seq, len, emb, rnn_w, rnn_b, sent);

    // 2: merged weight prep
    wprep_all_k<<<(2048 + 73728 + 294912 + 1179648 + 255) / 256, 256>>>(
        cw1, cw2, cw3, cw4, w1, w2, w3, w4);

    // 3-6: vision branch
    conv1mm_k<<<6272, 256, smem1>>>(images, w1, cb1, x1);
    convmm_k<64, 128, 112, 112, 128, 2><<<dim3(1568, 1), 256, smem128>>>(x1, w2, cb2, x2);
    convmm_k<128, 256, 56, 56, 64, 3><<<dim3(392, 4), 256, smem64>>>(x2, w3, cb3, x3);
    convmm_k<256, 512, 28, 28, 64, 3><<<dim3(98, 8), 256, smem64>>>(x3, w4, cb4, x4);

    // 7: fused head (pool + fc1 + fc2 + clf)
    head_k<<<64, 512>>>(x4, sent, fc1_w, fc1_b, fc2_w, fc2_b, clf_w, clf_b, out);
}